// round 2
// baseline (speedup 1.0000x reference)
#include <cuda_runtime.h>

#define CL   1024
#define CS   1024
#define CB   8
#define CE   512
#define CH   8
#define CDH  64
#define CBH  64
#define CM   8192
#define CK   512

// ---------------- device scratch (no dynamic allocation allowed) ----------------
__device__ __align__(128) float g_qh [CBH * CL * CDH];
__device__ __align__(128) float g_k1h[CBH * CS * CDH];
__device__ __align__(128) float g_k2h[CBH * CS * CDH];
__device__ __align__(128) float g_vh [CBH * CS * CDH];
__device__ __align__(128) float g_ao [CM * CE];
__device__ __align__(128) float g_ll [CBH * CL];
__device__ __align__(128) float g_vv [CBH * CS];
__device__ __align__(128) float g_aa [CBH * CS];
__device__ __align__(128) float g_va [CBH * CS];

// ---------------- MUFU-free math ----------------
__device__ __forceinline__ float fexp(float x) {
    float t = x * 1.4426950408889634f;
    t = fminf(fmaxf(t, -126.0f), 126.0f);
    int i = __float2int_rn(t);
    float u = (t - (float)i) * 0.6931471805599453f;
    float p = 1.3888889e-3f;
    p = fmaf(p, u, 8.3333333e-3f);
    p = fmaf(p, u, 4.1666667e-2f);
    p = fmaf(p, u, 1.6666667e-1f);
    p = fmaf(p, u, 0.5f);
    p = fmaf(p, u, 1.0f);
    p = fmaf(p, u, 1.0f);
    return p * __int_as_float((i + 127) << 23);
}

__device__ __forceinline__ float fsqrt_pos(float x) {
    float y = __int_as_float(0x5f3759df - (__float_as_int(x) >> 1));
    y = y * fmaf(-0.5f * x, y * y, 1.5f);
    y = y * fmaf(-0.5f * x, y * y, 1.5f);
    y = y * fmaf(-0.5f * x, y * y, 1.5f);
    return x * y;
}

__device__ __forceinline__ float frcp_pos(float x) {
    float y = __int_as_float(0x7EF127EAu - __float_as_int(x));
    y = y * (2.0f - x * y);
    y = y * (2.0f - x * y);
    y = y * (2.0f - x * y);
    return y;
}

// ---------------- projection GEMM: C = (A @ W^T + b) [*0.125] ----------------
// MODE 0: q -> head-major, *0.125.  MODE 1: k -> head-major.  MODE 2: row-major out.
template<int MODE>
__global__ void __launch_bounds__(256)
proj_kernel(const float* __restrict__ A, const float* __restrict__ W,
            const float* __restrict__ bias, float* __restrict__ C)
{
    __shared__ float As[16][128];
    __shared__ float Bs[16][64];
    const int tid = threadIdx.x;
    const int tx = tid & 15, ty = tid >> 4;
    const int m0 = blockIdx.x * 128;
    const int n0 = blockIdx.y * 64;
    const int lrow = tid >> 2;
    const int lkk  = (tid & 3) << 2;

    float acc[8][4];
#pragma unroll
    for (int i = 0; i < 8; i++)
#pragma unroll
        for (int j = 0; j < 4; j++) acc[i][j] = 0.f;

    for (int k0 = 0; k0 < CK; k0 += 16) {
        float4 a0 = *(const float4*)(A + (m0 + lrow)      * CK + k0 + lkk);
        float4 a1 = *(const float4*)(A + (m0 + lrow + 64) * CK + k0 + lkk);
        float4 bw = *(const float4*)(W + (n0 + lrow)      * CK + k0 + lkk);
        __syncthreads();
        As[lkk + 0][lrow] = a0.x; As[lkk + 1][lrow] = a0.y;
        As[lkk + 2][lrow] = a0.z; As[lkk + 3][lrow] = a0.w;
        As[lkk + 0][lrow + 64] = a1.x; As[lkk + 1][lrow + 64] = a1.y;
        As[lkk + 2][lrow + 64] = a1.z; As[lkk + 3][lrow + 64] = a1.w;
        Bs[lkk + 0][lrow] = bw.x; Bs[lkk + 1][lrow] = bw.y;
        Bs[lkk + 2][lrow] = bw.z; Bs[lkk + 3][lrow] = bw.w;
        __syncthreads();
#pragma unroll
        for (int k = 0; k < 16; k++) {
            float4 qa = *(const float4*)&As[k][ty * 8];
            float4 qb = *(const float4*)&As[k][ty * 8 + 4];
            float4 bb = *(const float4*)&Bs[k][tx * 4];
            float av[8] = {qa.x, qa.y, qa.z, qa.w, qb.x, qb.y, qb.z, qb.w};
            float bv[4] = {bb.x, bb.y, bb.z, bb.w};
#pragma unroll
            for (int i = 0; i < 8; i++)
#pragma unroll
                for (int j = 0; j < 4; j++)
                    acc[i][j] = fmaf(av[i], bv[j], acc[i][j]);
        }
    }

    float4 bb4 = *(const float4*)(bias + n0 + tx * 4);
    float bvals[4] = {bb4.x, bb4.y, bb4.z, bb4.w};
    const int h = n0 >> 6;
#pragma unroll
    for (int i = 0; i < 8; i++) {
        int r = m0 + ty * 8 + i;
        float4 v;
        v.x = acc[i][0] + bvals[0];
        v.y = acc[i][1] + bvals[1];
        v.z = acc[i][2] + bvals[2];
        v.w = acc[i][3] + bvals[3];
        if (MODE == 0) { v.x *= 0.125f; v.y *= 0.125f; v.z *= 0.125f; v.w *= 0.125f; }
        if (MODE <= 1) {
            int t = r >> 3, bi = r & 7;
            *(float4*)(C + ((bi * 8 + h) * 1024 + t) * 64 + tx * 4) = v;
        } else {
            *(float4*)(C + r * CE + n0 + tx * 4) = v;
        }
    }
}

// ---------------- gated value: C (+)= (A@Wv^T+bv) * sigmoid(A@Wg^T+bg), head-major ----------------
__global__ void __launch_bounds__(256)
projvg_kernel(const float* __restrict__ A,
              const float* __restrict__ Wv, const float* __restrict__ bv,
              const float* __restrict__ Wg, const float* __restrict__ bg,
              float* __restrict__ C, int accum)
{
    __shared__ float As[16][128];
    __shared__ float Bv[16][64];
    __shared__ float Bg[16][64];
    const int tid = threadIdx.x;
    const int tx = tid & 15, ty = tid >> 4;
    const int m0 = blockIdx.x * 128;
    const int n0 = blockIdx.y * 64;
    const int lrow = tid >> 2;
    const int lkk  = (tid & 3) << 2;

    float accv[8][4], accg[8][4];
#pragma unroll
    for (int i = 0; i < 8; i++)
#pragma unroll
        for (int j = 0; j < 4; j++) { accv[i][j] = 0.f; accg[i][j] = 0.f; }

    for (int k0 = 0; k0 < CK; k0 += 16) {
        float4 a0 = *(const float4*)(A  + (m0 + lrow)      * CK + k0 + lkk);
        float4 a1 = *(const float4*)(A  + (m0 + lrow + 64) * CK + k0 + lkk);
        float4 vw = *(const float4*)(Wv + (n0 + lrow)      * CK + k0 + lkk);
        float4 gw = *(const float4*)(Wg + (n0 + lrow)      * CK + k0 + lkk);
        __syncthreads();
        As[lkk + 0][lrow] = a0.x; As[lkk + 1][lrow] = a0.y;
        As[lkk + 2][lrow] = a0.z; As[lkk + 3][lrow] = a0.w;
        As[lkk + 0][lrow + 64] = a1.x; As[lkk + 1][lrow + 64] = a1.y;
        As[lkk + 2][lrow + 64] = a1.z; As[lkk + 3][lrow + 64] = a1.w;
        Bv[lkk + 0][lrow] = vw.x; Bv[lkk + 1][lrow] = vw.y;
        Bv[lkk + 2][lrow] = vw.z; Bv[lkk + 3][lrow] = vw.w;
        Bg[lkk + 0][lrow] = gw.x; Bg[lkk + 1][lrow] = gw.y;
        Bg[lkk + 2][lrow] = gw.z; Bg[lkk + 3][lrow] = gw.w;
        __syncthreads();
#pragma unroll 8
        for (int k = 0; k < 16; k++) {
            float4 qa = *(const float4*)&As[k][ty * 8];
            float4 qb = *(const float4*)&As[k][ty * 8 + 4];
            float4 b1 = *(const float4*)&Bv[k][tx * 4];
            float4 b2 = *(const float4*)&Bg[k][tx * 4];
            float av[8] = {qa.x, qa.y, qa.z, qa.w, qb.x, qb.y, qb.z, qb.w};
            float v1[4] = {b1.x, b1.y, b1.z, b1.w};
            float v2[4] = {b2.x, b2.y, b2.z, b2.w};
#pragma unroll
            for (int i = 0; i < 8; i++)
#pragma unroll
                for (int j = 0; j < 4; j++) {
                    accv[i][j] = fmaf(av[i], v1[j], accv[i][j]);
                    accg[i][j] = fmaf(av[i], v2[j], accg[i][j]);
                }
        }
    }

    float4 bbv = *(const float4*)(bv + n0 + tx * 4);
    float4 bbg = *(const float4*)(bg + n0 + tx * 4);
    float bva[4] = {bbv.x, bbv.y, bbv.z, bbv.w};
    float bga[4] = {bbg.x, bbg.y, bbg.z, bbg.w};
    const int h = n0 >> 6;
#pragma unroll
    for (int i = 0; i < 8; i++) {
        int r = m0 + ty * 8 + i;
        int t = r >> 3, bi = r & 7;
        float res[4];
#pragma unroll
        for (int j = 0; j < 4; j++) {
            float vx = accv[i][j] + bva[j];
            float gx = accg[i][j] + bga[j];
            res[j] = vx * frcp_pos(1.0f + fexp(-gx));
        }
        float* dst = C + ((bi * 8 + h) * 1024 + t) * 64 + tx * 4;
        float4 v;
        if (accum) {
            float4 old = *(float4*)dst;
            v.x = old.x + res[0]; v.y = old.y + res[1];
            v.z = old.z + res[2]; v.w = old.w + res[3];
        } else {
            v.x = res[0]; v.y = res[1]; v.z = res[2]; v.w = res[3];
        }
        *(float4*)dst = v;
    }
}

// ---------------- per-row norms ----------------
__global__ void __launch_bounds__(256) norm_q_kernel()
{
    int row  = blockIdx.x * 8 + (threadIdx.x >> 5);
    int lane = threadIdx.x & 31;
    const float* p = g_qh + row * 64;
    float a = p[lane], b = p[lane + 32];
    float s = a * a + b * b;
#pragma unroll
    for (int o = 16; o; o >>= 1) s += __shfl_down_sync(0xffffffffu, s, o);
    if (lane == 0) g_ll[row] = s;
}

__global__ void __launch_bounds__(256) norm_k_kernel()
{
    int row  = blockIdx.x * 8 + (threadIdx.x >> 5);
    int lane = threadIdx.x & 31;
    const float* p1 = g_k1h + row * 64;
    const float* p2 = g_k2h + row * 64;
    float x0 = p1[lane], x1 = p1[lane + 32];
    float y0 = p2[lane], y1 = p2[lane + 32];
    float svv = x0 * x0 + x1 * x1;
    float saa = y0 * y0 + y1 * y1;
    float sva = x0 * y0 + x1 * y1;
#pragma unroll
    for (int o = 16; o; o >>= 1) {
        svv += __shfl_down_sync(0xffffffffu, svv, o);
        saa += __shfl_down_sync(0xffffffffu, saa, o);
        sva += __shfl_down_sync(0xffffffffu, sva, o);
    }
    if (lane == 0) { g_vv[row] = svv; g_aa[row] = saa; g_va[row] = sva; }
}

// ---------------- fused gram-det flash attention ----------------
#define FLASH_SMEM_FLOATS 32832
#define FLASH_SMEM_BYTES (FLASH_SMEM_FLOATS * 4)
__global__ void __launch_bounds__(256, 1) flash_kernel()
{
    extern __shared__ float sm[];
    float* qT      = sm;                 // [64][132]
    float* k1T     = qT  + 64 * 132;     // [64][68]
    float* k2T     = k1T + 64 * 68;      // [64][68]
    float* v_s     = k2T + 64 * 68;      // [64][64]
    float* p_s     = v_s + 64 * 64;      // [128][68]
    float* red     = p_s + 128 * 68;     // [128][17]
    float* m_row   = red + 128 * 17;     // [128]
    float* l_row   = m_row + 128;
    float* alpha_s = l_row + 128;
    float* ll_s    = alpha_s + 128;
    float* vv_s    = ll_s + 128;         // [64]
    float* aa_s    = vv_s + 64;
    float* va_s    = aa_s + 64;

    const int tid = threadIdx.x;
    const int tx = tid & 15, ty = tid >> 4;
    const int bh = blockIdx.y;
    const int l0 = blockIdx.x * 128;

    {
        const float* qp = g_qh + (bh * 1024 + l0) * 64;
#pragma unroll
        for (int u = 0; u < 8; u++) {
            int id = tid + u * 256;
            int r = id >> 4;
            int c4 = (id & 15) << 2;
            float4 a = *(const float4*)(qp + r * 64 + c4);
            qT[(c4 + 0) * 132 + r] = a.x;
            qT[(c4 + 1) * 132 + r] = a.y;
            qT[(c4 + 2) * 132 + r] = a.z;
            qT[(c4 + 3) * 132 + r] = a.w;
        }
    }
    if (tid < 128) {
        m_row[tid] = -1e30f;
        l_row[tid] = 0.f;
        ll_s[tid]  = g_ll[bh * 1024 + l0 + tid];
    }
    float o[8][4] = {};

    for (int s0 = 0; s0 < 1024; s0 += 64) {
        __syncthreads();
        const float* k1p = g_k1h + (bh * 1024 + s0) * 64;
        const float* k2p = g_k2h + (bh * 1024 + s0) * 64;
        const float* vp  = g_vh  + (bh * 1024 + s0) * 64;
#pragma unroll
        for (int u = 0; u < 4; u++) {
            int id = tid + u * 256;
            int r = id >> 4;
            int c4 = (id & 15) << 2;
            float4 a = *(const float4*)(k1p + r * 64 + c4);
            k1T[(c4 + 0) * 68 + r] = a.x; k1T[(c4 + 1) * 68 + r] = a.y;
            k1T[(c4 + 2) * 68 + r] = a.z; k1T[(c4 + 3) * 68 + r] = a.w;
            float4 b = *(const float4*)(k2p + r * 64 + c4);
            k2T[(c4 + 0) * 68 + r] = b.x; k2T[(c4 + 1) * 68 + r] = b.y;
            k2T[(c4 + 2) * 68 + r] = b.z; k2T[(c4 + 3) * 68 + r] = b.w;
            float4 c = *(const float4*)(vp + r * 64 + c4);
            *(float4*)(v_s + r * 64 + c4) = c;
        }
        if (tid < 64) {
            vv_s[tid] = g_vv[bh * 1024 + s0 + tid];
            aa_s[tid] = g_aa[bh * 1024 + s0 + tid];
            va_s[tid] = g_va[bh * 1024 + s0 + tid];
        }
        __syncthreads();

        float lv[8][4] = {};
        float la[8][4] = {};
#pragma unroll 4
        for (int d = 0; d < 64; d++) {
            float4 a0 = *(const float4*)(qT + d * 132 + ty * 8);
            float4 a1 = *(const float4*)(qT + d * 132 + ty * 8 + 4);
            float4 b1 = *(const float4*)(k1T + d * 68 + tx * 4);
            float4 b2 = *(const float4*)(k2T + d * 68 + tx * 4);
            float av[8] = {a0.x, a0.y, a0.z, a0.w, a1.x, a1.y, a1.z, a1.w};
            float b1v[4] = {b1.x, b1.y, b1.z, b1.w};
            float b2v[4] = {b2.x, b2.y, b2.z, b2.w};
#pragma unroll
            for (int i = 0; i < 8; i++)
#pragma unroll
                for (int j = 0; j < 4; j++) {
                    lv[i][j] = fmaf(av[i], b1v[j], lv[i][j]);
                    la[i][j] = fmaf(av[i], b2v[j], la[i][j]);
                }
        }

        float cvv[4], caa[4], cva[4], g2[4];
#pragma unroll
        for (int j = 0; j < 4; j++) {
            cvv[j] = vv_s[tx * 4 + j];
            caa[j] = aa_s[tx * 4 + j];
            cva[j] = va_s[tx * 4 + j];
            g2[j]  = cvv[j] * caa[j] - cva[j] * cva[j];
        }
#pragma unroll
        for (int i = 0; i < 8; i++) {
            float lli = ll_s[ty * 8 + i];
            float mx = -1e30f;
#pragma unroll
            for (int j = 0; j < 4; j++) {
                float LV = lv[i][j], LA = la[i][j];
                float det = lli * g2[j]
                          - LV * (LV * caa[j] - LA * cva[j])
                          + LA * (LV * cva[j] - LA * cvv[j]);
                det = fmaxf(det, 1e-8f);
                float sc = -fsqrt_pos(det);
                lv[i][j] = sc;
                mx = fmaxf(mx, sc);
            }
            red[(ty * 8 + i) * 17 + tx] = mx;
        }
        __syncthreads();
        if (tid < 128) {
            float mo = m_row[tid];
            float tm = red[tid * 17];
#pragma unroll
            for (int c = 1; c < 16; c++) tm = fmaxf(tm, red[tid * 17 + c]);
            float mn = fmaxf(mo, tm);
            m_row[tid]   = mn;
            alpha_s[tid] = fexp(mo - mn);
        }
        __syncthreads();
#pragma unroll
        for (int i = 0; i < 8; i++) {
            float mn = m_row[ty * 8 + i];
            float p0 = fexp(lv[i][0] - mn);
            float p1 = fexp(lv[i][1] - mn);
            float p2 = fexp(lv[i][2] - mn);
            float p3 = fexp(lv[i][3] - mn);
            float4 pv; pv.x = p0; pv.y = p1; pv.z = p2; pv.w = p3;
            *(float4*)(p_s + (ty * 8 + i) * 68 + tx * 4) = pv;
            red[(ty * 8 + i) * 17 + tx] = p0 + p1 + p2 + p3;
        }
        __syncthreads();
        if (tid < 128) {
            float s = 0.f;
#pragma unroll
            for (int c = 0; c < 16; c++) s += red[tid * 17 + c];
            l_row[tid] = l_row[tid] * alpha_s[tid] + s;
        }
#pragma unroll
        for (int i = 0; i < 8; i++) {
            float al = alpha_s[ty * 8 + i];
#pragma unroll
            for (int j = 0; j < 4; j++) o[i][j] *= al;
        }
#pragma unroll 4
        for (int s = 0; s < 64; s++) {
            float4 vvl = *(const float4*)(v_s + s * 64 + tx * 4);
            float vj[4] = {vvl.x, vvl.y, vvl.z, vvl.w};
            float pr[8];
#pragma unroll
            for (int i = 0; i < 8; i++) pr[i] = p_s[(ty * 8 + i) * 68 + s];
#pragma unroll
            for (int i = 0; i < 8; i++)
#pragma unroll
                for (int j = 0; j < 4; j++)
                    o[i][j] = fmaf(pr[i], vj[j], o[i][j]);
        }
    }

    __syncthreads();
    if (tid < 128) alpha_s[tid] = frcp_pos(l_row[tid]);
    __syncthreads();

    const int bi = bh >> 3, h = bh & 7;
#pragma unroll
    for (int i = 0; i < 8; i++) {
        int l = l0 + ty * 8 + i;
        float inv = alpha_s[ty * 8 + i];
        float4 v;
        v.x = o[i][0] * inv;
        v.y = o[i][1] * inv;
        v.z = o[i][2] * inv;
        v.w = o[i][3] * inv;
        *(float4*)(g_ao + (l * 8 + bi) * 512 + h * 64 + tx * 4) = v;
    }
}

// ---------------- launch ----------------
extern "C" void kernel_launch(void* const* d_in, const int* in_sizes, int n_in,
                              void* d_out, int out_size) {
    const float* query = (const float*)d_in[0];
    const float* mod1  = (const float*)d_in[1];
    const float* mod2  = (const float*)d_in[2];
    const float* Wq  = (const float*)d_in[3];  const float* bq  = (const float*)d_in[4];
    const float* Wk1 = (const float*)d_in[5];  const float* bk1 = (const float*)d_in[6];
    const float* Wk2 = (const float*)d_in[7];  const float* bk2 = (const float*)d_in[8];
    const float* Wv1 = (const float*)d_in[9];  const float* bv1 = (const float*)d_in[10];
    const float* Wv2 = (const float*)d_in[11]; const float* bv2 = (const float*)d_in[12];
    const float* Wg1 = (const float*)d_in[13]; const float* bg1 = (const float*)d_in[14];
    const float* Wg2 = (const float*)d_in[15]; const float* bg2 = (const float*)d_in[16];
    const float* Wo  = (const float*)d_in[17]; const float* bo  = (const float*)d_in[18];
    float* out = (float*)d_out;

    float *p_qh, *p_k1h, *p_k2h, *p_vh, *p_ao;
    cudaGetSymbolAddress((void**)&p_qh,  g_qh);
    cudaGetSymbolAddress((void**)&p_k1h, g_k1h);
    cudaGetSymbolAddress((void**)&p_k2h, g_k2h);
    cudaGetSymbolAddress((void**)&p_vh,  g_vh);
    cudaGetSymbolAddress((void**)&p_ao,  g_ao);

    cudaFuncSetAttribute(flash_kernel,
                         cudaFuncAttributeMaxDynamicSharedMemorySize,
                         FLASH_SMEM_BYTES);

    dim3 pg(64, 8), pb(256);
    proj_kernel<0><<<pg, pb>>>(query, Wq,  bq,  p_qh);
    proj_kernel<1><<<pg, pb>>>(mod1,  Wk1, bk1, p_k1h);
    proj_kernel<1><<<pg, pb>>>(mod2,  Wk2, bk2, p_k2h);
    projvg_kernel<<<pg, pb>>>(mod1, Wv1, bv1, Wg1, bg1, p_vh, 0);
    projvg_kernel<<<pg, pb>>>(mod2, Wv2, bv2, Wg2, bg2, p_vh, 1);
    norm_q_kernel<<<8192, 256>>>();
    norm_k_kernel<<<8192, 256>>>();
    flash_kernel<<<dim3(8, 64), 256, FLASH_SMEM_BYTES>>>();
    proj_kernel<2><<<pg, pb>>>(p_ao, Wo, bo, out);
}

// round 3
// speedup vs baseline: 1.0438x; 1.0438x over previous
#include <cuda_runtime.h>

#define CL   1024
#define CS   1024
#define CB   8
#define CE   512
#define CH   8
#define CDH  64
#define CBH  64
#define CM   8192
#define CK   512

// ---------------- device scratch ----------------
__device__ __align__(128) float g_qh [CBH * CL * CDH];
__device__ __align__(128) float g_k1h[CBH * CS * CDH];
__device__ __align__(128) float g_k2h[CBH * CS * CDH];
__device__ __align__(128) float g_vh [CBH * CS * CDH];
__device__ __align__(128) float g_ao [CM * CE];
__device__ __align__(128) float g_ll [CBH * CL];
__device__ __align__(128) float g_vv [CBH * CS];
__device__ __align__(128) float g_aa [CBH * CS];
__device__ __align__(128) float g_va [CBH * CS];

// ---------------- packed f32x2 helpers ----------------
typedef unsigned long long u64;
__device__ __forceinline__ u64 f2pk(float lo, float hi) {
    u64 r; asm("mov.b64 %0,{%1,%2};" : "=l"(r) : "f"(lo), "f"(hi)); return r;
}
__device__ __forceinline__ u64 f2dup(float x) { return f2pk(x, x); }
__device__ __forceinline__ u64 f2fma(u64 a, u64 b, u64 c) {
    u64 d; asm("fma.rn.f32x2 %0,%1,%2,%3;" : "=l"(d) : "l"(a), "l"(b), "l"(c)); return d;
}
__device__ __forceinline__ u64 f2mul(u64 a, u64 b) {
    u64 d; asm("mul.rn.f32x2 %0,%1,%2;" : "=l"(d) : "l"(a), "l"(b)); return d;
}
__device__ __forceinline__ float2 f2upk(u64 v) {
    float2 f; asm("mov.b64 {%0,%1},%2;" : "=f"(f.x), "=f"(f.y) : "l"(v)); return f;
}

// ---------------- MUFU-free math ----------------
__device__ __forceinline__ float fexp(float x) {
    float t = x * 1.4426950408889634f;
    t = fminf(fmaxf(t, -126.0f), 126.0f);
    int i = __float2int_rn(t);
    float u = (t - (float)i) * 0.6931471805599453f;
    float p = 1.3888889e-3f;
    p = fmaf(p, u, 8.3333333e-3f);
    p = fmaf(p, u, 4.1666667e-2f);
    p = fmaf(p, u, 1.6666667e-1f);
    p = fmaf(p, u, 0.5f);
    p = fmaf(p, u, 1.0f);
    p = fmaf(p, u, 1.0f);
    return p * __int_as_float((i + 127) << 23);
}

__device__ __forceinline__ float fsqrt_pos(float x) {
    float y = __int_as_float(0x5f3759df - (__float_as_int(x) >> 1));
    y = y * fmaf(-0.5f * x, y * y, 1.5f);
    y = y * fmaf(-0.5f * x, y * y, 1.5f);
    y = y * fmaf(-0.5f * x, y * y, 1.5f);
    return x * y;
}

__device__ __forceinline__ float frcp_pos(float x) {
    float y = __int_as_float(0x7EF127EAu - __float_as_int(x));
    y = y * (2.0f - x * y);
    y = y * (2.0f - x * y);
    y = y * (2.0f - x * y);
    return y;
}

// ---------------- projection GEMM: C = (A @ W^T + b) [*0.125] ----------------
template<int MODE>
__global__ void __launch_bounds__(256)
proj_kernel(const float* __restrict__ A, const float* __restrict__ W,
            const float* __restrict__ bias, float* __restrict__ C)
{
    __shared__ float As[16][128];
    __shared__ float Bs[16][64];
    const int tid = threadIdx.x;
    const int tx = tid & 15, ty = tid >> 4;
    const int m0 = blockIdx.x * 128;
    const int n0 = blockIdx.y * 64;
    const int lrow = tid >> 2;
    const int lkk  = (tid & 3) << 2;

    u64 pa[4][4];
#pragma unroll
    for (int i = 0; i < 4; i++)
#pragma unroll
        for (int j = 0; j < 4; j++) pa[i][j] = 0ull;

    for (int k0 = 0; k0 < CK; k0 += 16) {
        float4 a0 = *(const float4*)(A + (m0 + lrow)      * CK + k0 + lkk);
        float4 a1 = *(const float4*)(A + (m0 + lrow + 64) * CK + k0 + lkk);
        float4 bw = *(const float4*)(W + (n0 + lrow)      * CK + k0 + lkk);
        __syncthreads();
        As[lkk + 0][lrow] = a0.x; As[lkk + 1][lrow] = a0.y;
        As[lkk + 2][lrow] = a0.z; As[lkk + 3][lrow] = a0.w;
        As[lkk + 0][lrow + 64] = a1.x; As[lkk + 1][lrow + 64] = a1.y;
        As[lkk + 2][lrow + 64] = a1.z; As[lkk + 3][lrow + 64] = a1.w;
        Bs[lkk + 0][lrow] = bw.x; Bs[lkk + 1][lrow] = bw.y;
        Bs[lkk + 2][lrow] = bw.z; Bs[lkk + 3][lrow] = bw.w;
        __syncthreads();
#pragma unroll
        for (int k = 0; k < 16; k++) {
            const u64* ap = (const u64*)&As[k][ty * 8];
            u64 av0 = ap[0], av1 = ap[1], av2 = ap[2], av3 = ap[3];
            float4 bb = *(const float4*)&Bs[k][tx * 4];
            u64 b0 = f2dup(bb.x), b1 = f2dup(bb.y), b2 = f2dup(bb.z), b3 = f2dup(bb.w);
            pa[0][0] = f2fma(av0, b0, pa[0][0]); pa[0][1] = f2fma(av0, b1, pa[0][1]);
            pa[0][2] = f2fma(av0, b2, pa[0][2]); pa[0][3] = f2fma(av0, b3, pa[0][3]);
            pa[1][0] = f2fma(av1, b0, pa[1][0]); pa[1][1] = f2fma(av1, b1, pa[1][1]);
            pa[1][2] = f2fma(av1, b2, pa[1][2]); pa[1][3] = f2fma(av1, b3, pa[1][3]);
            pa[2][0] = f2fma(av2, b0, pa[2][0]); pa[2][1] = f2fma(av2, b1, pa[2][1]);
            pa[2][2] = f2fma(av2, b2, pa[2][2]); pa[2][3] = f2fma(av2, b3, pa[2][3]);
            pa[3][0] = f2fma(av3, b0, pa[3][0]); pa[3][1] = f2fma(av3, b1, pa[3][1]);
            pa[3][2] = f2fma(av3, b2, pa[3][2]); pa[3][3] = f2fma(av3, b3, pa[3][3]);
        }
    }

    float acc[8][4];
#pragma unroll
    for (int ip = 0; ip < 4; ip++)
#pragma unroll
        for (int j = 0; j < 4; j++) {
            float2 f = f2upk(pa[ip][j]);
            acc[2 * ip][j] = f.x;
            acc[2 * ip + 1][j] = f.y;
        }

    float4 bb4 = *(const float4*)(bias + n0 + tx * 4);
    float bvals[4] = {bb4.x, bb4.y, bb4.z, bb4.w};
    const int h = n0 >> 6;
#pragma unroll
    for (int i = 0; i < 8; i++) {
        int r = m0 + ty * 8 + i;
        float4 v;
        v.x = acc[i][0] + bvals[0];
        v.y = acc[i][1] + bvals[1];
        v.z = acc[i][2] + bvals[2];
        v.w = acc[i][3] + bvals[3];
        if (MODE == 0) { v.x *= 0.125f; v.y *= 0.125f; v.z *= 0.125f; v.w *= 0.125f; }
        if (MODE <= 1) {
            int t = r >> 3, bi = r & 7;
            *(float4*)(C + ((bi * 8 + h) * 1024 + t) * 64 + tx * 4) = v;
        } else {
            *(float4*)(C + r * CE + n0 + tx * 4) = v;
        }
    }
}

// ---------------- gated value projection ----------------
__global__ void __launch_bounds__(256)
projvg_kernel(const float* __restrict__ A,
              const float* __restrict__ Wv, const float* __restrict__ bv,
              const float* __restrict__ Wg, const float* __restrict__ bg,
              float* __restrict__ C, int accum)
{
    __shared__ float As[16][128];
    __shared__ float Bv[16][64];
    __shared__ float Bg[16][64];
    const int tid = threadIdx.x;
    const int tx = tid & 15, ty = tid >> 4;
    const int m0 = blockIdx.x * 128;
    const int n0 = blockIdx.y * 64;
    const int lrow = tid >> 2;
    const int lkk  = (tid & 3) << 2;

    u64 pv_[4][4], pg_[4][4];
#pragma unroll
    for (int i = 0; i < 4; i++)
#pragma unroll
        for (int j = 0; j < 4; j++) { pv_[i][j] = 0ull; pg_[i][j] = 0ull; }

    for (int k0 = 0; k0 < CK; k0 += 16) {
        float4 a0 = *(const float4*)(A  + (m0 + lrow)      * CK + k0 + lkk);
        float4 a1 = *(const float4*)(A  + (m0 + lrow + 64) * CK + k0 + lkk);
        float4 vw = *(const float4*)(Wv + (n0 + lrow)      * CK + k0 + lkk);
        float4 gw = *(const float4*)(Wg + (n0 + lrow)      * CK + k0 + lkk);
        __syncthreads();
        As[lkk + 0][lrow] = a0.x; As[lkk + 1][lrow] = a0.y;
        As[lkk + 2][lrow] = a0.z; As[lkk + 3][lrow] = a0.w;
        As[lkk + 0][lrow + 64] = a1.x; As[lkk + 1][lrow + 64] = a1.y;
        As[lkk + 2][lrow + 64] = a1.z; As[lkk + 3][lrow + 64] = a1.w;
        Bv[lkk + 0][lrow] = vw.x; Bv[lkk + 1][lrow] = vw.y;
        Bv[lkk + 2][lrow] = vw.z; Bv[lkk + 3][lrow] = vw.w;
        Bg[lkk + 0][lrow] = gw.x; Bg[lkk + 1][lrow] = gw.y;
        Bg[lkk + 2][lrow] = gw.z; Bg[lkk + 3][lrow] = gw.w;
        __syncthreads();
#pragma unroll
        for (int k = 0; k < 16; k++) {
            const u64* ap = (const u64*)&As[k][ty * 8];
            u64 av0 = ap[0], av1 = ap[1], av2 = ap[2], av3 = ap[3];
            float4 b1 = *(const float4*)&Bv[k][tx * 4];
            float4 b2 = *(const float4*)&Bg[k][tx * 4];
            u64 v0 = f2dup(b1.x), v1 = f2dup(b1.y), v2 = f2dup(b1.z), v3 = f2dup(b1.w);
            u64 g0 = f2dup(b2.x), g1 = f2dup(b2.y), g2 = f2dup(b2.z), g3 = f2dup(b2.w);
            pv_[0][0] = f2fma(av0, v0, pv_[0][0]); pv_[0][1] = f2fma(av0, v1, pv_[0][1]);
            pv_[0][2] = f2fma(av0, v2, pv_[0][2]); pv_[0][3] = f2fma(av0, v3, pv_[0][3]);
            pv_[1][0] = f2fma(av1, v0, pv_[1][0]); pv_[1][1] = f2fma(av1, v1, pv_[1][1]);
            pv_[1][2] = f2fma(av1, v2, pv_[1][2]); pv_[1][3] = f2fma(av1, v3, pv_[1][3]);
            pv_[2][0] = f2fma(av2, v0, pv_[2][0]); pv_[2][1] = f2fma(av2, v1, pv_[2][1]);
            pv_[2][2] = f2fma(av2, v2, pv_[2][2]); pv_[2][3] = f2fma(av2, v3, pv_[2][3]);
            pv_[3][0] = f2fma(av3, v0, pv_[3][0]); pv_[3][1] = f2fma(av3, v1, pv_[3][1]);
            pv_[3][2] = f2fma(av3, v2, pv_[3][2]); pv_[3][3] = f2fma(av3, v3, pv_[3][3]);
            pg_[0][0] = f2fma(av0, g0, pg_[0][0]); pg_[0][1] = f2fma(av0, g1, pg_[0][1]);
            pg_[0][2] = f2fma(av0, g2, pg_[0][2]); pg_[0][3] = f2fma(av0, g3, pg_[0][3]);
            pg_[1][0] = f2fma(av1, g0, pg_[1][0]); pg_[1][1] = f2fma(av1, g1, pg_[1][1]);
            pg_[1][2] = f2fma(av1, g2, pg_[1][2]); pg_[1][3] = f2fma(av1, g3, pg_[1][3]);
            pg_[2][0] = f2fma(av2, g0, pg_[2][0]); pg_[2][1] = f2fma(av2, g1, pg_[2][1]);
            pg_[2][2] = f2fma(av2, g2, pg_[2][2]); pg_[2][3] = f2fma(av2, g3, pg_[2][3]);
            pg_[3][0] = f2fma(av3, g0, pg_[3][0]); pg_[3][1] = f2fma(av3, g1, pg_[3][1]);
            pg_[3][2] = f2fma(av3, g2, pg_[3][2]); pg_[3][3] = f2fma(av3, g3, pg_[3][3]);
        }
    }

    float accv[8][4], accg[8][4];
#pragma unroll
    for (int ip = 0; ip < 4; ip++)
#pragma unroll
        for (int j = 0; j < 4; j++) {
            float2 fv = f2upk(pv_[ip][j]);
            float2 fg = f2upk(pg_[ip][j]);
            accv[2 * ip][j] = fv.x; accv[2 * ip + 1][j] = fv.y;
            accg[2 * ip][j] = fg.x; accg[2 * ip + 1][j] = fg.y;
        }

    float4 bbv = *(const float4*)(bv + n0 + tx * 4);
    float4 bbg = *(const float4*)(bg + n0 + tx * 4);
    float bva[4] = {bbv.x, bbv.y, bbv.z, bbv.w};
    float bga[4] = {bbg.x, bbg.y, bbg.z, bbg.w};
    const int h = n0 >> 6;
#pragma unroll
    for (int i = 0; i < 8; i++) {
        int r = m0 + ty * 8 + i;
        int t = r >> 3, bi = r & 7;
        float res[4];
#pragma unroll
        for (int j = 0; j < 4; j++) {
            float vx = accv[i][j] + bva[j];
            float gx = accg[i][j] + bga[j];
            res[j] = vx * frcp_pos(1.0f + fexp(-gx));
        }
        float* dst = C + ((bi * 8 + h) * 1024 + t) * 64 + tx * 4;
        float4 v;
        if (accum) {
            float4 old = *(float4*)dst;
            v.x = old.x + res[0]; v.y = old.y + res[1];
            v.z = old.z + res[2]; v.w = old.w + res[3];
        } else {
            v.x = res[0]; v.y = res[1]; v.z = res[2]; v.w = res[3];
        }
        *(float4*)dst = v;
    }
}

// ---------------- per-row norms ----------------
__global__ void __launch_bounds__(256) norm_q_kernel()
{
    int row  = blockIdx.x * 8 + (threadIdx.x >> 5);
    int lane = threadIdx.x & 31;
    const float* p = g_qh + row * 64;
    float a = p[lane], b = p[lane + 32];
    float s = a * a + b * b;
#pragma unroll
    for (int o = 16; o; o >>= 1) s += __shfl_down_sync(0xffffffffu, s, o);
    if (lane == 0) g_ll[row] = s;
}

__global__ void __launch_bounds__(256) norm_k_kernel()
{
    int row  = blockIdx.x * 8 + (threadIdx.x >> 5);
    int lane = threadIdx.x & 31;
    const float* p1 = g_k1h + row * 64;
    const float* p2 = g_k2h + row * 64;
    float x0 = p1[lane], x1 = p1[lane + 32];
    float y0 = p2[lane], y1 = p2[lane + 32];
    float svv = x0 * x0 + x1 * x1;
    float saa = y0 * y0 + y1 * y1;
    float sva = x0 * y0 + x1 * y1;
#pragma unroll
    for (int o = 16; o; o >>= 1) {
        svv += __shfl_down_sync(0xffffffffu, svv, o);
        saa += __shfl_down_sync(0xffffffffu, saa, o);
        sva += __shfl_down_sync(0xffffffffu, sva, o);
    }
    if (lane == 0) { g_vv[row] = svv; g_aa[row] = saa; g_va[row] = sva; }
}

// ---------------- fused gram-det flash attention ----------------
#define FLASH_SMEM_FLOATS 32832
#define FLASH_SMEM_BYTES (FLASH_SMEM_FLOATS * 4)
__global__ void __launch_bounds__(256, 1) flash_kernel()
{
    extern __shared__ float sm[];
    float* qT      = sm;                 // [64][132]
    float* k1T     = qT  + 64 * 132;     // [64][68]
    float* k2T     = k1T + 64 * 68;      // [64][68]
    float* v_s     = k2T + 64 * 68;      // [64][64]
    float* p_s     = v_s + 64 * 64;      // [128][68]
    float* red     = p_s + 128 * 68;     // [128][17]
    float* m_row   = red + 128 * 17;     // [128]
    float* l_row   = m_row + 128;
    float* alpha_s = l_row + 128;
    float* ll_s    = alpha_s + 128;
    float* vv_s    = ll_s + 128;
    float* aa_s    = vv_s + 64;
    float* va_s    = aa_s + 64;

    const int tid = threadIdx.x;
    const int tx = tid & 15, ty = tid >> 4;
    const int bh = blockIdx.y;
    const int l0 = blockIdx.x * 128;

    {
        const float* qp = g_qh + (bh * 1024 + l0) * 64;
#pragma unroll
        for (int u = 0; u < 8; u++) {
            int id = tid + u * 256;
            int r = id >> 4;
            int c4 = (id & 15) << 2;
            float4 a = *(const float4*)(qp + r * 64 + c4);
            qT[(c4 + 0) * 132 + r] = a.x;
            qT[(c4 + 1) * 132 + r] = a.y;
            qT[(c4 + 2) * 132 + r] = a.z;
            qT[(c4 + 3) * 132 + r] = a.w;
        }
    }
    if (tid < 128) {
        m_row[tid] = -1e30f;
        l_row[tid] = 0.f;
        ll_s[tid]  = g_ll[bh * 1024 + l0 + tid];
    }
    u64 po[8][2];
#pragma unroll
    for (int i = 0; i < 8; i++) { po[i][0] = 0ull; po[i][1] = 0ull; }

    for (int s0 = 0; s0 < 1024; s0 += 64) {
        __syncthreads();
        const float* k1p = g_k1h + (bh * 1024 + s0) * 64;
        const float* k2p = g_k2h + (bh * 1024 + s0) * 64;
        const float* vp  = g_vh  + (bh * 1024 + s0) * 64;
#pragma unroll
        for (int u = 0; u < 4; u++) {
            int id = tid + u * 256;
            int r = id >> 4;
            int c4 = (id & 15) << 2;
            float4 a = *(const float4*)(k1p + r * 64 + c4);
            k1T[(c4 + 0) * 68 + r] = a.x; k1T[(c4 + 1) * 68 + r] = a.y;
            k1T[(c4 + 2) * 68 + r] = a.z; k1T[(c4 + 3) * 68 + r] = a.w;
            float4 b = *(const float4*)(k2p + r * 64 + c4);
            k2T[(c4 + 0) * 68 + r] = b.x; k2T[(c4 + 1) * 68 + r] = b.y;
            k2T[(c4 + 2) * 68 + r] = b.z; k2T[(c4 + 3) * 68 + r] = b.w;
            float4 c = *(const float4*)(vp + r * 64 + c4);
            *(float4*)(v_s + r * 64 + c4) = c;
        }
        if (tid < 64) {
            vv_s[tid] = g_vv[bh * 1024 + s0 + tid];
            aa_s[tid] = g_aa[bh * 1024 + s0 + tid];
            va_s[tid] = g_va[bh * 1024 + s0 + tid];
        }
        __syncthreads();

        // QK1^T / QK2^T with packed f32x2, pairs over the i (q-row) axis
        u64 plv[4][4], pla[4][4];
#pragma unroll
        for (int i = 0; i < 4; i++)
#pragma unroll
            for (int j = 0; j < 4; j++) { plv[i][j] = 0ull; pla[i][j] = 0ull; }
#pragma unroll 4
        for (int d = 0; d < 64; d++) {
            const u64* ap = (const u64*)(qT + d * 132 + ty * 8);
            u64 a0 = ap[0], a1 = ap[1], a2 = ap[2], a3 = ap[3];
            float4 b1 = *(const float4*)(k1T + d * 68 + tx * 4);
            float4 b2 = *(const float4*)(k2T + d * 68 + tx * 4);
            u64 c0 = f2dup(b1.x), c1 = f2dup(b1.y), c2 = f2dup(b1.z), c3 = f2dup(b1.w);
            u64 e0 = f2dup(b2.x), e1 = f2dup(b2.y), e2 = f2dup(b2.z), e3 = f2dup(b2.w);
            plv[0][0] = f2fma(a0, c0, plv[0][0]); plv[0][1] = f2fma(a0, c1, plv[0][1]);
            plv[0][2] = f2fma(a0, c2, plv[0][2]); plv[0][3] = f2fma(a0, c3, plv[0][3]);
            plv[1][0] = f2fma(a1, c0, plv[1][0]); plv[1][1] = f2fma(a1, c1, plv[1][1]);
            plv[1][2] = f2fma(a1, c2, plv[1][2]); plv[1][3] = f2fma(a1, c3, plv[1][3]);
            plv[2][0] = f2fma(a2, c0, plv[2][0]); plv[2][1] = f2fma(a2, c1, plv[2][1]);
            plv[2][2] = f2fma(a2, c2, plv[2][2]); plv[2][3] = f2fma(a2, c3, plv[2][3]);
            plv[3][0] = f2fma(a3, c0, plv[3][0]); plv[3][1] = f2fma(a3, c1, plv[3][1]);
            plv[3][2] = f2fma(a3, c2, plv[3][2]); plv[3][3] = f2fma(a3, c3, plv[3][3]);
            pla[0][0] = f2fma(a0, e0, pla[0][0]); pla[0][1] = f2fma(a0, e1, pla[0][1]);
            pla[0][2] = f2fma(a0, e2, pla[0][2]); pla[0][3] = f2fma(a0, e3, pla[0][3]);
            pla[1][0] = f2fma(a1, e0, pla[1][0]); pla[1][1] = f2fma(a1, e1, pla[1][1]);
            pla[1][2] = f2fma(a1, e2, pla[1][2]); pla[1][3] = f2fma(a1, e3, pla[1][3]);
            pla[2][0] = f2fma(a2, e0, pla[2][0]); pla[2][1] = f2fma(a2, e1, pla[2][1]);
            pla[2][2] = f2fma(a2, e2, pla[2][2]); pla[2][3] = f2fma(a2, e3, pla[2][3]);
            pla[3][0] = f2fma(a3, e0, pla[3][0]); pla[3][1] = f2fma(a3, e1, pla[3][1]);
            pla[3][2] = f2fma(a3, e2, pla[3][2]); pla[3][3] = f2fma(a3, e3, pla[3][3]);
        }

        float lv[8][4], la[8][4];
#pragma unroll
        for (int ip = 0; ip < 4; ip++)
#pragma unroll
            for (int j = 0; j < 4; j++) {
                float2 fv = f2upk(plv[ip][j]);
                float2 fa = f2upk(pla[ip][j]);
                lv[2 * ip][j] = fv.x; lv[2 * ip + 1][j] = fv.y;
                la[2 * ip][j] = fa.x; la[2 * ip + 1][j] = fa.y;
            }

        float cvv[4], caa[4], cva[4], g2[4];
#pragma unroll
        for (int j = 0; j < 4; j++) {
            cvv[j] = vv_s[tx * 4 + j];
            caa[j] = aa_s[tx * 4 + j];
            cva[j] = va_s[tx * 4 + j];
            g2[j]  = cvv[j] * caa[j] - cva[j] * cva[j];
        }
#pragma unroll
        for (int i = 0; i < 8; i++) {
            float lli = ll_s[ty * 8 + i];
            float mx = -1e30f;
#pragma unroll
            for (int j = 0; j < 4; j++) {
                float LV = lv[i][j], LA = la[i][j];
                float det = lli * g2[j]
                          - LV * (LV * caa[j] - LA * cva[j])
                          + LA * (LV * cva[j] - LA * cvv[j]);
                det = fmaxf(det, 1e-8f);
                float sc = -fsqrt_pos(det);
                lv[i][j] = sc;
                mx = fmaxf(mx, sc);
            }
            red[(ty * 8 + i) * 17 + tx] = mx;
        }
        __syncthreads();
        if (tid < 128) {
            float mo = m_row[tid];
            float tm = red[tid * 17];
#pragma unroll
            for (int c = 1; c < 16; c++) tm = fmaxf(tm, red[tid * 17 + c]);
            float mn = fmaxf(mo, tm);
            m_row[tid]   = mn;
            alpha_s[tid] = fexp(mo - mn);
        }
        __syncthreads();
#pragma unroll
        for (int i = 0; i < 8; i++) {
            float mn = m_row[ty * 8 + i];
            float p0 = fexp(lv[i][0] - mn);
            float p1 = fexp(lv[i][1] - mn);
            float p2 = fexp(lv[i][2] - mn);
            float p3 = fexp(lv[i][3] - mn);
            float4 pv; pv.x = p0; pv.y = p1; pv.z = p2; pv.w = p3;
            *(float4*)(p_s + (ty * 8 + i) * 68 + tx * 4) = pv;
            red[(ty * 8 + i) * 17 + tx] = p0 + p1 + p2 + p3;
        }
        __syncthreads();
        if (tid < 128) {
            float s = 0.f;
#pragma unroll
            for (int c = 0; c < 16; c++) s += red[tid * 17 + c];
            l_row[tid] = l_row[tid] * alpha_s[tid] + s;
        }
#pragma unroll
        for (int i = 0; i < 8; i++) {
            u64 ad = f2dup(alpha_s[ty * 8 + i]);
            po[i][0] = f2mul(po[i][0], ad);
            po[i][1] = f2mul(po[i][1], ad);
        }
#pragma unroll 4
        for (int s = 0; s < 64; s++) {
            const u64* vv2 = (const u64*)(v_s + s * 64 + tx * 4);
            u64 v01 = vv2[0], v23 = vv2[1];
#pragma unroll
            for (int i = 0; i < 8; i++) {
                u64 pd = f2dup(p_s[(ty * 8 + i) * 68 + s]);
                po[i][0] = f2fma(pd, v01, po[i][0]);
                po[i][1] = f2fma(pd, v23, po[i][1]);
            }
        }
    }

    __syncthreads();
    if (tid < 128) alpha_s[tid] = frcp_pos(l_row[tid]);
    __syncthreads();

    const int bi = bh >> 3, h = bh & 7;
#pragma unroll
    for (int i = 0; i < 8; i++) {
        int l = l0 + ty * 8 + i;
        float inv = alpha_s[ty * 8 + i];
        float2 f0 = f2upk(po[i][0]);
        float2 f1 = f2upk(po[i][1]);
        float4 v;
        v.x = f0.x * inv;
        v.y = f0.y * inv;
        v.z = f1.x * inv;
        v.w = f1.y * inv;
        *(float4*)(g_ao + (l * 8 + bi) * 512 + h * 64 + tx * 4) = v;
    }
}

// ---------------- launch ----------------
extern "C" void kernel_launch(void* const* d_in, const int* in_sizes, int n_in,
                              void* d_out, int out_size) {
    const float* query = (const float*)d_in[0];
    const float* mod1  = (const float*)d_in[1];
    const float* mod2  = (const float*)d_in[2];
    const float* Wq  = (const float*)d_in[3];  const float* bq  = (const float*)d_in[4];
    const float* Wk1 = (const float*)d_in[5];  const float* bk1 = (const float*)d_in[6];
    const float* Wk2 = (const float*)d_in[7];  const float* bk2 = (const float*)d_in[8];
    const float* Wv1 = (const float*)d_in[9];  const float* bv1 = (const float*)d_in[10];
    const float* Wv2 = (const float*)d_in[11]; const float* bv2 = (const float*)d_in[12];
    const float* Wg1 = (const float*)d_in[13]; const float* bg1 = (const float*)d_in[14];
    const float* Wg2 = (const float*)d_in[15]; const float* bg2 = (const float*)d_in[16];
    const float* Wo  = (const float*)d_in[17]; const float* bo  = (const float*)d_in[18];
    float* out = (float*)d_out;

    float *p_qh, *p_k1h, *p_k2h, *p_vh, *p_ao;
    cudaGetSymbolAddress((void**)&p_qh,  g_qh);
    cudaGetSymbolAddress((void**)&p_k1h, g_k1h);
    cudaGetSymbolAddress((void**)&p_k2h, g_k2h);
    cudaGetSymbolAddress((void**)&p_vh,  g_vh);
    cudaGetSymbolAddress((void**)&p_ao,  g_ao);

    cudaFuncSetAttribute(flash_kernel,
                         cudaFuncAttributeMaxDynamicSharedMemorySize,
                         FLASH_SMEM_BYTES);

    dim3 pg(64, 8), pb(256);
    proj_kernel<0><<<pg, pb>>>(query, Wq,  bq,  p_qh);
    proj_kernel<1><<<pg, pb>>>(mod1,  Wk1, bk1, p_k1h);
    proj_kernel<1><<<pg, pb>>>(mod2,  Wk2, bk2, p_k2h);
    projvg_kernel<<<pg, pb>>>(mod1, Wv1, bv1, Wg1, bg1, p_vh, 0);
    projvg_kernel<<<pg, pb>>>(mod2, Wv2, bv2, Wg2, bg2, p_vh, 1);
    norm_q_kernel<<<8192, 256>>>();
    norm_k_kernel<<<8192, 256>>>();
    flash_kernel<<<dim3(8, 64), 256, FLASH_SMEM_BYTES>>>();
    proj_kernel<2><<<pg, pb>>>(p_ao, Wo, bo, out);
}

// round 5
// speedup vs baseline: 1.4242x; 1.3645x over previous
#include <cuda_runtime.h>
#include <cuda_bf16.h>
#include <cstdint>

#define CL   1024
#define CS   1024
#define CB   8
#define CE   512
#define CH   8
#define CDH  64
#define CBH  64
#define CM   8192
#define CK   512

// ---------------- device scratch ----------------
__device__ __align__(128) float g_qh [CBH * CL * CDH];
__device__ __align__(128) float g_k1h[CBH * CS * CDH];
__device__ __align__(128) float g_k2h[CBH * CS * CDH];
__device__ __align__(128) float g_vh [CBH * CS * CDH];
__device__ __align__(128) float g_ao [CM * CE];
__device__ __align__(128) float g_ll [CBH * CL];
__device__ __align__(128) float g_vv [CBH * CS];
__device__ __align__(128) float g_aa [CBH * CS];
__device__ __align__(128) float g_va [CBH * CS];

// ---------------- packed f32x2 helpers (flash kernel) ----------------
typedef unsigned long long u64;
__device__ __forceinline__ u64 f2pk(float lo, float hi) {
    u64 r; asm("mov.b64 %0,{%1,%2};" : "=l"(r) : "f"(lo), "f"(hi)); return r;
}
__device__ __forceinline__ u64 f2dup(float x) { return f2pk(x, x); }
__device__ __forceinline__ u64 f2fma(u64 a, u64 b, u64 c) {
    u64 d; asm("fma.rn.f32x2 %0,%1,%2,%3;" : "=l"(d) : "l"(a), "l"(b), "l"(c)); return d;
}
__device__ __forceinline__ u64 f2mul(u64 a, u64 b) {
    u64 d; asm("mul.rn.f32x2 %0,%1,%2;" : "=l"(d) : "l"(a), "l"(b)); return d;
}
__device__ __forceinline__ float2 f2upk(u64 v) {
    float2 f; asm("mov.b64 {%0,%1},%2;" : "=f"(f.x), "=f"(f.y) : "l"(v)); return f;
}

// ---------------- MUFU-free math ----------------
__device__ __forceinline__ float fexp(float x) {
    float t = x * 1.4426950408889634f;
    t = fminf(fmaxf(t, -126.0f), 126.0f);
    int i = __float2int_rn(t);
    float u = (t - (float)i) * 0.6931471805599453f;
    float p = 1.3888889e-3f;
    p = fmaf(p, u, 8.3333333e-3f);
    p = fmaf(p, u, 4.1666667e-2f);
    p = fmaf(p, u, 1.6666667e-1f);
    p = fmaf(p, u, 0.5f);
    p = fmaf(p, u, 1.0f);
    p = fmaf(p, u, 1.0f);
    return p * __int_as_float((i + 127) << 23);
}
__device__ __forceinline__ float fsqrt_pos(float x) {
    float y = __int_as_float(0x5f3759df - (__float_as_int(x) >> 1));
    y = y * fmaf(-0.5f * x, y * y, 1.5f);
    y = y * fmaf(-0.5f * x, y * y, 1.5f);
    y = y * fmaf(-0.5f * x, y * y, 1.5f);
    return x * y;
}
__device__ __forceinline__ float frcp_pos(float x) {
    float y = __int_as_float(0x7EF127EAu - __float_as_int(x));
    y = y * (2.0f - x * y);
    y = y * (2.0f - x * y);
    y = y * (2.0f - x * y);
    return y;
}

// ---------------- mma.sync bf16 helper ----------------
__device__ __forceinline__ void mma16816(float* c,
    uint32_t a0, uint32_t a1, uint32_t a2, uint32_t a3,
    uint32_t b0, uint32_t b1)
{
    asm volatile(
        "mma.sync.aligned.m16n8k16.row.col.f32.bf16.bf16.f32 "
        "{%0,%1,%2,%3},{%4,%5,%6,%7},{%8,%9},{%0,%1,%2,%3};"
        : "+f"(c[0]), "+f"(c[1]), "+f"(c[2]), "+f"(c[3])
        : "r"(a0), "r"(a1), "r"(a2), "r"(a3), "r"(b0), "r"(b1));
}

// fp32 -> (hi,lo) bf16 split, 4 consecutive k elements
#define GP 72   // smem row pitch in bf16 elements (64 + 8 pad)
__device__ __forceinline__ uint32_t pkbf(__nv_bfloat16 a, __nv_bfloat16 b) {
    __nv_bfloat162 t(a, b);
    return *reinterpret_cast<uint32_t*>(&t);
}
__device__ __forceinline__ void split_store(__nv_bfloat16* hi, __nv_bfloat16* lo,
                                            int r, int g, float4 x)
{
    __nv_bfloat16 h0 = __float2bfloat16(x.x);
    __nv_bfloat16 h1 = __float2bfloat16(x.y);
    __nv_bfloat16 h2 = __float2bfloat16(x.z);
    __nv_bfloat16 h3 = __float2bfloat16(x.w);
    __nv_bfloat16 l0 = __float2bfloat16(x.x - __bfloat162float(h0));
    __nv_bfloat16 l1 = __float2bfloat16(x.y - __bfloat162float(h1));
    __nv_bfloat16 l2 = __float2bfloat16(x.z - __bfloat162float(h2));
    __nv_bfloat16 l3 = __float2bfloat16(x.w - __bfloat162float(h3));
    int off = r * GP + g * 4;
    *(uint2*)(hi + off) = make_uint2(pkbf(h0, h1), pkbf(h2, h3));
    *(uint2*)(lo + off) = make_uint2(pkbf(l0, l1), pkbf(l2, l3));
}

#define TSZ (128 * GP)

// =====================================================================
// proj_mma<MODE>: C = (A @ W^T + b) [*0.125]
//   MODE 0: head-major out, *0.125 | MODE 1: head-major | MODE 2: row-major
//   CTA: 128x128 tile, 8 warps (2m x 4n), warp tile 64x32, bf16 split HMMA.
// =====================================================================
#define PJ_SMEM_B (4 * TSZ * 2)

template<int MODE>
__global__ void __launch_bounds__(256)
proj_mma(const float* __restrict__ A, const float* __restrict__ W,
         const float* __restrict__ bias, float* __restrict__ C)
{
    extern __shared__ __nv_bfloat16 sb16[];
    __nv_bfloat16* Ah = sb16;
    __nv_bfloat16* Al = sb16 + TSZ;
    __nv_bfloat16* Wh = sb16 + 2 * TSZ;
    __nv_bfloat16* Wl = sb16 + 3 * TSZ;

    const int tid = threadIdx.x;
    const int wid = tid >> 5, lane = tid & 31;
    const int wm = wid >> 2, wn = wid & 3;
    const int m0 = blockIdx.x * 128;
    const int n0 = blockIdx.y * 128;
    const int lq = lane >> 2;           // quad row
    const int lk = (lane & 3) * 2;      // k offset within fragment

    float acc[4][4][4];
#pragma unroll
    for (int a = 0; a < 4; a++)
#pragma unroll
        for (int b = 0; b < 4; b++)
#pragma unroll
            for (int c = 0; c < 4; c++) acc[a][b][c] = 0.f;

    for (int blk = 0; blk < 8; blk++) {
        const int k0 = blk * 64;
        __syncthreads();
#pragma unroll
        for (int u = 0; u < 8; u++) {
            int id = tid + u * 256;
            int r = id >> 4, g = id & 15;
            float4 x = *(const float4*)(A + (size_t)(m0 + r) * CK + k0 + g * 4);
            split_store(Ah, Al, r, g, x);
            float4 y = *(const float4*)(W + (size_t)(n0 + r) * CK + k0 + g * 4);
            split_store(Wh, Wl, r, g, y);
        }
        __syncthreads();

#pragma unroll
        for (int ks = 0; ks < 4; ks++) {
            uint32_t ah[4][4], al[4][4];
#pragma unroll
            for (int mt = 0; mt < 4; mt++) {
                const __nv_bfloat16* ar = Ah + (wm * 64 + mt * 16 + lq) * GP + ks * 16 + lk;
                ah[mt][0] = *(const uint32_t*)ar;
                ah[mt][1] = *(const uint32_t*)(ar + 8 * GP);
                ah[mt][2] = *(const uint32_t*)(ar + 8);
                ah[mt][3] = *(const uint32_t*)(ar + 8 * GP + 8);
                const __nv_bfloat16* al_ = Al + (wm * 64 + mt * 16 + lq) * GP + ks * 16 + lk;
                al[mt][0] = *(const uint32_t*)al_;
                al[mt][1] = *(const uint32_t*)(al_ + 8 * GP);
                al[mt][2] = *(const uint32_t*)(al_ + 8);
                al[mt][3] = *(const uint32_t*)(al_ + 8 * GP + 8);
            }
#pragma unroll
            for (int nt = 0; nt < 4; nt++) {
                const __nv_bfloat16* bh = Wh + (wn * 32 + nt * 8 + lq) * GP + ks * 16 + lk;
                uint32_t bh0 = *(const uint32_t*)bh;
                uint32_t bh1 = *(const uint32_t*)(bh + 8);
                const __nv_bfloat16* bl = Wl + (wn * 32 + nt * 8 + lq) * GP + ks * 16 + lk;
                uint32_t bl0 = *(const uint32_t*)bl;
                uint32_t bl1 = *(const uint32_t*)(bl + 8);
#pragma unroll
                for (int mt = 0; mt < 4; mt++) {
                    mma16816(acc[mt][nt], ah[mt][0], ah[mt][1], ah[mt][2], ah[mt][3], bh0, bh1);
                    mma16816(acc[mt][nt], ah[mt][0], ah[mt][1], ah[mt][2], ah[mt][3], bl0, bl1);
                    mma16816(acc[mt][nt], al[mt][0], al[mt][1], al[mt][2], al[mt][3], bh0, bh1);
                }
            }
        }
    }

    // epilogue
#pragma unroll
    for (int mt = 0; mt < 4; mt++) {
#pragma unroll
        for (int nt = 0; nt < 4; nt++) {
            int row = m0 + wm * 64 + mt * 16 + lq;
            int col = n0 + wn * 32 + nt * 8 + lk;
            float b0 = bias[col], b1 = bias[col + 1];
#pragma unroll
            for (int half = 0; half < 2; half++) {
                int r = row + half * 8;
                float2 v;
                v.x = acc[mt][nt][half * 2 + 0] + b0;
                v.y = acc[mt][nt][half * 2 + 1] + b1;
                if (MODE == 0) { v.x *= 0.125f; v.y *= 0.125f; }
                if (MODE <= 1) {
                    int t = r >> 3, bi = r & 7;
                    int h = col >> 6, d = col & 63;
                    *(float2*)(C + ((size_t)(bi * 8 + h) * 1024 + t) * 64 + d) = v;
                } else {
                    *(float2*)(C + (size_t)r * CE + col) = v;
                }
            }
        }
    }
}

// =====================================================================
// projvg_mma: C (+)= (A@Wv^T+bv) * sigmoid(A@Wg^T+bg), head-major out
// =====================================================================
#define VG_SMEM_B (6 * TSZ * 2)

__global__ void __launch_bounds__(256)
projvg_mma(const float* __restrict__ A,
           const float* __restrict__ Wv, const float* __restrict__ bv,
           const float* __restrict__ Wg, const float* __restrict__ bg,
           float* __restrict__ C, int accum)
{
    extern __shared__ __nv_bfloat16 sb16[];
    __nv_bfloat16* Ah = sb16;
    __nv_bfloat16* Al = sb16 + TSZ;
    __nv_bfloat16* Vh = sb16 + 2 * TSZ;
    __nv_bfloat16* Vl = sb16 + 3 * TSZ;
    __nv_bfloat16* Gh = sb16 + 4 * TSZ;
    __nv_bfloat16* Gl = sb16 + 5 * TSZ;

    const int tid = threadIdx.x;
    const int wid = tid >> 5, lane = tid & 31;
    const int wm = wid >> 2, wn = wid & 3;
    const int m0 = blockIdx.x * 128;
    const int n0 = blockIdx.y * 128;
    const int lq = lane >> 2;
    const int lk = (lane & 3) * 2;

    float av_[4][4][4], ag_[4][4][4];
#pragma unroll
    for (int a = 0; a < 4; a++)
#pragma unroll
        for (int b = 0; b < 4; b++)
#pragma unroll
            for (int c = 0; c < 4; c++) { av_[a][b][c] = 0.f; ag_[a][b][c] = 0.f; }

    for (int blk = 0; blk < 8; blk++) {
        const int k0 = blk * 64;
        __syncthreads();
#pragma unroll
        for (int u = 0; u < 8; u++) {
            int id = tid + u * 256;
            int r = id >> 4, g = id & 15;
            float4 x = *(const float4*)(A  + (size_t)(m0 + r) * CK + k0 + g * 4);
            split_store(Ah, Al, r, g, x);
            float4 y = *(const float4*)(Wv + (size_t)(n0 + r) * CK + k0 + g * 4);
            split_store(Vh, Vl, r, g, y);
            float4 z = *(const float4*)(Wg + (size_t)(n0 + r) * CK + k0 + g * 4);
            split_store(Gh, Gl, r, g, z);
        }
        __syncthreads();

#pragma unroll
        for (int ks = 0; ks < 4; ks++) {
            uint32_t ah[4][4], al[4][4];
#pragma unroll
            for (int mt = 0; mt < 4; mt++) {
                const __nv_bfloat16* ar = Ah + (wm * 64 + mt * 16 + lq) * GP + ks * 16 + lk;
                ah[mt][0] = *(const uint32_t*)ar;
                ah[mt][1] = *(const uint32_t*)(ar + 8 * GP);
                ah[mt][2] = *(const uint32_t*)(ar + 8);
                ah[mt][3] = *(const uint32_t*)(ar + 8 * GP + 8);
                const __nv_bfloat16* al_ = Al + (wm * 64 + mt * 16 + lq) * GP + ks * 16 + lk;
                al[mt][0] = *(const uint32_t*)al_;
                al[mt][1] = *(const uint32_t*)(al_ + 8 * GP);
                al[mt][2] = *(const uint32_t*)(al_ + 8);
                al[mt][3] = *(const uint32_t*)(al_ + 8 * GP + 8);
            }
#pragma unroll
            for (int nt = 0; nt < 4; nt++) {
                const __nv_bfloat16* vh = Vh + (wn * 32 + nt * 8 + lq) * GP + ks * 16 + lk;
                uint32_t vh0 = *(const uint32_t*)vh;
                uint32_t vh1 = *(const uint32_t*)(vh + 8);
                const __nv_bfloat16* vl = Vl + (wn * 32 + nt * 8 + lq) * GP + ks * 16 + lk;
                uint32_t vl0 = *(const uint32_t*)vl;
                uint32_t vl1 = *(const uint32_t*)(vl + 8);
                const __nv_bfloat16* gh = Gh + (wn * 32 + nt * 8 + lq) * GP + ks * 16 + lk;
                uint32_t gh0 = *(const uint32_t*)gh;
                uint32_t gh1 = *(const uint32_t*)(gh + 8);
                const __nv_bfloat16* gl = Gl + (wn * 32 + nt * 8 + lq) * GP + ks * 16 + lk;
                uint32_t gl0 = *(const uint32_t*)gl;
                uint32_t gl1 = *(const uint32_t*)(gl + 8);
#pragma unroll
                for (int mt = 0; mt < 4; mt++) {
                    mma16816(av_[mt][nt], ah[mt][0], ah[mt][1], ah[mt][2], ah[mt][3], vh0, vh1);
                    mma16816(av_[mt][nt], ah[mt][0], ah[mt][1], ah[mt][2], ah[mt][3], vl0, vl1);
                    mma16816(av_[mt][nt], al[mt][0], al[mt][1], al[mt][2], al[mt][3], vh0, vh1);
                    mma16816(ag_[mt][nt], ah[mt][0], ah[mt][1], ah[mt][2], ah[mt][3], gh0, gh1);
                    mma16816(ag_[mt][nt], ah[mt][0], ah[mt][1], ah[mt][2], ah[mt][3], gl0, gl1);
                    mma16816(ag_[mt][nt], al[mt][0], al[mt][1], al[mt][2], al[mt][3], gh0, gh1);
                }
            }
        }
    }

#pragma unroll
    for (int mt = 0; mt < 4; mt++) {
#pragma unroll
        for (int nt = 0; nt < 4; nt++) {
            int row = m0 + wm * 64 + mt * 16 + lq;
            int col = n0 + wn * 32 + nt * 8 + lk;
            float bv0 = bv[col], bv1 = bv[col + 1];
            float bg0 = bg[col], bg1 = bg[col + 1];
            int h = col >> 6, d = col & 63;
#pragma unroll
            for (int half = 0; half < 2; half++) {
                int r = row + half * 8;
                int t = r >> 3, bi = r & 7;
                float vx0 = av_[mt][nt][half * 2 + 0] + bv0;
                float vx1 = av_[mt][nt][half * 2 + 1] + bv1;
                float gx0 = ag_[mt][nt][half * 2 + 0] + bg0;
                float gx1 = ag_[mt][nt][half * 2 + 1] + bg1;
                float2 v;
                v.x = vx0 * frcp_pos(1.0f + fexp(-gx0));
                v.y = vx1 * frcp_pos(1.0f + fexp(-gx1));
                float* dst = C + ((size_t)(bi * 8 + h) * 1024 + t) * 64 + d;
                if (accum) {
                    float2 old = *(float2*)dst;
                    v.x += old.x; v.y += old.y;
                }
                *(float2*)dst = v;
            }
        }
    }
}

// ---------------- per-row norms ----------------
__global__ void __launch_bounds__(256) norm_q_kernel()
{
    int row  = blockIdx.x * 8 + (threadIdx.x >> 5);
    int lane = threadIdx.x & 31;
    const float* p = g_qh + row * 64;
    float a = p[lane], b = p[lane + 32];
    float s = a * a + b * b;
#pragma unroll
    for (int o = 16; o; o >>= 1) s += __shfl_down_sync(0xffffffffu, s, o);
    if (lane == 0) g_ll[row] = s;
}

__global__ void __launch_bounds__(256) norm_k_kernel()
{
    int row  = blockIdx.x * 8 + (threadIdx.x >> 5);
    int lane = threadIdx.x & 31;
    const float* p1 = g_k1h + row * 64;
    const float* p2 = g_k2h + row * 64;
    float x0 = p1[lane], x1 = p1[lane + 32];
    float y0 = p2[lane], y1 = p2[lane + 32];
    float svv = x0 * x0 + x1 * x1;
    float saa = y0 * y0 + y1 * y1;
    float sva = x0 * y0 + x1 * y1;
#pragma unroll
    for (int o = 16; o; o >>= 1) {
        svv += __shfl_down_sync(0xffffffffu, svv, o);
        saa += __shfl_down_sync(0xffffffffu, saa, o);
        sva += __shfl_down_sync(0xffffffffu, sva, o);
    }
    if (lane == 0) { g_vv[row] = svv; g_aa[row] = saa; g_va[row] = sva; }
}

// ---------------- fused gram-det flash attention (R2, passing) ----------------
#define FLASH_SMEM_FLOATS 32832
#define FLASH_SMEM_BYTES (FLASH_SMEM_FLOATS * 4)
__global__ void __launch_bounds__(256, 1) flash_kernel()
{
    extern __shared__ float sm[];
    float* qT      = sm;                 // [64][132]
    float* k1T     = qT  + 64 * 132;     // [64][68]
    float* k2T     = k1T + 64 * 68;      // [64][68]
    float* v_s     = k2T + 64 * 68;      // [64][64]
    float* p_s     = v_s + 64 * 64;      // [128][68]
    float* red     = p_s + 128 * 68;     // [128][17]
    float* m_row   = red + 128 * 17;     // [128]
    float* l_row   = m_row + 128;
    float* alpha_s = l_row + 128;
    float* ll_s    = alpha_s + 128;
    float* vv_s    = ll_s + 128;
    float* aa_s    = vv_s + 64;
    float* va_s    = aa_s + 64;

    const int tid = threadIdx.x;
    const int tx = tid & 15, ty = tid >> 4;
    const int bh = blockIdx.y;
    const int l0 = blockIdx.x * 128;

    {
        const float* qp = g_qh + (bh * 1024 + l0) * 64;
#pragma unroll
        for (int u = 0; u < 8; u++) {
            int id = tid + u * 256;
            int r = id >> 4;
            int c4 = (id & 15) << 2;
            float4 a = *(const float4*)(qp + r * 64 + c4);
            qT[(c4 + 0) * 132 + r] = a.x;
            qT[(c4 + 1) * 132 + r] = a.y;
            qT[(c4 + 2) * 132 + r] = a.z;
            qT[(c4 + 3) * 132 + r] = a.w;
        }
    }
    if (tid < 128) {
        m_row[tid] = -1e30f;
        l_row[tid] = 0.f;
        ll_s[tid]  = g_ll[bh * 1024 + l0 + tid];
    }
    u64 po[8][2];
#pragma unroll
    for (int i = 0; i < 8; i++) { po[i][0] = 0ull; po[i][1] = 0ull; }

    for (int s0 = 0; s0 < 1024; s0 += 64) {
        __syncthreads();
        const float* k1p = g_k1h + (bh * 1024 + s0) * 64;
        const float* k2p = g_k2h + (bh * 1024 + s0) * 64;
        const float* vp  = g_vh  + (bh * 1024 + s0) * 64;
#pragma unroll
        for (int u = 0; u < 4; u++) {
            int id = tid + u * 256;
            int r = id >> 4;
            int c4 = (id & 15) << 2;
            float4 a = *(const float4*)(k1p + r * 64 + c4);
            k1T[(c4 + 0) * 68 + r] = a.x; k1T[(c4 + 1) * 68 + r] = a.y;
            k1T[(c4 + 2) * 68 + r] = a.z; k1T[(c4 + 3) * 68 + r] = a.w;
            float4 b = *(const float4*)(k2p + r * 64 + c4);
            k2T[(c4 + 0) * 68 + r] = b.x; k2T[(c4 + 1) * 68 + r] = b.y;
            k2T[(c4 + 2) * 68 + r] = b.z; k2T[(c4 + 3) * 68 + r] = b.w;
            float4 c = *(const float4*)(vp + r * 64 + c4);
            *(float4*)(v_s + r * 64 + c4) = c;
        }
        if (tid < 64) {
            vv_s[tid] = g_vv[bh * 1024 + s0 + tid];
            aa_s[tid] = g_aa[bh * 1024 + s0 + tid];
            va_s[tid] = g_va[bh * 1024 + s0 + tid];
        }
        __syncthreads();

        u64 plv[4][4], pla[4][4];
#pragma unroll
        for (int i = 0; i < 4; i++)
#pragma unroll
            for (int j = 0; j < 4; j++) { plv[i][j] = 0ull; pla[i][j] = 0ull; }
#pragma unroll 4
        for (int d = 0; d < 64; d++) {
            const u64* ap = (const u64*)(qT + d * 132 + ty * 8);
            u64 a0 = ap[0], a1 = ap[1], a2 = ap[2], a3 = ap[3];
            float4 b1 = *(const float4*)(k1T + d * 68 + tx * 4);
            float4 b2 = *(const float4*)(k2T + d * 68 + tx * 4);
            u64 c0 = f2dup(b1.x), c1 = f2dup(b1.y), c2 = f2dup(b1.z), c3 = f2dup(b1.w);
            u64 e0 = f2dup(b2.x), e1 = f2dup(b2.y), e2 = f2dup(b2.z), e3 = f2dup(b2.w);
            plv[0][0] = f2fma(a0, c0, plv[0][0]); plv[0][1] = f2fma(a0, c1, plv[0][1]);
            plv[0][2] = f2fma(a0, c2, plv[0][2]); plv[0][3] = f2fma(a0, c3, plv[0][3]);
            plv[1][0] = f2fma(a1, c0, plv[1][0]); plv[1][1] = f2fma(a1, c1, plv[1][1]);
            plv[1][2] = f2fma(a1, c2, plv[1][2]); plv[1][3] = f2fma(a1, c3, plv[1][3]);
            plv[2][0] = f2fma(a2, c0, plv[2][0]); plv[2][1] = f2fma(a2, c1, plv[2][1]);
            plv[2][2] = f2fma(a2, c2, plv[2][2]); plv[2][3] = f2fma(a2, c3, plv[2][3]);
            plv[3][0] = f2fma(a3, c0, plv[3][0]); plv[3][1] = f2fma(a3, c1, plv[3][1]);
            plv[3][2] = f2fma(a3, c2, plv[3][2]); plv[3][3] = f2fma(a3, c3, plv[3][3]);
            pla[0][0] = f2fma(a0, e0, pla[0][0]); pla[0][1] = f2fma(a0, e1, pla[0][1]);
            pla[0][2] = f2fma(a0, e2, pla[0][2]); pla[0][3] = f2fma(a0, e3, pla[0][3]);
            pla[1][0] = f2fma(a1, e0, pla[1][0]); pla[1][1] = f2fma(a1, e1, pla[1][1]);
            pla[1][2] = f2fma(a1, e2, pla[1][2]); pla[1][3] = f2fma(a1, e3, pla[1][3]);
            pla[2][0] = f2fma(a2, e0, pla[2][0]); pla[2][1] = f2fma(a2, e1, pla[2][1]);
            pla[2][2] = f2fma(a2, e2, pla[2][2]); pla[2][3] = f2fma(a2, e3, pla[2][3]);
            pla[3][0] = f2fma(a3, e0, pla[3][0]); pla[3][1] = f2fma(a3, e1, pla[3][1]);
            pla[3][2] = f2fma(a3, e2, pla[3][2]); pla[3][3] = f2fma(a3, e3, pla[3][3]);
        }

        float lv[8][4], la[8][4];
#pragma unroll
        for (int ip = 0; ip < 4; ip++)
#pragma unroll
            for (int j = 0; j < 4; j++) {
                float2 fv = f2upk(plv[ip][j]);
                float2 fa = f2upk(pla[ip][j]);
                lv[2 * ip][j] = fv.x; lv[2 * ip + 1][j] = fv.y;
                la[2 * ip][j] = fa.x; la[2 * ip + 1][j] = fa.y;
            }

        float cvv[4], caa[4], cva[4], g2[4];
#pragma unroll
        for (int j = 0; j < 4; j++) {
            cvv[j] = vv_s[tx * 4 + j];
            caa[j] = aa_s[tx * 4 + j];
            cva[j] = va_s[tx * 4 + j];
            g2[j]  = cvv[j] * caa[j] - cva[j] * cva[j];
        }
#pragma unroll
        for (int i = 0; i < 8; i++) {
            float lli = ll_s[ty * 8 + i];
            float mx = -1e30f;
#pragma unroll
            for (int j = 0; j < 4; j++) {
                float LV = lv[i][j], LA = la[i][j];
                float det = lli * g2[j]
                          - LV * (LV * caa[j] - LA * cva[j])
                          + LA * (LV * cva[j] - LA * cvv[j]);
                det = fmaxf(det, 1e-8f);
                float sc = -fsqrt_pos(det);
                lv[i][j] = sc;
                mx = fmaxf(mx, sc);
            }
            red[(ty * 8 + i) * 17 + tx] = mx;
        }
        __syncthreads();
        if (tid < 128) {
            float mo = m_row[tid];
            float tm = red[tid * 17];
#pragma unroll
            for (int c = 1; c < 16; c++) tm = fmaxf(tm, red[tid * 17 + c]);
            float mn = fmaxf(mo, tm);
            m_row[tid]   = mn;
            alpha_s[tid] = fexp(mo - mn);
        }
        __syncthreads();
#pragma unroll
        for (int i = 0; i < 8; i++) {
            float mn = m_row[ty * 8 + i];
            float p0 = fexp(lv[i][0] - mn);
            float p1 = fexp(lv[i][1] - mn);
            float p2 = fexp(lv[i][2] - mn);
            float p3 = fexp(lv[i][3] - mn);
            float4 pv; pv.x = p0; pv.y = p1; pv.z = p2; pv.w = p3;
            *(float4*)(p_s + (ty * 8 + i) * 68 + tx * 4) = pv;
            red[(ty * 8 + i) * 17 + tx] = p0 + p1 + p2 + p3;
        }
        __syncthreads();
        if (tid < 128) {
            float s = 0.f;
#pragma unroll
            for (int c = 0; c < 16; c++) s += red[tid * 17 + c];
            l_row[tid] = l_row[tid] * alpha_s[tid] + s;
        }
#pragma unroll
        for (int i = 0; i < 8; i++) {
            u64 ad = f2dup(alpha_s[ty * 8 + i]);
            po[i][0] = f2mul(po[i][0], ad);
            po[i][1] = f2mul(po[i][1], ad);
        }
#pragma unroll 4
        for (int s = 0; s < 64; s++) {
            const u64* vv2 = (const u64*)(v_s + s * 64 + tx * 4);
            u64 v01 = vv2[0], v23 = vv2[1];
#pragma unroll
            for (int i = 0; i < 8; i++) {
                u64 pd = f2dup(p_s[(ty * 8 + i) * 68 + s]);
                po[i][0] = f2fma(pd, v01, po[i][0]);
                po[i][1] = f2fma(pd, v23, po[i][1]);
            }
        }
    }

    __syncthreads();
    if (tid < 128) alpha_s[tid] = frcp_pos(l_row[tid]);
    __syncthreads();

    const int bi = bh >> 3, h = bh & 7;
#pragma unroll
    for (int i = 0; i < 8; i++) {
        int l = l0 + ty * 8 + i;
        float inv = alpha_s[ty * 8 + i];
        float2 f0 = f2upk(po[i][0]);
        float2 f1 = f2upk(po[i][1]);
        float4 v;
        v.x = f0.x * inv;
        v.y = f0.y * inv;
        v.z = f1.x * inv;
        v.w = f1.y * inv;
        *(float4*)(g_ao + (l * 8 + bi) * 512 + h * 64 + tx * 4) = v;
    }
}

// ---------------- launch ----------------
extern "C" void kernel_launch(void* const* d_in, const int* in_sizes, int n_in,
                              void* d_out, int out_size) {
    const float* query = (const float*)d_in[0];
    const float* mod1  = (const float*)d_in[1];
    const float* mod2  = (const float*)d_in[2];
    const float* Wq  = (const float*)d_in[3];  const float* bq  = (const float*)d_in[4];
    const float* Wk1 = (const float*)d_in[5];  const float* bk1 = (const float*)d_in[6];
    const float* Wk2 = (const float*)d_in[7];  const float* bk2 = (const float*)d_in[8];
    const float* Wv1 = (const float*)d_in[9];  const float* bv1 = (const float*)d_in[10];
    const float* Wv2 = (const float*)d_in[11]; const float* bv2 = (const float*)d_in[12];
    const float* Wg1 = (const float*)d_in[13]; const float* bg1 = (const float*)d_in[14];
    const float* Wg2 = (const float*)d_in[15]; const float* bg2 = (const float*)d_in[16];
    const float* Wo  = (const float*)d_in[17]; const float* bo  = (const float*)d_in[18];
    float* out = (float*)d_out;

    float *p_qh, *p_k1h, *p_k2h, *p_vh, *p_ao;
    cudaGetSymbolAddress((void**)&p_qh,  g_qh);
    cudaGetSymbolAddress((void**)&p_k1h, g_k1h);
    cudaGetSymbolAddress((void**)&p_k2h, g_k2h);
    cudaGetSymbolAddress((void**)&p_vh,  g_vh);
    cudaGetSymbolAddress((void**)&p_ao,  g_ao);

    cudaFuncSetAttribute(proj_mma<0>, cudaFuncAttributeMaxDynamicSharedMemorySize, PJ_SMEM_B);
    cudaFuncSetAttribute(proj_mma<1>, cudaFuncAttributeMaxDynamicSharedMemorySize, PJ_SMEM_B);
    cudaFuncSetAttribute(proj_mma<2>, cudaFuncAttributeMaxDynamicSharedMemorySize, PJ_SMEM_B);
    cudaFuncSetAttribute(projvg_mma,  cudaFuncAttributeMaxDynamicSharedMemorySize, VG_SMEM_B);
    cudaFuncSetAttribute(flash_kernel, cudaFuncAttributeMaxDynamicSharedMemorySize, FLASH_SMEM_BYTES);

    dim3 pg(64, 4), pb(256);
    proj_mma<0><<<pg, pb, PJ_SMEM_B>>>(query, Wq,  bq,  p_qh);
    proj_mma<1><<<pg, pb, PJ_SMEM_B>>>(mod1,  Wk1, bk1, p_k1h);
    proj_mma<1><<<pg, pb, PJ_SMEM_B>>>(mod2,  Wk2, bk2, p_k2h);
    projvg_mma<<<pg, pb, VG_SMEM_B>>>(mod1, Wv1, bv1, Wg1, bg1, p_vh, 0);
    projvg_mma<<<pg, pb, VG_SMEM_B>>>(mod2, Wv2, bv2, Wg2, bg2, p_vh, 1);
    norm_q_kernel<<<8192, 256>>>();
    norm_k_kernel<<<8192, 256>>>();
    flash_kernel<<<dim3(8, 64), 256, FLASH_SMEM_BYTES>>>();
    proj_mma<2><<<pg, pb, PJ_SMEM_B>>>(p_ao, Wo, bo, out);
}

// round 6
// speedup vs baseline: 2.0806x; 1.4609x over previous
#include <cuda_runtime.h>
#include <cuda_bf16.h>
#include <cstdint>

#define CL   1024
#define CS   1024
#define CB   8
#define CE   512
#define CH   8
#define CDH  64
#define CBH  64
#define CM   8192
#define CK   512

// ---------------- device scratch ----------------
__device__ __align__(128) float g_qh [CBH * CL * CDH];
__device__ __align__(128) float g_k1h[CBH * CS * CDH];
__device__ __align__(128) float g_k2h[CBH * CS * CDH];
__device__ __align__(128) float g_vh [CBH * CS * CDH];
__device__ __align__(128) float g_ao [CM * CE];
__device__ __align__(128) float g_ll [CBH * CL];
__device__ __align__(128) float g_vv [CBH * CS];
__device__ __align__(128) float g_aa [CBH * CS];
__device__ __align__(128) float g_va [CBH * CS];

// ---------------- MUFU-free math ----------------
__device__ __forceinline__ float fexp(float x) {
    float t = x * 1.4426950408889634f;
    t = fminf(fmaxf(t, -126.0f), 126.0f);
    int i = __float2int_rn(t);
    float u = (t - (float)i) * 0.6931471805599453f;
    float p = 1.3888889e-3f;
    p = fmaf(p, u, 8.3333333e-3f);
    p = fmaf(p, u, 4.1666667e-2f);
    p = fmaf(p, u, 1.6666667e-1f);
    p = fmaf(p, u, 0.5f);
    p = fmaf(p, u, 1.0f);
    p = fmaf(p, u, 1.0f);
    return p * __int_as_float((i + 127) << 23);
}
__device__ __forceinline__ float fsqrt_pos(float x) {
    float y = __int_as_float(0x5f3759df - (__float_as_int(x) >> 1));
    y = y * fmaf(-0.5f * x, y * y, 1.5f);
    y = y * fmaf(-0.5f * x, y * y, 1.5f);
    y = y * fmaf(-0.5f * x, y * y, 1.5f);
    return x * y;
}
__device__ __forceinline__ float frcp_pos(float x) {
    float y = __int_as_float(0x7EF127EAu - __float_as_int(x));
    y = y * (2.0f - x * y);
    y = y * (2.0f - x * y);
    y = y * (2.0f - x * y);
    return y;
}

// ---------------- mma.sync bf16 helper ----------------
__device__ __forceinline__ void mma16816(float* c,
    uint32_t a0, uint32_t a1, uint32_t a2, uint32_t a3,
    uint32_t b0, uint32_t b1)
{
    asm volatile(
        "mma.sync.aligned.m16n8k16.row.col.f32.bf16.bf16.f32 "
        "{%0,%1,%2,%3},{%4,%5,%6,%7},{%8,%9},{%0,%1,%2,%3};"
        : "+f"(c[0]), "+f"(c[1]), "+f"(c[2]), "+f"(c[3])
        : "r"(a0), "r"(a1), "r"(a2), "r"(a3), "r"(b0), "r"(b1));
}

#define GP 72   // smem row pitch in bf16 elements
__device__ __forceinline__ uint32_t pkbf(__nv_bfloat16 a, __nv_bfloat16 b) {
    __nv_bfloat162 t(a, b);
    return *reinterpret_cast<uint32_t*>(&t);
}
__device__ __forceinline__ uint32_t pk_hi(float x, float y) {
    return pkbf(__float2bfloat16(x), __float2bfloat16(y));
}
__device__ __forceinline__ uint32_t pk_lo(float x, float y) {
    __nv_bfloat16 hx = __float2bfloat16(x), hy = __float2bfloat16(y);
    return pkbf(__float2bfloat16(x - __bfloat162float(hx)),
                __float2bfloat16(y - __bfloat162float(hy)));
}
__device__ __forceinline__ void split_store(__nv_bfloat16* hi, __nv_bfloat16* lo,
                                            int r, int g, float4 x)
{
    int off = r * GP + g * 4;
    *(uint2*)(hi + off) = make_uint2(pk_hi(x.x, x.y), pk_hi(x.z, x.w));
    *(uint2*)(lo + off) = make_uint2(pk_lo(x.x, x.y), pk_lo(x.z, x.w));
}

#define TSZ (128 * GP)

// =====================================================================
// proj_mma<MODE>: C = (A @ W^T + b) [*0.125]  (unchanged from R4)
// =====================================================================
#define PJ_SMEM_B (4 * TSZ * 2)

template<int MODE>
__global__ void __launch_bounds__(256)
proj_mma(const float* __restrict__ A, const float* __restrict__ W,
         const float* __restrict__ bias, float* __restrict__ C)
{
    extern __shared__ __nv_bfloat16 sb16[];
    __nv_bfloat16* Ah = sb16;
    __nv_bfloat16* Al = sb16 + TSZ;
    __nv_bfloat16* Wh = sb16 + 2 * TSZ;
    __nv_bfloat16* Wl = sb16 + 3 * TSZ;

    const int tid = threadIdx.x;
    const int wid = tid >> 5, lane = tid & 31;
    const int wm = wid >> 2, wn = wid & 3;
    const int m0 = blockIdx.x * 128;
    const int n0 = blockIdx.y * 128;
    const int lq = lane >> 2;
    const int lk = (lane & 3) * 2;

    float acc[4][4][4];
#pragma unroll
    for (int a = 0; a < 4; a++)
#pragma unroll
        for (int b = 0; b < 4; b++)
#pragma unroll
            for (int c = 0; c < 4; c++) acc[a][b][c] = 0.f;

    for (int blk = 0; blk < 8; blk++) {
        const int k0 = blk * 64;
        __syncthreads();
#pragma unroll
        for (int u = 0; u < 8; u++) {
            int id = tid + u * 256;
            int r = id >> 4, g = id & 15;
            float4 x = *(const float4*)(A + (size_t)(m0 + r) * CK + k0 + g * 4);
            split_store(Ah, Al, r, g, x);
            float4 y = *(const float4*)(W + (size_t)(n0 + r) * CK + k0 + g * 4);
            split_store(Wh, Wl, r, g, y);
        }
        __syncthreads();

#pragma unroll
        for (int ks = 0; ks < 4; ks++) {
            uint32_t ah[4][4], al[4][4];
#pragma unroll
            for (int mt = 0; mt < 4; mt++) {
                const __nv_bfloat16* ar = Ah + (wm * 64 + mt * 16 + lq) * GP + ks * 16 + lk;
                ah[mt][0] = *(const uint32_t*)ar;
                ah[mt][1] = *(const uint32_t*)(ar + 8 * GP);
                ah[mt][2] = *(const uint32_t*)(ar + 8);
                ah[mt][3] = *(const uint32_t*)(ar + 8 * GP + 8);
                const __nv_bfloat16* al_ = Al + (wm * 64 + mt * 16 + lq) * GP + ks * 16 + lk;
                al[mt][0] = *(const uint32_t*)al_;
                al[mt][1] = *(const uint32_t*)(al_ + 8 * GP);
                al[mt][2] = *(const uint32_t*)(al_ + 8);
                al[mt][3] = *(const uint32_t*)(al_ + 8 * GP + 8);
            }
#pragma unroll
            for (int nt = 0; nt < 4; nt++) {
                const __nv_bfloat16* bh = Wh + (wn * 32 + nt * 8 + lq) * GP + ks * 16 + lk;
                uint32_t bh0 = *(const uint32_t*)bh;
                uint32_t bh1 = *(const uint32_t*)(bh + 8);
                const __nv_bfloat16* bl = Wl + (wn * 32 + nt * 8 + lq) * GP + ks * 16 + lk;
                uint32_t bl0 = *(const uint32_t*)bl;
                uint32_t bl1 = *(const uint32_t*)(bl + 8);
#pragma unroll
                for (int mt = 0; mt < 4; mt++) {
                    mma16816(acc[mt][nt], ah[mt][0], ah[mt][1], ah[mt][2], ah[mt][3], bh0, bh1);
                    mma16816(acc[mt][nt], ah[mt][0], ah[mt][1], ah[mt][2], ah[mt][3], bl0, bl1);
                    mma16816(acc[mt][nt], al[mt][0], al[mt][1], al[mt][2], al[mt][3], bh0, bh1);
                }
            }
        }
    }

#pragma unroll
    for (int mt = 0; mt < 4; mt++) {
#pragma unroll
        for (int nt = 0; nt < 4; nt++) {
            int row = m0 + wm * 64 + mt * 16 + lq;
            int col = n0 + wn * 32 + nt * 8 + lk;
            float b0 = bias[col], b1 = bias[col + 1];
#pragma unroll
            for (int half = 0; half < 2; half++) {
                int r = row + half * 8;
                float2 v;
                v.x = acc[mt][nt][half * 2 + 0] + b0;
                v.y = acc[mt][nt][half * 2 + 1] + b1;
                if (MODE == 0) { v.x *= 0.125f; v.y *= 0.125f; }
                if (MODE <= 1) {
                    int t = r >> 3, bi = r & 7;
                    int h = col >> 6, d = col & 63;
                    *(float2*)(C + ((size_t)(bi * 8 + h) * 1024 + t) * 64 + d) = v;
                } else {
                    *(float2*)(C + (size_t)r * CE + col) = v;
                }
            }
        }
    }
}

// =====================================================================
// projvg_mma (unchanged from R4)
// =====================================================================
#define VG_SMEM_B (6 * TSZ * 2)

__global__ void __launch_bounds__(256)
projvg_mma(const float* __restrict__ A,
           const float* __restrict__ Wv, const float* __restrict__ bv,
           const float* __restrict__ Wg, const float* __restrict__ bg,
           float* __restrict__ C, int accum)
{
    extern __shared__ __nv_bfloat16 sb16[];
    __nv_bfloat16* Ah = sb16;
    __nv_bfloat16* Al = sb16 + TSZ;
    __nv_bfloat16* Vh = sb16 + 2 * TSZ;
    __nv_bfloat16* Vl = sb16 + 3 * TSZ;
    __nv_bfloat16* Gh = sb16 + 4 * TSZ;
    __nv_bfloat16* Gl = sb16 + 5 * TSZ;

    const int tid = threadIdx.x;
    const int wid = tid >> 5, lane = tid & 31;
    const int wm = wid >> 2, wn = wid & 3;
    const int m0 = blockIdx.x * 128;
    const int n0 = blockIdx.y * 128;
    const int lq = lane >> 2;
    const int lk = (lane & 3) * 2;

    float av_[4][4][4], ag_[4][4][4];
#pragma unroll
    for (int a = 0; a < 4; a++)
#pragma unroll
        for (int b = 0; b < 4; b++)
#pragma unroll
            for (int c = 0; c < 4; c++) { av_[a][b][c] = 0.f; ag_[a][b][c] = 0.f; }

    for (int blk = 0; blk < 8; blk++) {
        const int k0 = blk * 64;
        __syncthreads();
#pragma unroll
        for (int u = 0; u < 8; u++) {
            int id = tid + u * 256;
            int r = id >> 4, g = id & 15;
            float4 x = *(const float4*)(A  + (size_t)(m0 + r) * CK + k0 + g * 4);
            split_store(Ah, Al, r, g, x);
            float4 y = *(const float4*)(Wv + (size_t)(n0 + r) * CK + k0 + g * 4);
            split_store(Vh, Vl, r, g, y);
            float4 z = *(const float4*)(Wg + (size_t)(n0 + r) * CK + k0 + g * 4);
            split_store(Gh, Gl, r, g, z);
        }
        __syncthreads();

#pragma unroll
        for (int ks = 0; ks < 4; ks++) {
            uint32_t ah[4][4], al[4][4];
#pragma unroll
            for (int mt = 0; mt < 4; mt++) {
                const __nv_bfloat16* ar = Ah + (wm * 64 + mt * 16 + lq) * GP + ks * 16 + lk;
                ah[mt][0] = *(const uint32_t*)ar;
                ah[mt][1] = *(const uint32_t*)(ar + 8 * GP);
                ah[mt][2] = *(const uint32_t*)(ar + 8);
                ah[mt][3] = *(const uint32_t*)(ar + 8 * GP + 8);
                const __nv_bfloat16* al_ = Al + (wm * 64 + mt * 16 + lq) * GP + ks * 16 + lk;
                al[mt][0] = *(const uint32_t*)al_;
                al[mt][1] = *(const uint32_t*)(al_ + 8 * GP);
                al[mt][2] = *(const uint32_t*)(al_ + 8);
                al[mt][3] = *(const uint32_t*)(al_ + 8 * GP + 8);
            }
#pragma unroll
            for (int nt = 0; nt < 4; nt++) {
                const __nv_bfloat16* vh = Vh + (wn * 32 + nt * 8 + lq) * GP + ks * 16 + lk;
                uint32_t vh0 = *(const uint32_t*)vh;
                uint32_t vh1 = *(const uint32_t*)(vh + 8);
                const __nv_bfloat16* vl = Vl + (wn * 32 + nt * 8 + lq) * GP + ks * 16 + lk;
                uint32_t vl0 = *(const uint32_t*)vl;
                uint32_t vl1 = *(const uint32_t*)(vl + 8);
                const __nv_bfloat16* gh = Gh + (wn * 32 + nt * 8 + lq) * GP + ks * 16 + lk;
                uint32_t gh0 = *(const uint32_t*)gh;
                uint32_t gh1 = *(const uint32_t*)(gh + 8);
                const __nv_bfloat16* gl = Gl + (wn * 32 + nt * 8 + lq) * GP + ks * 16 + lk;
                uint32_t gl0 = *(const uint32_t*)gl;
                uint32_t gl1 = *(const uint32_t*)(gl + 8);
#pragma unroll
                for (int mt = 0; mt < 4; mt++) {
                    mma16816(av_[mt][nt], ah[mt][0], ah[mt][1], ah[mt][2], ah[mt][3], vh0, vh1);
                    mma16816(av_[mt][nt], ah[mt][0], ah[mt][1], ah[mt][2], ah[mt][3], vl0, vl1);
                    mma16816(av_[mt][nt], al[mt][0], al[mt][1], al[mt][2], al[mt][3], vh0, vh1);
                    mma16816(ag_[mt][nt], ah[mt][0], ah[mt][1], ah[mt][2], ah[mt][3], gh0, gh1);
                    mma16816(ag_[mt][nt], ah[mt][0], ah[mt][1], ah[mt][2], ah[mt][3], gl0, gl1);
                    mma16816(ag_[mt][nt], al[mt][0], al[mt][1], al[mt][2], al[mt][3], gh0, gh1);
                }
            }
        }
    }

#pragma unroll
    for (int mt = 0; mt < 4; mt++) {
#pragma unroll
        for (int nt = 0; nt < 4; nt++) {
            int row = m0 + wm * 64 + mt * 16 + lq;
            int col = n0 + wn * 32 + nt * 8 + lk;
            float bv0 = bv[col], bv1 = bv[col + 1];
            float bg0 = bg[col], bg1 = bg[col + 1];
            int h = col >> 6, d = col & 63;
#pragma unroll
            for (int half = 0; half < 2; half++) {
                int r = row + half * 8;
                int t = r >> 3, bi = r & 7;
                float vx0 = av_[mt][nt][half * 2 + 0] + bv0;
                float vx1 = av_[mt][nt][half * 2 + 1] + bv1;
                float gx0 = ag_[mt][nt][half * 2 + 0] + bg0;
                float gx1 = ag_[mt][nt][half * 2 + 1] + bg1;
                float2 v;
                v.x = vx0 * frcp_pos(1.0f + fexp(-gx0));
                v.y = vx1 * frcp_pos(1.0f + fexp(-gx1));
                float* dst = C + ((size_t)(bi * 8 + h) * 1024 + t) * 64 + d;
                if (accum) {
                    float2 old = *(float2*)dst;
                    v.x += old.x; v.y += old.y;
                }
                *(float2*)dst = v;
            }
        }
    }
}

// ---------------- per-row norms ----------------
__global__ void __launch_bounds__(256) norm_q_kernel()
{
    int row  = blockIdx.x * 8 + (threadIdx.x >> 5);
    int lane = threadIdx.x & 31;
    const float* p = g_qh + row * 64;
    float a = p[lane], b = p[lane + 32];
    float s = a * a + b * b;
#pragma unroll
    for (int o = 16; o; o >>= 1) s += __shfl_down_sync(0xffffffffu, s, o);
    if (lane == 0) g_ll[row] = s;
}

__global__ void __launch_bounds__(256) norm_k_kernel()
{
    int row  = blockIdx.x * 8 + (threadIdx.x >> 5);
    int lane = threadIdx.x & 31;
    const float* p1 = g_k1h + row * 64;
    const float* p2 = g_k2h + row * 64;
    float x0 = p1[lane], x1 = p1[lane + 32];
    float y0 = p2[lane], y1 = p2[lane + 32];
    float svv = x0 * x0 + x1 * x1;
    float saa = y0 * y0 + y1 * y1;
    float sva = x0 * y0 + x1 * y1;
#pragma unroll
    for (int o = 16; o; o >>= 1) {
        svv += __shfl_down_sync(0xffffffffu, svv, o);
        saa += __shfl_down_sync(0xffffffffu, saa, o);
        sva += __shfl_down_sync(0xffffffffu, sva, o);
    }
    if (lane == 0) { g_vv[row] = svv; g_aa[row] = saa; g_va[row] = sva; }
}

// =====================================================================
// flash_mma: fused gram-det flash attention on HMMA
//   grid (L/128, BH), 256 threads = 8 warps, warp owns 16 q-rows x all 64 s.
// =====================================================================
// smem (bf16 elems): K1h,K1l,K2h,K2l (64*GP each), VTh,VTl (64*GP each)
#define FK (64 * GP)
#define FL_SMEM_B (6 * FK * 2)

__global__ void __launch_bounds__(256, 1) flash_mma()
{
    extern __shared__ __nv_bfloat16 fs[];
    __nv_bfloat16* K1h = fs;
    __nv_bfloat16* K1l = fs + FK;
    __nv_bfloat16* K2h = fs + 2 * FK;
    __nv_bfloat16* K2l = fs + 3 * FK;
    __nv_bfloat16* VTh = fs + 4 * FK;
    __nv_bfloat16* VTl = fs + 5 * FK;

    const int tid = threadIdx.x;
    const int wid = tid >> 5, lane = tid & 31;
    const int lq = lane >> 2;
    const int lk = (lane & 3) * 2;
    const int bh = blockIdx.y;
    const int l0 = blockIdx.x * 128;
    const int bhS = bh * 1024;

    // --- Q fragments (hi/lo), held for the whole kernel ---
    uint32_t qh[4][4], ql[4][4];
    {
        const float* q0 = g_qh + (size_t)(bhS + l0 + wid * 16 + lq) * 64;
        const float* q8 = q0 + 8 * 64;
#pragma unroll
        for (int ks = 0; ks < 4; ks++) {
            float2 x00 = *(const float2*)(q0 + ks * 16 + lk);
            float2 x10 = *(const float2*)(q8 + ks * 16 + lk);
            float2 x01 = *(const float2*)(q0 + ks * 16 + lk + 8);
            float2 x11 = *(const float2*)(q8 + ks * 16 + lk + 8);
            qh[ks][0] = pk_hi(x00.x, x00.y); ql[ks][0] = pk_lo(x00.x, x00.y);
            qh[ks][1] = pk_hi(x10.x, x10.y); ql[ks][1] = pk_lo(x10.x, x10.y);
            qh[ks][2] = pk_hi(x01.x, x01.y); ql[ks][2] = pk_lo(x01.x, x01.y);
            qh[ks][3] = pk_hi(x11.x, x11.y); ql[ks][3] = pk_lo(x11.x, x11.y);
        }
    }
    const float ll0 = g_ll[bhS + l0 + wid * 16 + lq];
    const float ll1 = g_ll[bhS + l0 + wid * 16 + lq + 8];

    float m0 = -1e30f, m1 = -1e30f, ls0 = 0.f, ls1 = 0.f;
    float o[8][4];
#pragma unroll
    for (int dt = 0; dt < 8; dt++)
#pragma unroll
        for (int c = 0; c < 4; c++) o[dt][c] = 0.f;

    const int cgrp = tid >> 6;       // 0..3 (for V transpose)
    const int ccol = tid & 63;       // d column

    for (int s0 = 0; s0 < 1024; s0 += 64) {
        __syncthreads();
        // stage K1, K2 (hi/lo) — 64 rows x 64 cols, row-major pitch GP
        {
            const float* k1p = g_k1h + (size_t)(bhS + s0) * 64;
            const float* k2p = g_k2h + (size_t)(bhS + s0) * 64;
#pragma unroll
            for (int u = 0; u < 4; u++) {
                int id = tid + u * 256;
                int r = id >> 4, g = id & 15;
                float4 a = *(const float4*)(k1p + r * 64 + g * 4);
                split_store(K1h, K1l, r, g, a);
                float4 b = *(const float4*)(k2p + r * 64 + g * 4);
                split_store(K2h, K2l, r, g, b);
            }
            // V transposed: VT[d][s], column reads
            const float* vp = g_vh + (size_t)(bhS + s0) * 64;
#pragma unroll
            for (int u = 0; u < 4; u++) {
                int rb = cgrp * 16 + u * 4;
                float x0 = vp[(rb + 0) * 64 + ccol];
                float x1 = vp[(rb + 1) * 64 + ccol];
                float x2 = vp[(rb + 2) * 64 + ccol];
                float x3 = vp[(rb + 3) * 64 + ccol];
                *(uint2*)(VTh + ccol * GP + rb) = make_uint2(pk_hi(x0, x1), pk_hi(x2, x3));
                *(uint2*)(VTl + ccol * GP + rb) = make_uint2(pk_lo(x0, x1), pk_lo(x2, x3));
            }
        }
        __syncthreads();

        // QK1^T and QK2^T (3-term split)
        float lv[8][4], la[8][4];
#pragma unroll
        for (int nt = 0; nt < 8; nt++)
#pragma unroll
            for (int c = 0; c < 4; c++) { lv[nt][c] = 0.f; la[nt][c] = 0.f; }
#pragma unroll
        for (int nt = 0; nt < 8; nt++) {
#pragma unroll
            for (int ks = 0; ks < 4; ks++) {
                const __nv_bfloat16* b1h = K1h + (nt * 8 + lq) * GP + ks * 16 + lk;
                uint32_t h0 = *(const uint32_t*)b1h;
                uint32_t h1 = *(const uint32_t*)(b1h + 8);
                const __nv_bfloat16* b1l = K1l + (nt * 8 + lq) * GP + ks * 16 + lk;
                uint32_t l0_ = *(const uint32_t*)b1l;
                uint32_t l1_ = *(const uint32_t*)(b1l + 8);
                mma16816(lv[nt], qh[ks][0], qh[ks][1], qh[ks][2], qh[ks][3], h0, h1);
                mma16816(lv[nt], qh[ks][0], qh[ks][1], qh[ks][2], qh[ks][3], l0_, l1_);
                mma16816(lv[nt], ql[ks][0], ql[ks][1], ql[ks][2], ql[ks][3], h0, h1);
                const __nv_bfloat16* b2h = K2h + (nt * 8 + lq) * GP + ks * 16 + lk;
                uint32_t g0 = *(const uint32_t*)b2h;
                uint32_t g1 = *(const uint32_t*)(b2h + 8);
                const __nv_bfloat16* b2l = K2l + (nt * 8 + lq) * GP + ks * 16 + lk;
                uint32_t e0 = *(const uint32_t*)b2l;
                uint32_t e1 = *(const uint32_t*)(b2l + 8);
                mma16816(la[nt], qh[ks][0], qh[ks][1], qh[ks][2], qh[ks][3], g0, g1);
                mma16816(la[nt], qh[ks][0], qh[ks][1], qh[ks][2], qh[ks][3], e0, e1);
                mma16816(la[nt], ql[ks][0], ql[ks][1], ql[ks][2], ql[ks][3], g0, g1);
            }
        }

        // gram-det scores (in-place into lv) + row max
        float mx0 = -1e30f, mx1 = -1e30f;
#pragma unroll
        for (int nt = 0; nt < 8; nt++) {
            float2 vv2 = *(const float2*)(g_vv + bhS + s0 + nt * 8 + lk);
            float2 aa2 = *(const float2*)(g_aa + bhS + s0 + nt * 8 + lk);
            float2 va2 = *(const float2*)(g_va + bhS + s0 + nt * 8 + lk);
            float g2x = vv2.x * aa2.x - va2.x * va2.x;
            float g2y = vv2.y * aa2.y - va2.y * va2.y;
            {
                float LV = lv[nt][0], LA = la[nt][0];
                float det = ll0 * g2x - LV * (LV * aa2.x - LA * va2.x) + LA * (LV * va2.x - LA * vv2.x);
                float sc = -fsqrt_pos(fmaxf(det, 1e-8f));
                lv[nt][0] = sc; mx0 = fmaxf(mx0, sc);
            }
            {
                float LV = lv[nt][1], LA = la[nt][1];
                float det = ll0 * g2y - LV * (LV * aa2.y - LA * va2.y) + LA * (LV * va2.y - LA * vv2.y);
                float sc = -fsqrt_pos(fmaxf(det, 1e-8f));
                lv[nt][1] = sc; mx0 = fmaxf(mx0, sc);
            }
            {
                float LV = lv[nt][2], LA = la[nt][2];
                float det = ll1 * g2x - LV * (LV * aa2.x - LA * va2.x) + LA * (LV * va2.x - LA * vv2.x);
                float sc = -fsqrt_pos(fmaxf(det, 1e-8f));
                lv[nt][2] = sc; mx1 = fmaxf(mx1, sc);
            }
            {
                float LV = lv[nt][3], LA = la[nt][3];
                float det = ll1 * g2y - LV * (LV * aa2.y - LA * va2.y) + LA * (LV * va2.y - LA * vv2.y);
                float sc = -fsqrt_pos(fmaxf(det, 1e-8f));
                lv[nt][3] = sc; mx1 = fmaxf(mx1, sc);
            }
        }
        // quad max reduce
        mx0 = fmaxf(mx0, __shfl_xor_sync(0xffffffffu, mx0, 1));
        mx0 = fmaxf(mx0, __shfl_xor_sync(0xffffffffu, mx0, 2));
        mx1 = fmaxf(mx1, __shfl_xor_sync(0xffffffffu, mx1, 1));
        mx1 = fmaxf(mx1, __shfl_xor_sync(0xffffffffu, mx1, 2));

        float mn0 = fmaxf(m0, mx0), mn1 = fmaxf(m1, mx1);
        float alpha0 = fexp(m0 - mn0), alpha1 = fexp(m1 - mn1);
        m0 = mn0; m1 = mn1;

        // p = exp(sc - mn), row sums
        float rs0 = 0.f, rs1 = 0.f;
#pragma unroll
        for (int nt = 0; nt < 8; nt++) {
            float p0 = fexp(lv[nt][0] - mn0);
            float p1 = fexp(lv[nt][1] - mn0);
            float p2 = fexp(lv[nt][2] - mn1);
            float p3 = fexp(lv[nt][3] - mn1);
            lv[nt][0] = p0; lv[nt][1] = p1; lv[nt][2] = p2; lv[nt][3] = p3;
            rs0 += p0 + p1; rs1 += p2 + p3;
        }
        rs0 += __shfl_xor_sync(0xffffffffu, rs0, 1);
        rs0 += __shfl_xor_sync(0xffffffffu, rs0, 2);
        rs1 += __shfl_xor_sync(0xffffffffu, rs1, 1);
        rs1 += __shfl_xor_sync(0xffffffffu, rs1, 2);
        ls0 = ls0 * alpha0 + rs0;
        ls1 = ls1 * alpha1 + rs1;

        // rescale O
#pragma unroll
        for (int dt = 0; dt < 8; dt++) {
            o[dt][0] *= alpha0; o[dt][1] *= alpha0;
            o[dt][2] *= alpha1; o[dt][3] *= alpha1;
        }

        // P fragments (hi/lo); C-frag of QK == A-frag of PV
        uint32_t ph[4][4], pl[4][4];
#pragma unroll
        for (int ks = 0; ks < 4; ks++) {
            ph[ks][0] = pk_hi(lv[2 * ks][0], lv[2 * ks][1]);
            pl[ks][0] = pk_lo(lv[2 * ks][0], lv[2 * ks][1]);
            ph[ks][1] = pk_hi(lv[2 * ks][2], lv[2 * ks][3]);
            pl[ks][1] = pk_lo(lv[2 * ks][2], lv[2 * ks][3]);
            ph[ks][2] = pk_hi(lv[2 * ks + 1][0], lv[2 * ks + 1][1]);
            pl[ks][2] = pk_lo(lv[2 * ks + 1][0], lv[2 * ks + 1][1]);
            ph[ks][3] = pk_hi(lv[2 * ks + 1][2], lv[2 * ks + 1][3]);
            pl[ks][3] = pk_lo(lv[2 * ks + 1][2], lv[2 * ks + 1][3]);
        }

        // PV (3-term split)
#pragma unroll
        for (int dt = 0; dt < 8; dt++) {
#pragma unroll
            for (int ks = 0; ks < 4; ks++) {
                const __nv_bfloat16* vh = VTh + (dt * 8 + lq) * GP + ks * 16 + lk;
                uint32_t vh0 = *(const uint32_t*)vh;
                uint32_t vh1 = *(const uint32_t*)(vh + 8);
                const __nv_bfloat16* vl = VTl + (dt * 8 + lq) * GP + ks * 16 + lk;
                uint32_t vl0 = *(const uint32_t*)vl;
                uint32_t vl1 = *(const uint32_t*)(vl + 8);
                mma16816(o[dt], ph[ks][0], ph[ks][1], ph[ks][2], ph[ks][3], vh0, vh1);
                mma16816(o[dt], ph[ks][0], ph[ks][1], ph[ks][2], ph[ks][3], vl0, vl1);
                mma16816(o[dt], pl[ks][0], pl[ks][1], pl[ks][2], pl[ks][3], vh0, vh1);
            }
        }
    }

    // epilogue
    const float inv0 = frcp_pos(ls0);
    const float inv1 = frcp_pos(ls1);
    const int bi = bh >> 3, h = bh & 7;
    const int r0 = l0 + wid * 16 + lq;
#pragma unroll
    for (int dt = 0; dt < 8; dt++) {
        int d = dt * 8 + lk;
        float2 v0, v1;
        v0.x = o[dt][0] * inv0; v0.y = o[dt][1] * inv0;
        v1.x = o[dt][2] * inv1; v1.y = o[dt][3] * inv1;
        *(float2*)(g_ao + (size_t)(r0 * 8 + bi) * 512 + h * 64 + d) = v0;
        *(float2*)(g_ao + (size_t)((r0 + 8) * 8 + bi) * 512 + h * 64 + d) = v1;
    }
}

// ---------------- launch ----------------
extern "C" void kernel_launch(void* const* d_in, const int* in_sizes, int n_in,
                              void* d_out, int out_size) {
    const float* query = (const float*)d_in[0];
    const float* mod1  = (const float*)d_in[1];
    const float* mod2  = (const float*)d_in[2];
    const float* Wq  = (const float*)d_in[3];  const float* bq  = (const float*)d_in[4];
    const float* Wk1 = (const float*)d_in[5];  const float* bk1 = (const float*)d_in[6];
    const float* Wk2 = (const float*)d_in[7];  const float* bk2 = (const float*)d_in[8];
    const float* Wv1 = (const float*)d_in[9];  const float* bv1 = (const float*)d_in[10];
    const float* Wv2 = (const float*)d_in[11]; const float* bv2 = (const float*)d_in[12];
    const float* Wg1 = (const float*)d_in[13]; const float* bg1 = (const float*)d_in[14];
    const float* Wg2 = (const float*)d_in[15]; const float* bg2 = (const float*)d_in[16];
    const float* Wo  = (const float*)d_in[17]; const float* bo  = (const float*)d_in[18];
    float* out = (float*)d_out;

    float *p_qh, *p_k1h, *p_k2h, *p_vh, *p_ao;
    cudaGetSymbolAddress((void**)&p_qh,  g_qh);
    cudaGetSymbolAddress((void**)&p_k1h, g_k1h);
    cudaGetSymbolAddress((void**)&p_k2h, g_k2h);
    cudaGetSymbolAddress((void**)&p_vh,  g_vh);
    cudaGetSymbolAddress((void**)&p_ao,  g_ao);

    cudaFuncSetAttribute(proj_mma<0>, cudaFuncAttributeMaxDynamicSharedMemorySize, PJ_SMEM_B);
    cudaFuncSetAttribute(proj_mma<1>, cudaFuncAttributeMaxDynamicSharedMemorySize, PJ_SMEM_B);
    cudaFuncSetAttribute(proj_mma<2>, cudaFuncAttributeMaxDynamicSharedMemorySize, PJ_SMEM_B);
    cudaFuncSetAttribute(projvg_mma,  cudaFuncAttributeMaxDynamicSharedMemorySize, VG_SMEM_B);
    cudaFuncSetAttribute(flash_mma,   cudaFuncAttributeMaxDynamicSharedMemorySize, FL_SMEM_B);

    dim3 pg(64, 4), pb(256);
    proj_mma<0><<<pg, pb, PJ_SMEM_B>>>(query, Wq,  bq,  p_qh);
    proj_mma<1><<<pg, pb, PJ_SMEM_B>>>(mod1,  Wk1, bk1, p_k1h);
    proj_mma<1><<<pg, pb, PJ_SMEM_B>>>(mod2,  Wk2, bk2, p_k2h);
    projvg_mma<<<pg, pb, VG_SMEM_B>>>(mod1, Wv1, bv1, Wg1, bg1, p_vh, 0);
    projvg_mma<<<pg, pb, VG_SMEM_B>>>(mod2, Wv2, bv2, Wg2, bg2, p_vh, 1);
    norm_q_kernel<<<8192, 256>>>();
    norm_k_kernel<<<8192, 256>>>();
    flash_mma<<<dim3(8, 64), 256, FL_SMEM_B>>>();
    proj_mma<2><<<pg, pb, PJ_SMEM_B>>>(p_ao, Wo, bo, out);
}

// round 7
// speedup vs baseline: 2.1514x; 1.0340x over previous
#include <cuda_runtime.h>
#include <cuda_bf16.h>
#include <cstdint>

#define CL   1024
#define CS   1024
#define CB   8
#define CE   512
#define CH   8
#define CDH  64
#define CBH  64
#define CM   8192
#define CK   512

// ---------------- device scratch ----------------
__device__ __align__(128) float g_qh [CBH * CL * CDH];
__device__ __align__(128) float g_k1h[CBH * CS * CDH];
__device__ __align__(128) float g_k2h[CBH * CS * CDH];
__device__ __align__(128) float g_vh [CBH * CS * CDH];
__device__ __align__(128) float g_ao [CM * CE];
__device__ __align__(128) float g_ll [CBH * CL];
__device__ __align__(128) float g_vv [CBH * CS];
__device__ __align__(128) float g_aa [CBH * CS];
__device__ __align__(128) float g_va [CBH * CS];
// bf16 hi/lo operand caches for flash
__device__ __align__(128) __nv_bfloat16 g_k1hb[CBH * CS * CDH];
__device__ __align__(128) __nv_bfloat16 g_k1lb[CBH * CS * CDH];
__device__ __align__(128) __nv_bfloat16 g_k2hb[CBH * CS * CDH];
__device__ __align__(128) __nv_bfloat16 g_k2lb[CBH * CS * CDH];
__device__ __align__(128) __nv_bfloat16 g_vthb[CBH * CDH * CS];   // [bh][d][s]
__device__ __align__(128) __nv_bfloat16 g_vtlb[CBH * CDH * CS];

// ---------------- MUFU-free math ----------------
__device__ __forceinline__ float fexp(float x) {
    float t = x * 1.4426950408889634f;
    t = fminf(fmaxf(t, -126.0f), 126.0f);
    int i = __float2int_rn(t);
    float u = (t - (float)i) * 0.6931471805599453f;
    float p = 1.3888889e-3f;
    p = fmaf(p, u, 8.3333333e-3f);
    p = fmaf(p, u, 4.1666667e-2f);
    p = fmaf(p, u, 1.6666667e-1f);
    p = fmaf(p, u, 0.5f);
    p = fmaf(p, u, 1.0f);
    p = fmaf(p, u, 1.0f);
    return p * __int_as_float((i + 127) << 23);
}
__device__ __forceinline__ float fsqrt_pos(float x) {
    float y = __int_as_float(0x5f3759df - (__float_as_int(x) >> 1));
    y = y * fmaf(-0.5f * x, y * y, 1.5f);
    y = y * fmaf(-0.5f * x, y * y, 1.5f);
    y = y * fmaf(-0.5f * x, y * y, 1.5f);
    return x * y;
}
__device__ __forceinline__ float frcp_pos(float x) {
    float y = __int_as_float(0x7EF127EAu - __float_as_int(x));
    y = y * (2.0f - x * y);
    y = y * (2.0f - x * y);
    y = y * (2.0f - x * y);
    return y;
}

// ---------------- mma.sync bf16 helper ----------------
__device__ __forceinline__ void mma16816(float* c,
    uint32_t a0, uint32_t a1, uint32_t a2, uint32_t a3,
    uint32_t b0, uint32_t b1)
{
    asm volatile(
        "mma.sync.aligned.m16n8k16.row.col.f32.bf16.bf16.f32 "
        "{%0,%1,%2,%3},{%4,%5,%6,%7},{%8,%9},{%0,%1,%2,%3};"
        : "+f"(c[0]), "+f"(c[1]), "+f"(c[2]), "+f"(c[3])
        : "r"(a0), "r"(a1), "r"(a2), "r"(a3), "r"(b0), "r"(b1));
}

#define GP 72   // smem row pitch in bf16 elements
__device__ __forceinline__ uint32_t pkbf(__nv_bfloat16 a, __nv_bfloat16 b) {
    __nv_bfloat162 t(a, b);
    return *reinterpret_cast<uint32_t*>(&t);
}
__device__ __forceinline__ uint32_t pk_hi(float x, float y) {
    return pkbf(__float2bfloat16(x), __float2bfloat16(y));
}
__device__ __forceinline__ uint32_t pk_lo(float x, float y) {
    __nv_bfloat16 hx = __float2bfloat16(x), hy = __float2bfloat16(y);
    return pkbf(__float2bfloat16(x - __bfloat162float(hx)),
                __float2bfloat16(y - __bfloat162float(hy)));
}
__device__ __forceinline__ void split_store(__nv_bfloat16* hi, __nv_bfloat16* lo,
                                            int r, int g, float4 x)
{
    int off = r * GP + g * 4;
    *(uint2*)(hi + off) = make_uint2(pk_hi(x.x, x.y), pk_hi(x.z, x.w));
    *(uint2*)(lo + off) = make_uint2(pk_lo(x.x, x.y), pk_lo(x.z, x.w));
}
__device__ __forceinline__ uint32_t smem_u32(const void* p) {
    uint32_t a;
    asm("{ .reg .u64 t; cvta.to.shared.u64 t, %1; cvt.u32.u64 %0, t; }" : "=r"(a) : "l"(p));
    return a;
}
__device__ __forceinline__ void cpa16(uint32_t dst, const void* src) {
    asm volatile("cp.async.cg.shared.global [%0], [%1], 16;" :: "r"(dst), "l"(src));
}

#define TSZ (128 * GP)

// =====================================================================
// proj3_mma: the 3 input projections in one launch (grid.z picks which)
//   z=0: q = (query@Wq^T+bq)*0.125 -> g_qh
//   z=1: k1 -> g_k1h  (+ bf16 hi/lo dual store)
//   z=2: k2 -> g_k2h  (+ bf16 hi/lo dual store)
// =====================================================================
#define PJ_SMEM_B (4 * TSZ * 2)

__global__ void __launch_bounds__(256)
proj3_mma(const float* __restrict__ query, const float* __restrict__ mod1,
          const float* __restrict__ mod2,
          const float* __restrict__ Wq,  const float* __restrict__ bq,
          const float* __restrict__ Wk1, const float* __restrict__ bk1,
          const float* __restrict__ Wk2, const float* __restrict__ bk2)
{
    extern __shared__ __nv_bfloat16 sb16[];
    __nv_bfloat16* Ah = sb16;
    __nv_bfloat16* Al = sb16 + TSZ;
    __nv_bfloat16* Wh = sb16 + 2 * TSZ;
    __nv_bfloat16* Wl = sb16 + 3 * TSZ;

    const int z = blockIdx.z;
    const float* A    = (z == 0) ? query : (z == 1) ? mod1 : mod2;
    const float* W    = (z == 0) ? Wq    : (z == 1) ? Wk1  : Wk2;
    const float* bias = (z == 0) ? bq    : (z == 1) ? bk1  : bk2;
    float* C          = (z == 0) ? g_qh  : (z == 1) ? g_k1h : g_k2h;
    __nv_bfloat16* CH_ = (z == 1) ? g_k1hb : g_k2hb;
    __nv_bfloat16* CL_ = (z == 1) ? g_k1lb : g_k2lb;

    const int tid = threadIdx.x;
    const int wid = tid >> 5, lane = tid & 31;
    const int wm = wid >> 2, wn = wid & 3;
    const int m0 = blockIdx.x * 128;
    const int n0 = blockIdx.y * 128;
    const int lq = lane >> 2;
    const int lk = (lane & 3) * 2;

    float acc[4][4][4];
#pragma unroll
    for (int a = 0; a < 4; a++)
#pragma unroll
        for (int b = 0; b < 4; b++)
#pragma unroll
            for (int c = 0; c < 4; c++) acc[a][b][c] = 0.f;

    for (int blk = 0; blk < 8; blk++) {
        const int k0 = blk * 64;
        __syncthreads();
#pragma unroll
        for (int u = 0; u < 8; u++) {
            int id = tid + u * 256;
            int r = id >> 4, g = id & 15;
            float4 x = *(const float4*)(A + (size_t)(m0 + r) * CK + k0 + g * 4);
            split_store(Ah, Al, r, g, x);
            float4 y = *(const float4*)(W + (size_t)(n0 + r) * CK + k0 + g * 4);
            split_store(Wh, Wl, r, g, y);
        }
        __syncthreads();

#pragma unroll
        for (int ks = 0; ks < 4; ks++) {
            uint32_t ah[4][4], al[4][4];
#pragma unroll
            for (int mt = 0; mt < 4; mt++) {
                const __nv_bfloat16* ar = Ah + (wm * 64 + mt * 16 + lq) * GP + ks * 16 + lk;
                ah[mt][0] = *(const uint32_t*)ar;
                ah[mt][1] = *(const uint32_t*)(ar + 8 * GP);
                ah[mt][2] = *(const uint32_t*)(ar + 8);
                ah[mt][3] = *(const uint32_t*)(ar + 8 * GP + 8);
                const __nv_bfloat16* al_ = Al + (wm * 64 + mt * 16 + lq) * GP + ks * 16 + lk;
                al[mt][0] = *(const uint32_t*)al_;
                al[mt][1] = *(const uint32_t*)(al_ + 8 * GP);
                al[mt][2] = *(const uint32_t*)(al_ + 8);
                al[mt][3] = *(const uint32_t*)(al_ + 8 * GP + 8);
            }
#pragma unroll
            for (int nt = 0; nt < 4; nt++) {
                const __nv_bfloat16* bh = Wh + (wn * 32 + nt * 8 + lq) * GP + ks * 16 + lk;
                uint32_t bh0 = *(const uint32_t*)bh;
                uint32_t bh1 = *(const uint32_t*)(bh + 8);
                const __nv_bfloat16* bl = Wl + (wn * 32 + nt * 8 + lq) * GP + ks * 16 + lk;
                uint32_t bl0 = *(const uint32_t*)bl;
                uint32_t bl1 = *(const uint32_t*)(bl + 8);
#pragma unroll
                for (int mt = 0; mt < 4; mt++) {
                    mma16816(acc[mt][nt], ah[mt][0], ah[mt][1], ah[mt][2], ah[mt][3], bh0, bh1);
                    mma16816(acc[mt][nt], ah[mt][0], ah[mt][1], ah[mt][2], ah[mt][3], bl0, bl1);
                    mma16816(acc[mt][nt], al[mt][0], al[mt][1], al[mt][2], al[mt][3], bh0, bh1);
                }
            }
        }
    }

    const float scale = (z == 0) ? 0.125f : 1.0f;
#pragma unroll
    for (int mt = 0; mt < 4; mt++) {
#pragma unroll
        for (int nt = 0; nt < 4; nt++) {
            int row = m0 + wm * 64 + mt * 16 + lq;
            int col = n0 + wn * 32 + nt * 8 + lk;
            float b0 = bias[col], b1 = bias[col + 1];
            int h = col >> 6, d = col & 63;
#pragma unroll
            for (int half = 0; half < 2; half++) {
                int r = row + half * 8;
                int t = r >> 3, bi = r & 7;
                float2 v;
                v.x = (acc[mt][nt][half * 2 + 0] + b0) * scale;
                v.y = (acc[mt][nt][half * 2 + 1] + b1) * scale;
                size_t off = ((size_t)(bi * 8 + h) * 1024 + t) * 64 + d;
                *(float2*)(C + off) = v;
                if (z >= 1) {
                    *(uint32_t*)(CH_ + off) = pk_hi(v.x, v.y);
                    *(uint32_t*)(CL_ + off) = pk_lo(v.x, v.y);
                }
            }
        }
    }
}

// =====================================================================
// proj_out: out = g_ao @ Wo^T + bo (row-major), same tile scheme
// =====================================================================
__global__ void __launch_bounds__(256)
proj_out(const float* __restrict__ A, const float* __restrict__ W,
         const float* __restrict__ bias, float* __restrict__ C)
{
    extern __shared__ __nv_bfloat16 sb16[];
    __nv_bfloat16* Ah = sb16;
    __nv_bfloat16* Al = sb16 + TSZ;
    __nv_bfloat16* Wh = sb16 + 2 * TSZ;
    __nv_bfloat16* Wl = sb16 + 3 * TSZ;

    const int tid = threadIdx.x;
    const int wid = tid >> 5, lane = tid & 31;
    const int wm = wid >> 2, wn = wid & 3;
    const int m0 = blockIdx.x * 128;
    const int n0 = blockIdx.y * 128;
    const int lq = lane >> 2;
    const int lk = (lane & 3) * 2;

    float acc[4][4][4];
#pragma unroll
    for (int a = 0; a < 4; a++)
#pragma unroll
        for (int b = 0; b < 4; b++)
#pragma unroll
            for (int c = 0; c < 4; c++) acc[a][b][c] = 0.f;

    for (int blk = 0; blk < 8; blk++) {
        const int k0 = blk * 64;
        __syncthreads();
#pragma unroll
        for (int u = 0; u < 8; u++) {
            int id = tid + u * 256;
            int r = id >> 4, g = id & 15;
            float4 x = *(const float4*)(A + (size_t)(m0 + r) * CK + k0 + g * 4);
            split_store(Ah, Al, r, g, x);
            float4 y = *(const float4*)(W + (size_t)(n0 + r) * CK + k0 + g * 4);
            split_store(Wh, Wl, r, g, y);
        }
        __syncthreads();

#pragma unroll
        for (int ks = 0; ks < 4; ks++) {
            uint32_t ah[4][4], al[4][4];
#pragma unroll
            for (int mt = 0; mt < 4; mt++) {
                const __nv_bfloat16* ar = Ah + (wm * 64 + mt * 16 + lq) * GP + ks * 16 + lk;
                ah[mt][0] = *(const uint32_t*)ar;
                ah[mt][1] = *(const uint32_t*)(ar + 8 * GP);
                ah[mt][2] = *(const uint32_t*)(ar + 8);
                ah[mt][3] = *(const uint32_t*)(ar + 8 * GP + 8);
                const __nv_bfloat16* al_ = Al + (wm * 64 + mt * 16 + lq) * GP + ks * 16 + lk;
                al[mt][0] = *(const uint32_t*)al_;
                al[mt][1] = *(const uint32_t*)(al_ + 8 * GP);
                al[mt][2] = *(const uint32_t*)(al_ + 8);
                al[mt][3] = *(const uint32_t*)(al_ + 8 * GP + 8);
            }
#pragma unroll
            for (int nt = 0; nt < 4; nt++) {
                const __nv_bfloat16* bh = Wh + (wn * 32 + nt * 8 + lq) * GP + ks * 16 + lk;
                uint32_t bh0 = *(const uint32_t*)bh;
                uint32_t bh1 = *(const uint32_t*)(bh + 8);
                const __nv_bfloat16* bl = Wl + (wn * 32 + nt * 8 + lq) * GP + ks * 16 + lk;
                uint32_t bl0 = *(const uint32_t*)bl;
                uint32_t bl1 = *(const uint32_t*)(bl + 8);
#pragma unroll
                for (int mt = 0; mt < 4; mt++) {
                    mma16816(acc[mt][nt], ah[mt][0], ah[mt][1], ah[mt][2], ah[mt][3], bh0, bh1);
                    mma16816(acc[mt][nt], ah[mt][0], ah[mt][1], ah[mt][2], ah[mt][3], bl0, bl1);
                    mma16816(acc[mt][nt], al[mt][0], al[mt][1], al[mt][2], al[mt][3], bh0, bh1);
                }
            }
        }
    }

#pragma unroll
    for (int mt = 0; mt < 4; mt++) {
#pragma unroll
        for (int nt = 0; nt < 4; nt++) {
            int row = m0 + wm * 64 + mt * 16 + lq;
            int col = n0 + wn * 32 + nt * 8 + lk;
            float b0 = bias[col], b1 = bias[col + 1];
#pragma unroll
            for (int half = 0; half < 2; half++) {
                int r = row + half * 8;
                float2 v;
                v.x = acc[mt][nt][half * 2 + 0] + b0;
                v.y = acc[mt][nt][half * 2 + 1] + b1;
                *(float2*)(C + (size_t)r * CE + col) = v;
            }
        }
    }
}

// =====================================================================
// projvg_mma (unchanged from R5)
// =====================================================================
#define VG_SMEM_B (6 * TSZ * 2)

__global__ void __launch_bounds__(256)
projvg_mma(const float* __restrict__ A,
           const float* __restrict__ Wv, const float* __restrict__ bv,
           const float* __restrict__ Wg, const float* __restrict__ bg,
           float* __restrict__ C, int accum)
{
    extern __shared__ __nv_bfloat16 sb16[];
    __nv_bfloat16* Ah = sb16;
    __nv_bfloat16* Al = sb16 + TSZ;
    __nv_bfloat16* Vh = sb16 + 2 * TSZ;
    __nv_bfloat16* Vl = sb16 + 3 * TSZ;
    __nv_bfloat16* Gh = sb16 + 4 * TSZ;
    __nv_bfloat16* Gl = sb16 + 5 * TSZ;

    const int tid = threadIdx.x;
    const int wid = tid >> 5, lane = tid & 31;
    const int wm = wid >> 2, wn = wid & 3;
    const int m0 = blockIdx.x * 128;
    const int n0 = blockIdx.y * 128;
    const int lq = lane >> 2;
    const int lk = (lane & 3) * 2;

    float av_[4][4][4], ag_[4][4][4];
#pragma unroll
    for (int a = 0; a < 4; a++)
#pragma unroll
        for (int b = 0; b < 4; b++)
#pragma unroll
            for (int c = 0; c < 4; c++) { av_[a][b][c] = 0.f; ag_[a][b][c] = 0.f; }

    for (int blk = 0; blk < 8; blk++) {
        const int k0 = blk * 64;
        __syncthreads();
#pragma unroll
        for (int u = 0; u < 8; u++) {
            int id = tid + u * 256;
            int r = id >> 4, g = id & 15;
            float4 x = *(const float4*)(A  + (size_t)(m0 + r) * CK + k0 + g * 4);
            split_store(Ah, Al, r, g, x);
            float4 y = *(const float4*)(Wv + (size_t)(n0 + r) * CK + k0 + g * 4);
            split_store(Vh, Vl, r, g, y);
            float4 z = *(const float4*)(Wg + (size_t)(n0 + r) * CK + k0 + g * 4);
            split_store(Gh, Gl, r, g, z);
        }
        __syncthreads();

#pragma unroll
        for (int ks = 0; ks < 4; ks++) {
            uint32_t ah[4][4], al[4][4];
#pragma unroll
            for (int mt = 0; mt < 4; mt++) {
                const __nv_bfloat16* ar = Ah + (wm * 64 + mt * 16 + lq) * GP + ks * 16 + lk;
                ah[mt][0] = *(const uint32_t*)ar;
                ah[mt][1] = *(const uint32_t*)(ar + 8 * GP);
                ah[mt][2] = *(const uint32_t*)(ar + 8);
                ah[mt][3] = *(const uint32_t*)(ar + 8 * GP + 8);
                const __nv_bfloat16* al_ = Al + (wm * 64 + mt * 16 + lq) * GP + ks * 16 + lk;
                al[mt][0] = *(const uint32_t*)al_;
                al[mt][1] = *(const uint32_t*)(al_ + 8 * GP);
                al[mt][2] = *(const uint32_t*)(al_ + 8);
                al[mt][3] = *(const uint32_t*)(al_ + 8 * GP + 8);
            }
#pragma unroll
            for (int nt = 0; nt < 4; nt++) {
                const __nv_bfloat16* vh = Vh + (wn * 32 + nt * 8 + lq) * GP + ks * 16 + lk;
                uint32_t vh0 = *(const uint32_t*)vh;
                uint32_t vh1 = *(const uint32_t*)(vh + 8);
                const __nv_bfloat16* vl = Vl + (wn * 32 + nt * 8 + lq) * GP + ks * 16 + lk;
                uint32_t vl0 = *(const uint32_t*)vl;
                uint32_t vl1 = *(const uint32_t*)(vl + 8);
                const __nv_bfloat16* gh = Gh + (wn * 32 + nt * 8 + lq) * GP + ks * 16 + lk;
                uint32_t gh0 = *(const uint32_t*)gh;
                uint32_t gh1 = *(const uint32_t*)(gh + 8);
                const __nv_bfloat16* gl = Gl + (wn * 32 + nt * 8 + lq) * GP + ks * 16 + lk;
                uint32_t gl0 = *(const uint32_t*)gl;
                uint32_t gl1 = *(const uint32_t*)(gl + 8);
#pragma unroll
                for (int mt = 0; mt < 4; mt++) {
                    mma16816(av_[mt][nt], ah[mt][0], ah[mt][1], ah[mt][2], ah[mt][3], vh0, vh1);
                    mma16816(av_[mt][nt], ah[mt][0], ah[mt][1], ah[mt][2], ah[mt][3], vl0, vl1);
                    mma16816(av_[mt][nt], al[mt][0], al[mt][1], al[mt][2], al[mt][3], vh0, vh1);
                    mma16816(ag_[mt][nt], ah[mt][0], ah[mt][1], ah[mt][2], ah[mt][3], gh0, gh1);
                    mma16816(ag_[mt][nt], ah[mt][0], ah[mt][1], ah[mt][2], ah[mt][3], gl0, gl1);
                    mma16816(ag_[mt][nt], al[mt][0], al[mt][1], al[mt][2], al[mt][3], gh0, gh1);
                }
            }
        }
    }

#pragma unroll
    for (int mt = 0; mt < 4; mt++) {
#pragma unroll
        for (int nt = 0; nt < 4; nt++) {
            int row = m0 + wm * 64 + mt * 16 + lq;
            int col = n0 + wn * 32 + nt * 8 + lk;
            float bv0 = bv[col], bv1 = bv[col + 1];
            float bg0 = bg[col], bg1 = bg[col + 1];
            int h = col >> 6, d = col & 63;
#pragma unroll
            for (int half = 0; half < 2; half++) {
                int r = row + half * 8;
                int t = r >> 3, bi = r & 7;
                float vx0 = av_[mt][nt][half * 2 + 0] + bv0;
                float vx1 = av_[mt][nt][half * 2 + 1] + bv1;
                float gx0 = ag_[mt][nt][half * 2 + 0] + bg0;
                float gx1 = ag_[mt][nt][half * 2 + 1] + bg1;
                float2 v;
                v.x = vx0 * frcp_pos(1.0f + fexp(-gx0));
                v.y = vx1 * frcp_pos(1.0f + fexp(-gx1));
                float* dst = C + ((size_t)(bi * 8 + h) * 1024 + t) * 64 + d;
                if (accum) {
                    float2 old = *(float2*)dst;
                    v.x += old.x; v.y += old.y;
                }
                *(float2*)dst = v;
            }
        }
    }
}

// ---------------- per-row norms ----------------
__global__ void __launch_bounds__(256) norm_q_kernel()
{
    int row  = blockIdx.x * 8 + (threadIdx.x >> 5);
    int lane = threadIdx.x & 31;
    const float* p = g_qh + row * 64;
    float a = p[lane], b = p[lane + 32];
    float s = a * a + b * b;
#pragma unroll
    for (int o = 16; o; o >>= 1) s += __shfl_down_sync(0xffffffffu, s, o);
    if (lane == 0) g_ll[row] = s;
}

__global__ void __launch_bounds__(256) norm_k_kernel()
{
    int row  = blockIdx.x * 8 + (threadIdx.x >> 5);
    int lane = threadIdx.x & 31;
    const float* p1 = g_k1h + row * 64;
    const float* p2 = g_k2h + row * 64;
    float x0 = p1[lane], x1 = p1[lane + 32];
    float y0 = p2[lane], y1 = p2[lane + 32];
    float svv = x0 * x0 + x1 * x1;
    float saa = y0 * y0 + y1 * y1;
    float sva = x0 * y0 + x1 * y1;
#pragma unroll
    for (int o = 16; o; o >>= 1) {
        svv += __shfl_down_sync(0xffffffffu, svv, o);
        saa += __shfl_down_sync(0xffffffffu, saa, o);
        sva += __shfl_down_sync(0xffffffffu, sva, o);
    }
    if (lane == 0) { g_vv[row] = svv; g_aa[row] = saa; g_va[row] = sva; }
}

// ---------------- V transpose -> bf16 hi/lo VT [bh][d][s] ----------------
__global__ void __launch_bounds__(256) prep_vt()
{
    __shared__ float tile[64 * 65];
    const int bh = blockIdx.y;
    const int s0 = blockIdx.x * 64;
    const int tid = threadIdx.x;
    const float* vp = g_vh + (size_t)(bh * 1024 + s0) * 64;
#pragma unroll
    for (int u = 0; u < 4; u++) {
        int id = tid + u * 256;
        int r = id >> 4, c4 = (id & 15) * 4;
        float4 x = *(const float4*)(vp + r * 64 + c4);
        tile[r * 65 + c4 + 0] = x.x;
        tile[r * 65 + c4 + 1] = x.y;
        tile[r * 65 + c4 + 2] = x.z;
        tile[r * 65 + c4 + 3] = x.w;
    }
    __syncthreads();
#pragma unroll
    for (int u = 0; u < 8; u++) {
        int id = tid + u * 256;           // 2048 (d, s-pair) items
        int d = id >> 5, sp = id & 31;
        float x0 = tile[(2 * sp) * 65 + d];
        float x1 = tile[(2 * sp + 1) * 65 + d];
        size_t off = ((size_t)(bh * 64 + d) * 1024 + s0 + 2 * sp);
        *(uint32_t*)(g_vthb + off) = pk_hi(x0, x1);
        *(uint32_t*)(g_vtlb + off) = pk_lo(x0, x1);
    }
}

// =====================================================================
// flash_mma v2: bf16 operands staged via cp.async, double-buffered
// =====================================================================
#define FK (64 * GP)
#define FL_SMEM_B (2 * 6 * FK * 2)

__global__ void __launch_bounds__(256) flash_mma()
{
    extern __shared__ __nv_bfloat16 fs[];
    const uint32_t sbs = smem_u32(fs);

    const int tid = threadIdx.x;
    const int wid = tid >> 5, lane = tid & 31;
    const int lq = lane >> 2;
    const int lk = (lane & 3) * 2;
    const int bh = blockIdx.y;
    const int l0 = blockIdx.x * 128;
    const int bhS = bh * 1024;

    // Q fragments (hi/lo), held in registers
    uint32_t qh[4][4], ql[4][4];
    {
        const float* q0 = g_qh + (size_t)(bhS + l0 + wid * 16 + lq) * 64;
        const float* q8 = q0 + 8 * 64;
#pragma unroll
        for (int ks = 0; ks < 4; ks++) {
            float2 x00 = *(const float2*)(q0 + ks * 16 + lk);
            float2 x10 = *(const float2*)(q8 + ks * 16 + lk);
            float2 x01 = *(const float2*)(q0 + ks * 16 + lk + 8);
            float2 x11 = *(const float2*)(q8 + ks * 16 + lk + 8);
            qh[ks][0] = pk_hi(x00.x, x00.y); ql[ks][0] = pk_lo(x00.x, x00.y);
            qh[ks][1] = pk_hi(x10.x, x10.y); ql[ks][1] = pk_lo(x10.x, x10.y);
            qh[ks][2] = pk_hi(x01.x, x01.y); ql[ks][2] = pk_lo(x01.x, x01.y);
            qh[ks][3] = pk_hi(x11.x, x11.y); ql[ks][3] = pk_lo(x11.x, x11.y);
        }
    }
    const float ll0 = g_ll[bhS + l0 + wid * 16 + lq];
    const float ll1 = g_ll[bhS + l0 + wid * 16 + lq + 8];

    float m0 = -1e30f, m1 = -1e30f, ls0 = 0.f, ls1 = 0.f;
    float o[8][4];
#pragma unroll
    for (int dt = 0; dt < 8; dt++)
#pragma unroll
        for (int c = 0; c < 4; c++) o[dt][c] = 0.f;

    // async stage: 6 tiles x 512 chunks of 16B, 12 per thread
    auto issue = [&](int buf, int s0) {
        const uint32_t dbase = sbs + (uint32_t)buf * (6 * FK * 2);
#pragma unroll
        for (int t = 0; t < 12; t++) {
            int cid = tid + t * 256;
            int tile = cid >> 9;
            int r = (cid >> 3) & 63;
            int c = cid & 7;
            const __nv_bfloat16* src;
            if (tile == 0)      src = g_k1hb + ((size_t)(bhS + s0 + r) * 64 + c * 8);
            else if (tile == 1) src = g_k1lb + ((size_t)(bhS + s0 + r) * 64 + c * 8);
            else if (tile == 2) src = g_k2hb + ((size_t)(bhS + s0 + r) * 64 + c * 8);
            else if (tile == 3) src = g_k2lb + ((size_t)(bhS + s0 + r) * 64 + c * 8);
            else if (tile == 4) src = g_vthb + ((size_t)(bh * 64 + r) * 1024 + s0 + c * 8);
            else                src = g_vtlb + ((size_t)(bh * 64 + r) * 1024 + s0 + c * 8);
            cpa16(dbase + (uint32_t)(tile * FK + r * GP + c * 8) * 2, src);
        }
        asm volatile("cp.async.commit_group;");
    };

    issue(0, 0);

    for (int it = 0; it < 16; it++) {
        const int buf = it & 1;
        const int s0 = it * 64;
        if (it < 15) issue(buf ^ 1, s0 + 64);
        if (it < 15) asm volatile("cp.async.wait_group 1;");
        else         asm volatile("cp.async.wait_group 0;");
        __syncthreads();

        const __nv_bfloat16* Kb  = fs + buf * (6 * FK);
        const __nv_bfloat16* K1h = Kb;
        const __nv_bfloat16* K1l = Kb + FK;
        const __nv_bfloat16* K2h = Kb + 2 * FK;
        const __nv_bfloat16* K2l = Kb + 3 * FK;
        const __nv_bfloat16* VTh = Kb + 4 * FK;
        const __nv_bfloat16* VTl = Kb + 5 * FK;

        // QK1^T, QK2^T (3-term split)
        float lv[8][4], la[8][4];
#pragma unroll
        for (int nt = 0; nt < 8; nt++)
#pragma unroll
            for (int c = 0; c < 4; c++) { lv[nt][c] = 0.f; la[nt][c] = 0.f; }
#pragma unroll
        for (int nt = 0; nt < 8; nt++) {
#pragma unroll
            for (int ks = 0; ks < 4; ks++) {
                const __nv_bfloat16* b1h = K1h + (nt * 8 + lq) * GP + ks * 16 + lk;
                uint32_t h0 = *(const uint32_t*)b1h;
                uint32_t h1 = *(const uint32_t*)(b1h + 8);
                const __nv_bfloat16* b1l = K1l + (nt * 8 + lq) * GP + ks * 16 + lk;
                uint32_t l0_ = *(const uint32_t*)b1l;
                uint32_t l1_ = *(const uint32_t*)(b1l + 8);
                mma16816(lv[nt], qh[ks][0], qh[ks][1], qh[ks][2], qh[ks][3], h0, h1);
                mma16816(lv[nt], qh[ks][0], qh[ks][1], qh[ks][2], qh[ks][3], l0_, l1_);
                mma16816(lv[nt], ql[ks][0], ql[ks][1], ql[ks][2], ql[ks][3], h0, h1);
                const __nv_bfloat16* b2h = K2h + (nt * 8 + lq) * GP + ks * 16 + lk;
                uint32_t g0 = *(const uint32_t*)b2h;
                uint32_t g1 = *(const uint32_t*)(b2h + 8);
                const __nv_bfloat16* b2l = K2l + (nt * 8 + lq) * GP + ks * 16 + lk;
                uint32_t e0 = *(const uint32_t*)b2l;
                uint32_t e1 = *(const uint32_t*)(b2l + 8);
                mma16816(la[nt], qh[ks][0], qh[ks][1], qh[ks][2], qh[ks][3], g0, g1);
                mma16816(la[nt], qh[ks][0], qh[ks][1], qh[ks][2], qh[ks][3], e0, e1);
                mma16816(la[nt], ql[ks][0], ql[ks][1], ql[ks][2], ql[ks][3], g0, g1);
            }
        }

        // gram-det scores + row max
        float mx0 = -1e30f, mx1 = -1e30f;
#pragma unroll
        for (int nt = 0; nt < 8; nt++) {
            float2 vv2 = *(const float2*)(g_vv + bhS + s0 + nt * 8 + lk);
            float2 aa2 = *(const float2*)(g_aa + bhS + s0 + nt * 8 + lk);
            float2 va2 = *(const float2*)(g_va + bhS + s0 + nt * 8 + lk);
            float g2x = vv2.x * aa2.x - va2.x * va2.x;
            float g2y = vv2.y * aa2.y - va2.y * va2.y;
            {
                float LV = lv[nt][0], LA = la[nt][0];
                float det = ll0 * g2x - LV * (LV * aa2.x - LA * va2.x) + LA * (LV * va2.x - LA * vv2.x);
                float sc = -fsqrt_pos(fmaxf(det, 1e-8f));
                lv[nt][0] = sc; mx0 = fmaxf(mx0, sc);
            }
            {
                float LV = lv[nt][1], LA = la[nt][1];
                float det = ll0 * g2y - LV * (LV * aa2.y - LA * va2.y) + LA * (LV * va2.y - LA * vv2.y);
                float sc = -fsqrt_pos(fmaxf(det, 1e-8f));
                lv[nt][1] = sc; mx0 = fmaxf(mx0, sc);
            }
            {
                float LV = lv[nt][2], LA = la[nt][2];
                float det = ll1 * g2x - LV * (LV * aa2.x - LA * va2.x) + LA * (LV * va2.x - LA * vv2.x);
                float sc = -fsqrt_pos(fmaxf(det, 1e-8f));
                lv[nt][2] = sc; mx1 = fmaxf(mx1, sc);
            }
            {
                float LV = lv[nt][3], LA = la[nt][3];
                float det = ll1 * g2y - LV * (LV * aa2.y - LA * va2.y) + LA * (LV * va2.y - LA * vv2.y);
                float sc = -fsqrt_pos(fmaxf(det, 1e-8f));
                lv[nt][3] = sc; mx1 = fmaxf(mx1, sc);
            }
        }
        mx0 = fmaxf(mx0, __shfl_xor_sync(0xffffffffu, mx0, 1));
        mx0 = fmaxf(mx0, __shfl_xor_sync(0xffffffffu, mx0, 2));
        mx1 = fmaxf(mx1, __shfl_xor_sync(0xffffffffu, mx1, 1));
        mx1 = fmaxf(mx1, __shfl_xor_sync(0xffffffffu, mx1, 2));

        float mn0 = fmaxf(m0, mx0), mn1 = fmaxf(m1, mx1);
        float alpha0 = fexp(m0 - mn0), alpha1 = fexp(m1 - mn1);
        m0 = mn0; m1 = mn1;

        float rs0 = 0.f, rs1 = 0.f;
#pragma unroll
        for (int nt = 0; nt < 8; nt++) {
            float p0 = fexp(lv[nt][0] - mn0);
            float p1 = fexp(lv[nt][1] - mn0);
            float p2 = fexp(lv[nt][2] - mn1);
            float p3 = fexp(lv[nt][3] - mn1);
            lv[nt][0] = p0; lv[nt][1] = p1; lv[nt][2] = p2; lv[nt][3] = p3;
            rs0 += p0 + p1; rs1 += p2 + p3;
        }
        rs0 += __shfl_xor_sync(0xffffffffu, rs0, 1);
        rs0 += __shfl_xor_sync(0xffffffffu, rs0, 2);
        rs1 += __shfl_xor_sync(0xffffffffu, rs1, 1);
        rs1 += __shfl_xor_sync(0xffffffffu, rs1, 2);
        ls0 = ls0 * alpha0 + rs0;
        ls1 = ls1 * alpha1 + rs1;

#pragma unroll
        for (int dt = 0; dt < 8; dt++) {
            o[dt][0] *= alpha0; o[dt][1] *= alpha0;
            o[dt][2] *= alpha1; o[dt][3] *= alpha1;
        }

        // P fragments (hi/lo)
        uint32_t ph[4][4], pl[4][4];
#pragma unroll
        for (int ks = 0; ks < 4; ks++) {
            ph[ks][0] = pk_hi(lv[2 * ks][0], lv[2 * ks][1]);
            pl[ks][0] = pk_lo(lv[2 * ks][0], lv[2 * ks][1]);
            ph[ks][1] = pk_hi(lv[2 * ks][2], lv[2 * ks][3]);
            pl[ks][1] = pk_lo(lv[2 * ks][2], lv[2 * ks][3]);
            ph[ks][2] = pk_hi(lv[2 * ks + 1][0], lv[2 * ks + 1][1]);
            pl[ks][2] = pk_lo(lv[2 * ks + 1][0], lv[2 * ks + 1][1]);
            ph[ks][3] = pk_hi(lv[2 * ks + 1][2], lv[2 * ks + 1][3]);
            pl[ks][3] = pk_lo(lv[2 * ks + 1][2], lv[2 * ks + 1][3]);
        }

        // PV (3-term split)
#pragma unroll
        for (int dt = 0; dt < 8; dt++) {
#pragma unroll
            for (int ks = 0; ks < 4; ks++) {
                const __nv_bfloat16* vh = VTh + (dt * 8 + lq) * GP + ks * 16 + lk;
                uint32_t vh0 = *(const uint32_t*)vh;
                uint32_t vh1 = *(const uint32_t*)(vh + 8);
                const __nv_bfloat16* vl = VTl + (dt * 8 + lq) * GP + ks * 16 + lk;
                uint32_t vl0 = *(const uint32_t*)vl;
                uint32_t vl1 = *(const uint32_t*)(vl + 8);
                mma16816(o[dt], ph[ks][0], ph[ks][1], ph[ks][2], ph[ks][3], vh0, vh1);
                mma16816(o[dt], ph[ks][0], ph[ks][1], ph[ks][2], ph[ks][3], vl0, vl1);
                mma16816(o[dt], pl[ks][0], pl[ks][1], pl[ks][2], pl[ks][3], vh0, vh1);
            }
        }
        __syncthreads();
    }

    const float inv0 = frcp_pos(ls0);
    const float inv1 = frcp_pos(ls1);
    const int bi = bh >> 3, h = bh & 7;
    const int r0 = l0 + wid * 16 + lq;
#pragma unroll
    for (int dt = 0; dt < 8; dt++) {
        int d = dt * 8 + lk;
        float2 v0, v1;
        v0.x = o[dt][0] * inv0; v0.y = o[dt][1] * inv0;
        v1.x = o[dt][2] * inv1; v1.y = o[dt][3] * inv1;
        *(float2*)(g_ao + (size_t)(r0 * 8 + bi) * 512 + h * 64 + d) = v0;
        *(float2*)(g_ao + (size_t)((r0 + 8) * 8 + bi) * 512 + h * 64 + d) = v1;
    }
}

// ---------------- launch ----------------
extern "C" void kernel_launch(void* const* d_in, const int* in_sizes, int n_in,
                              void* d_out, int out_size) {
    const float* query = (const float*)d_in[0];
    const float* mod1  = (const float*)d_in[1];
    const float* mod2  = (const float*)d_in[2];
    const float* Wq  = (const float*)d_in[3];  const float* bq  = (const float*)d_in[4];
    const float* Wk1 = (const float*)d_in[5];  const float* bk1 = (const float*)d_in[6];
    const float* Wk2 = (const float*)d_in[7];  const float* bk2 = (const float*)d_in[8];
    const float* Wv1 = (const float*)d_in[9];  const float* bv1 = (const float*)d_in[10];
    const float* Wv2 = (const float*)d_in[11]; const float* bv2 = (const float*)d_in[12];
    const float* Wg1 = (const float*)d_in[13]; const float* bg1 = (const float*)d_in[14];
    const float* Wg2 = (const float*)d_in[15]; const float* bg2 = (const float*)d_in[16];
    const float* Wo  = (const float*)d_in[17]; const float* bo  = (const float*)d_in[18];
    float* out = (float*)d_out;

    float *p_vh, *p_ao;
    cudaGetSymbolAddress((void**)&p_vh,  g_vh);
    cudaGetSymbolAddress((void**)&p_ao,  g_ao);

    cudaFuncSetAttribute(proj3_mma,  cudaFuncAttributeMaxDynamicSharedMemorySize, PJ_SMEM_B);
    cudaFuncSetAttribute(proj_out,   cudaFuncAttributeMaxDynamicSharedMemorySize, PJ_SMEM_B);
    cudaFuncSetAttribute(projvg_mma, cudaFuncAttributeMaxDynamicSharedMemorySize, VG_SMEM_B);
    cudaFuncSetAttribute(flash_mma,  cudaFuncAttributeMaxDynamicSharedMemorySize, FL_SMEM_B);

    dim3 pb(256);
    proj3_mma<<<dim3(64, 4, 3), pb, PJ_SMEM_B>>>(query, mod1, mod2,
                                                 Wq, bq, Wk1, bk1, Wk2, bk2);
    projvg_mma<<<dim3(64, 4), pb, VG_SMEM_B>>>(mod1, Wv1, bv1, Wg1, bg1, p_vh, 0);
    projvg_mma<<<dim3(64, 4), pb, VG_SMEM_B>>>(mod2, Wv2, bv2, Wg2, bg2, p_vh, 1);
    norm_q_kernel<<<8192, 256>>>();
    norm_k_kernel<<<8192, 256>>>();
    prep_vt<<<dim3(16, 64), 256>>>();
    flash_mma<<<dim3(8, 64), 256, FL_SMEM_B>>>();
    proj_out<<<dim3(64, 4), pb, PJ_SMEM_B>>>(p_ao, Wo, bo, out);
}

// round 8
// speedup vs baseline: 2.2630x; 1.0519x over previous
#include <cuda_runtime.h>
#include <cuda_bf16.h>
#include <cstdint>

#define CL   1024
#define CS   1024
#define CB   8
#define CE   512
#define CH   8
#define CDH  64
#define CBH  64
#define CM   8192
#define CK   512
#define WSZ  (CE * CK)

// ---------------- device scratch ----------------
__device__ __align__(128) float g_qh [CBH * CL * CDH];
__device__ __align__(128) float g_k1h[CBH * CS * CDH];
__device__ __align__(128) float g_k2h[CBH * CS * CDH];
__device__ __align__(128) float g_vh [CBH * CS * CDH];
__device__ __align__(128) float g_ll [CBH * CL];
__device__ __align__(128) float g_vv [CBH * CS];
__device__ __align__(128) float g_aa [CBH * CS];
__device__ __align__(128) float g_va [CBH * CS];
// bf16 hi/lo operand caches
__device__ __align__(128) __nv_bfloat16 g_k1hb[CBH * CS * CDH];
__device__ __align__(128) __nv_bfloat16 g_k1lb[CBH * CS * CDH];
__device__ __align__(128) __nv_bfloat16 g_k2hb[CBH * CS * CDH];
__device__ __align__(128) __nv_bfloat16 g_k2lb[CBH * CS * CDH];
__device__ __align__(128) __nv_bfloat16 g_vthb[CBH * CDH * CS];   // [bh][d][s]
__device__ __align__(128) __nv_bfloat16 g_vtlb[CBH * CDH * CS];
// pre-split GEMM operands
__device__ __align__(128) __nv_bfloat16 g_qryh[CM * CK];
__device__ __align__(128) __nv_bfloat16 g_qryl[CM * CK];
__device__ __align__(128) __nv_bfloat16 g_m1h [CM * CK];
__device__ __align__(128) __nv_bfloat16 g_m1l [CM * CK];
__device__ __align__(128) __nv_bfloat16 g_m2h [CM * CK];
__device__ __align__(128) __nv_bfloat16 g_m2l [CM * CK];
__device__ __align__(128) __nv_bfloat16 g_wh  [8 * WSZ];
__device__ __align__(128) __nv_bfloat16 g_wl  [8 * WSZ];
__device__ __align__(128) __nv_bfloat16 g_aoh [CM * CE];
__device__ __align__(128) __nv_bfloat16 g_aol [CM * CE];

// ---------------- MUFU-free math ----------------
__device__ __forceinline__ float fexp(float x) {
    float t = x * 1.4426950408889634f;
    t = fminf(fmaxf(t, -126.0f), 126.0f);
    int i = __float2int_rn(t);
    float u = (t - (float)i) * 0.6931471805599453f;
    float p = 1.3888889e-3f;
    p = fmaf(p, u, 8.3333333e-3f);
    p = fmaf(p, u, 4.1666667e-2f);
    p = fmaf(p, u, 1.6666667e-1f);
    p = fmaf(p, u, 0.5f);
    p = fmaf(p, u, 1.0f);
    p = fmaf(p, u, 1.0f);
    return p * __int_as_float((i + 127) << 23);
}
__device__ __forceinline__ float fsqrt_pos(float x) {
    float y = __int_as_float(0x5f3759df - (__float_as_int(x) >> 1));
    y = y * fmaf(-0.5f * x, y * y, 1.5f);
    y = y * fmaf(-0.5f * x, y * y, 1.5f);
    y = y * fmaf(-0.5f * x, y * y, 1.5f);
    return x * y;
}
__device__ __forceinline__ float frcp_pos(float x) {
    float y = __int_as_float(0x7EF127EAu - __float_as_int(x));
    y = y * (2.0f - x * y);
    y = y * (2.0f - x * y);
    y = y * (2.0f - x * y);
    return y;
}

// ---------------- mma.sync bf16 helper ----------------
__device__ __forceinline__ void mma16816(float* c,
    uint32_t a0, uint32_t a1, uint32_t a2, uint32_t a3,
    uint32_t b0, uint32_t b1)
{
    asm volatile(
        "mma.sync.aligned.m16n8k16.row.col.f32.bf16.bf16.f32 "
        "{%0,%1,%2,%3},{%4,%5,%6,%7},{%8,%9},{%0,%1,%2,%3};"
        : "+f"(c[0]), "+f"(c[1]), "+f"(c[2]), "+f"(c[3])
        : "r"(a0), "r"(a1), "r"(a2), "r"(a3), "r"(b0), "r"(b1));
}

#define GP 72
#define TSZ (128 * GP)
__device__ __forceinline__ uint32_t pkbf(__nv_bfloat16 a, __nv_bfloat16 b) {
    __nv_bfloat162 t(a, b);
    return *reinterpret_cast<uint32_t*>(&t);
}
__device__ __forceinline__ uint32_t pk_hi(float x, float y) {
    return pkbf(__float2bfloat16(x), __float2bfloat16(y));
}
__device__ __forceinline__ uint32_t pk_lo(float x, float y) {
    __nv_bfloat16 hx = __float2bfloat16(x), hy = __float2bfloat16(y);
    return pkbf(__float2bfloat16(x - __bfloat162float(hx)),
                __float2bfloat16(y - __bfloat162float(hy)));
}
__device__ __forceinline__ uint32_t smem_u32(const void* p) {
    uint32_t a;
    asm("{ .reg .u64 t; cvta.to.shared.u64 t, %1; cvt.u32.u64 %0, t; }" : "=r"(a) : "l"(p));
    return a;
}
__device__ __forceinline__ void cpa16(uint32_t dst, const void* src) {
    asm volatile("cp.async.cg.shared.global [%0], [%1], 16;" :: "r"(dst), "l"(src));
}

// ---------------- prep: fp32 -> hi/lo bf16 ----------------
__global__ void __launch_bounds__(256)
prep_act(const float* __restrict__ q, const float* __restrict__ m1,
         const float* __restrict__ m2)
{
    const int z = blockIdx.z;
    const float* src = (z == 0) ? q : (z == 1) ? m1 : m2;
    __nv_bfloat16* H = (z == 0) ? g_qryh : (z == 1) ? g_m1h : g_m2h;
    __nv_bfloat16* L = (z == 0) ? g_qryl : (z == 1) ? g_m1l : g_m2l;
    size_t i4 = (size_t)blockIdx.x * 256 + threadIdx.x;
    float4 x = ((const float4*)src)[i4];
    ((uint2*)H)[i4] = make_uint2(pk_hi(x.x, x.y), pk_hi(x.z, x.w));
    ((uint2*)L)[i4] = make_uint2(pk_lo(x.x, x.y), pk_lo(x.z, x.w));
}

__global__ void __launch_bounds__(256)
prep_w(const float* __restrict__ w0, const float* __restrict__ w1,
       const float* __restrict__ w2, const float* __restrict__ w3,
       const float* __restrict__ w4, const float* __restrict__ w5,
       const float* __restrict__ w6, const float* __restrict__ w7)
{
    const int z = blockIdx.z;
    const float* src;
    switch (z) {
        case 0: src = w0; break; case 1: src = w1; break;
        case 2: src = w2; break; case 3: src = w3; break;
        case 4: src = w4; break; case 5: src = w5; break;
        case 6: src = w6; break; default: src = w7; break;
    }
    size_t i4 = (size_t)blockIdx.x * 256 + threadIdx.x;
    float4 x = ((const float4*)src)[i4];
    ((uint2*)(g_wh + (size_t)z * WSZ))[i4] = make_uint2(pk_hi(x.x, x.y), pk_hi(x.z, x.w));
    ((uint2*)(g_wl + (size_t)z * WSZ))[i4] = make_uint2(pk_lo(x.x, x.y), pk_lo(x.z, x.w));
}

// =====================================================================
// proj3_cp: q/k1/k2 projections, pre-split operands, cp.async pipelined
// =====================================================================
#define PJ_STAGE (4 * TSZ)
#define PJ_SMEM_B (2 * PJ_STAGE * 2)

__global__ void __launch_bounds__(256)
proj3_cp(const float* __restrict__ bq, const float* __restrict__ bk1,
         const float* __restrict__ bk2)
{
    extern __shared__ __nv_bfloat16 fs[];
    const uint32_t sbs = smem_u32(fs);
    const int z = blockIdx.z;
    const __nv_bfloat16* Ah_g = (z == 0) ? g_qryh : (z == 1) ? g_m1h : g_m2h;
    const __nv_bfloat16* Al_g = (z == 0) ? g_qryl : (z == 1) ? g_m1l : g_m2l;
    const __nv_bfloat16* Wh_g = g_wh + (size_t)z * WSZ;
    const __nv_bfloat16* Wl_g = g_wl + (size_t)z * WSZ;
    const float* bias = (z == 0) ? bq : (z == 1) ? bk1 : bk2;
    float* C = (z == 0) ? g_qh : (z == 1) ? g_k1h : g_k2h;
    __nv_bfloat16* CHo = (z == 1) ? g_k1hb : g_k2hb;
    __nv_bfloat16* CLo = (z == 1) ? g_k1lb : g_k2lb;

    const int tid = threadIdx.x;
    const int wid = tid >> 5, lane = tid & 31;
    const int wm = wid >> 2, wn = wid & 3;
    const int m0 = blockIdx.x * 128;
    const int n0 = blockIdx.y * 128;
    const int lq = lane >> 2;
    const int lk = (lane & 3) * 2;

    auto issue = [&](int buf, int k0) {
        const uint32_t dbase = sbs + (uint32_t)buf * (PJ_STAGE * 2);
#pragma unroll
        for (int t = 0; t < 16; t++) {
            int cid = tid + t * 256;
            int tile = cid >> 10;
            int r = (cid >> 3) & 127;
            int c = cid & 7;
            const __nv_bfloat16* src;
            if (tile == 0)      src = Ah_g + (size_t)(m0 + r) * CK + k0 + c * 8;
            else if (tile == 1) src = Al_g + (size_t)(m0 + r) * CK + k0 + c * 8;
            else if (tile == 2) src = Wh_g + (size_t)(n0 + r) * CK + k0 + c * 8;
            else                src = Wl_g + (size_t)(n0 + r) * CK + k0 + c * 8;
            cpa16(dbase + (uint32_t)(tile * TSZ + r * GP + c * 8) * 2, src);
        }
        asm volatile("cp.async.commit_group;");
    };

    float acc[4][4][4];
#pragma unroll
    for (int a = 0; a < 4; a++)
#pragma unroll
        for (int b = 0; b < 4; b++)
#pragma unroll
            for (int c = 0; c < 4; c++) acc[a][b][c] = 0.f;

    issue(0, 0);
    for (int blk = 0; blk < 8; blk++) {
        const int buf = blk & 1;
        if (blk < 7) issue(buf ^ 1, (blk + 1) * 64);
        if (blk < 7) asm volatile("cp.async.wait_group 1;");
        else         asm volatile("cp.async.wait_group 0;");
        __syncthreads();

        const __nv_bfloat16* Ah = fs + buf * PJ_STAGE;
        const __nv_bfloat16* Al = Ah + TSZ;
        const __nv_bfloat16* Wh = Ah + 2 * TSZ;
        const __nv_bfloat16* Wl = Ah + 3 * TSZ;

#pragma unroll
        for (int ks = 0; ks < 4; ks++) {
            uint32_t ah[4][4], al[4][4];
#pragma unroll
            for (int mt = 0; mt < 4; mt++) {
                const __nv_bfloat16* ar = Ah + (wm * 64 + mt * 16 + lq) * GP + ks * 16 + lk;
                ah[mt][0] = *(const uint32_t*)ar;
                ah[mt][1] = *(const uint32_t*)(ar + 8 * GP);
                ah[mt][2] = *(const uint32_t*)(ar + 8);
                ah[mt][3] = *(const uint32_t*)(ar + 8 * GP + 8);
                const __nv_bfloat16* al_ = Al + (wm * 64 + mt * 16 + lq) * GP + ks * 16 + lk;
                al[mt][0] = *(const uint32_t*)al_;
                al[mt][1] = *(const uint32_t*)(al_ + 8 * GP);
                al[mt][2] = *(const uint32_t*)(al_ + 8);
                al[mt][3] = *(const uint32_t*)(al_ + 8 * GP + 8);
            }
#pragma unroll
            for (int nt = 0; nt < 4; nt++) {
                const __nv_bfloat16* bh = Wh + (wn * 32 + nt * 8 + lq) * GP + ks * 16 + lk;
                uint32_t bh0 = *(const uint32_t*)bh;
                uint32_t bh1 = *(const uint32_t*)(bh + 8);
                const __nv_bfloat16* bl = Wl + (wn * 32 + nt * 8 + lq) * GP + ks * 16 + lk;
                uint32_t bl0 = *(const uint32_t*)bl;
                uint32_t bl1 = *(const uint32_t*)(bl + 8);
#pragma unroll
                for (int mt = 0; mt < 4; mt++) {
                    mma16816(acc[mt][nt], ah[mt][0], ah[mt][1], ah[mt][2], ah[mt][3], bh0, bh1);
                    mma16816(acc[mt][nt], ah[mt][0], ah[mt][1], ah[mt][2], ah[mt][3], bl0, bl1);
                    mma16816(acc[mt][nt], al[mt][0], al[mt][1], al[mt][2], al[mt][3], bh0, bh1);
                }
            }
        }
        __syncthreads();
    }

    const float scale = (z == 0) ? 0.125f : 1.0f;
#pragma unroll
    for (int mt = 0; mt < 4; mt++) {
#pragma unroll
        for (int nt = 0; nt < 4; nt++) {
            int row = m0 + wm * 64 + mt * 16 + lq;
            int col = n0 + wn * 32 + nt * 8 + lk;
            float b0 = bias[col], b1 = bias[col + 1];
            int h = col >> 6, d = col & 63;
#pragma unroll
            for (int half = 0; half < 2; half++) {
                int r = row + half * 8;
                int t = r >> 3, bi = r & 7;
                float2 v;
                v.x = (acc[mt][nt][half * 2 + 0] + b0) * scale;
                v.y = (acc[mt][nt][half * 2 + 1] + b1) * scale;
                size_t off = ((size_t)(bi * 8 + h) * 1024 + t) * 64 + d;
                *(float2*)(C + off) = v;
                if (z >= 1) {
                    *(uint32_t*)(CHo + off) = pk_hi(v.x, v.y);
                    *(uint32_t*)(CLo + off) = pk_lo(v.x, v.y);
                }
            }
        }
    }
}

// =====================================================================
// projvg_cp: gated value projection, cp.async pipelined (one modality)
// =====================================================================
#define VG_STAGE (6 * TSZ)
#define VG_SMEM_B (2 * VG_STAGE * 2)

__global__ void __launch_bounds__(256)
projvg_cp(const float* __restrict__ bv, const float* __restrict__ bg, int mod)
{
    extern __shared__ __nv_bfloat16 fs[];
    const uint32_t sbs = smem_u32(fs);
    const __nv_bfloat16* Ah_g = mod ? g_m2h : g_m1h;
    const __nv_bfloat16* Al_g = mod ? g_m2l : g_m1l;
    const __nv_bfloat16* Vh_g = g_wh + (size_t)(3 + mod) * WSZ;
    const __nv_bfloat16* Vl_g = g_wl + (size_t)(3 + mod) * WSZ;
    const __nv_bfloat16* Gh_g = g_wh + (size_t)(5 + mod) * WSZ;
    const __nv_bfloat16* Gl_g = g_wl + (size_t)(5 + mod) * WSZ;

    const int tid = threadIdx.x;
    const int wid = tid >> 5, lane = tid & 31;
    const int wm = wid >> 2, wn = wid & 3;
    const int m0 = blockIdx.x * 128;
    const int n0 = blockIdx.y * 128;
    const int lq = lane >> 2;
    const int lk = (lane & 3) * 2;

    auto issue = [&](int buf, int k0) {
        const uint32_t dbase = sbs + (uint32_t)buf * (VG_STAGE * 2);
#pragma unroll
        for (int t = 0; t < 24; t++) {
            int cid = tid + t * 256;
            int tile = cid >> 10;
            int r = (cid >> 3) & 127;
            int c = cid & 7;
            const __nv_bfloat16* src;
            if (tile == 0)      src = Ah_g + (size_t)(m0 + r) * CK + k0 + c * 8;
            else if (tile == 1) src = Al_g + (size_t)(m0 + r) * CK + k0 + c * 8;
            else if (tile == 2) src = Vh_g + (size_t)(n0 + r) * CK + k0 + c * 8;
            else if (tile == 3) src = Vl_g + (size_t)(n0 + r) * CK + k0 + c * 8;
            else if (tile == 4) src = Gh_g + (size_t)(n0 + r) * CK + k0 + c * 8;
            else                src = Gl_g + (size_t)(n0 + r) * CK + k0 + c * 8;
            cpa16(dbase + (uint32_t)(tile * TSZ + r * GP + c * 8) * 2, src);
        }
        asm volatile("cp.async.commit_group;");
    };

    float av_[4][4][4], ag_[4][4][4];
#pragma unroll
    for (int a = 0; a < 4; a++)
#pragma unroll
        for (int b = 0; b < 4; b++)
#pragma unroll
            for (int c = 0; c < 4; c++) { av_[a][b][c] = 0.f; ag_[a][b][c] = 0.f; }

    issue(0, 0);
    for (int blk = 0; blk < 8; blk++) {
        const int buf = blk & 1;
        if (blk < 7) issue(buf ^ 1, (blk + 1) * 64);
        if (blk < 7) asm volatile("cp.async.wait_group 1;");
        else         asm volatile("cp.async.wait_group 0;");
        __syncthreads();

        const __nv_bfloat16* Ah = fs + buf * VG_STAGE;
        const __nv_bfloat16* Al = Ah + TSZ;
        const __nv_bfloat16* Vh = Ah + 2 * TSZ;
        const __nv_bfloat16* Vl = Ah + 3 * TSZ;
        const __nv_bfloat16* Gh = Ah + 4 * TSZ;
        const __nv_bfloat16* Gl = Ah + 5 * TSZ;

#pragma unroll
        for (int ks = 0; ks < 4; ks++) {
            uint32_t ah[4][4], al[4][4];
#pragma unroll
            for (int mt = 0; mt < 4; mt++) {
                const __nv_bfloat16* ar = Ah + (wm * 64 + mt * 16 + lq) * GP + ks * 16 + lk;
                ah[mt][0] = *(const uint32_t*)ar;
                ah[mt][1] = *(const uint32_t*)(ar + 8 * GP);
                ah[mt][2] = *(const uint32_t*)(ar + 8);
                ah[mt][3] = *(const uint32_t*)(ar + 8 * GP + 8);
                const __nv_bfloat16* al_ = Al + (wm * 64 + mt * 16 + lq) * GP + ks * 16 + lk;
                al[mt][0] = *(const uint32_t*)al_;
                al[mt][1] = *(const uint32_t*)(al_ + 8 * GP);
                al[mt][2] = *(const uint32_t*)(al_ + 8);
                al[mt][3] = *(const uint32_t*)(al_ + 8 * GP + 8);
            }
#pragma unroll
            for (int nt = 0; nt < 4; nt++) {
                const __nv_bfloat16* vh = Vh + (wn * 32 + nt * 8 + lq) * GP + ks * 16 + lk;
                uint32_t vh0 = *(const uint32_t*)vh;
                uint32_t vh1 = *(const uint32_t*)(vh + 8);
                const __nv_bfloat16* vl = Vl + (wn * 32 + nt * 8 + lq) * GP + ks * 16 + lk;
                uint32_t vl0 = *(const uint32_t*)vl;
                uint32_t vl1 = *(const uint32_t*)(vl + 8);
                const __nv_bfloat16* gh = Gh + (wn * 32 + nt * 8 + lq) * GP + ks * 16 + lk;
                uint32_t gh0 = *(const uint32_t*)gh;
                uint32_t gh1 = *(const uint32_t*)(gh + 8);
                const __nv_bfloat16* gl = Gl + (wn * 32 + nt * 8 + lq) * GP + ks * 16 + lk;
                uint32_t gl0 = *(const uint32_t*)gl;
                uint32_t gl1 = *(const uint32_t*)(gl + 8);
#pragma unroll
                for (int mt = 0; mt < 4; mt++) {
                    mma16816(av_[mt][nt], ah[mt][0], ah[mt][1], ah[mt][2], ah[mt][3], vh0, vh1);
                    mma16816(av_[mt][nt], ah[mt][0], ah[mt][1], ah[mt][2], ah[mt][3], vl0, vl1);
                    mma16816(av_[mt][nt], al[mt][0], al[mt][1], al[mt][2], al[mt][3], vh0, vh1);
                    mma16816(ag_[mt][nt], ah[mt][0], ah[mt][1], ah[mt][2], ah[mt][3], gh0, gh1);
                    mma16816(ag_[mt][nt], ah[mt][0], ah[mt][1], ah[mt][2], ah[mt][3], gl0, gl1);
                    mma16816(ag_[mt][nt], al[mt][0], al[mt][1], al[mt][2], al[mt][3], gh0, gh1);
                }
            }
        }
        __syncthreads();
    }

#pragma unroll
    for (int mt = 0; mt < 4; mt++) {
#pragma unroll
        for (int nt = 0; nt < 4; nt++) {
            int row = m0 + wm * 64 + mt * 16 + lq;
            int col = n0 + wn * 32 + nt * 8 + lk;
            float bv0 = bv[col], bv1 = bv[col + 1];
            float bg0 = bg[col], bg1 = bg[col + 1];
            int h = col >> 6, d = col & 63;
#pragma unroll
            for (int half = 0; half < 2; half++) {
                int r = row + half * 8;
                int t = r >> 3, bi = r & 7;
                float vx0 = av_[mt][nt][half * 2 + 0] + bv0;
                float vx1 = av_[mt][nt][half * 2 + 1] + bv1;
                float gx0 = ag_[mt][nt][half * 2 + 0] + bg0;
                float gx1 = ag_[mt][nt][half * 2 + 1] + bg1;
                float2 v;
                v.x = vx0 * frcp_pos(1.0f + fexp(-gx0));
                v.y = vx1 * frcp_pos(1.0f + fexp(-gx1));
                float* dst = g_vh + ((size_t)(bi * 8 + h) * 1024 + t) * 64 + d;
                if (mod) {
                    float2 old = *(float2*)dst;
                    v.x += old.x; v.y += old.y;
                }
                *(float2*)dst = v;
            }
        }
    }
}

// =====================================================================
// proj_out_cp: out = ao @ Wo^T + bo (row-major), pre-split ao from flash
// =====================================================================
__global__ void __launch_bounds__(256)
proj_out_cp(const float* __restrict__ bias, float* __restrict__ C)
{
    extern __shared__ __nv_bfloat16 fs[];
    const uint32_t sbs = smem_u32(fs);
    const __nv_bfloat16* Wh_g = g_wh + (size_t)7 * WSZ;
    const __nv_bfloat16* Wl_g = g_wl + (size_t)7 * WSZ;

    const int tid = threadIdx.x;
    const int wid = tid >> 5, lane = tid & 31;
    const int wm = wid >> 2, wn = wid & 3;
    const int m0 = blockIdx.x * 128;
    const int n0 = blockIdx.y * 128;
    const int lq = lane >> 2;
    const int lk = (lane & 3) * 2;

    auto issue = [&](int buf, int k0) {
        const uint32_t dbase = sbs + (uint32_t)buf * (PJ_STAGE * 2);
#pragma unroll
        for (int t = 0; t < 16; t++) {
            int cid = tid + t * 256;
            int tile = cid >> 10;
            int r = (cid >> 3) & 127;
            int c = cid & 7;
            const __nv_bfloat16* src;
            if (tile == 0)      src = g_aoh + (size_t)(m0 + r) * CE + k0 + c * 8;
            else if (tile == 1) src = g_aol + (size_t)(m0 + r) * CE + k0 + c * 8;
            else if (tile == 2) src = Wh_g + (size_t)(n0 + r) * CK + k0 + c * 8;
            else                src = Wl_g + (size_t)(n0 + r) * CK + k0 + c * 8;
            cpa16(dbase + (uint32_t)(tile * TSZ + r * GP + c * 8) * 2, src);
        }
        asm volatile("cp.async.commit_group;");
    };

    float acc[4][4][4];
#pragma unroll
    for (int a = 0; a < 4; a++)
#pragma unroll
        for (int b = 0; b < 4; b++)
#pragma unroll
            for (int c = 0; c < 4; c++) acc[a][b][c] = 0.f;

    issue(0, 0);
    for (int blk = 0; blk < 8; blk++) {
        const int buf = blk & 1;
        if (blk < 7) issue(buf ^ 1, (blk + 1) * 64);
        if (blk < 7) asm volatile("cp.async.wait_group 1;");
        else         asm volatile("cp.async.wait_group 0;");
        __syncthreads();

        const __nv_bfloat16* Ah = fs + buf * PJ_STAGE;
        const __nv_bfloat16* Al = Ah + TSZ;
        const __nv_bfloat16* Wh = Ah + 2 * TSZ;
        const __nv_bfloat16* Wl = Ah + 3 * TSZ;

#pragma unroll
        for (int ks = 0; ks < 4; ks++) {
            uint32_t ah[4][4], al[4][4];
#pragma unroll
            for (int mt = 0; mt < 4; mt++) {
                const __nv_bfloat16* ar = Ah + (wm * 64 + mt * 16 + lq) * GP + ks * 16 + lk;
                ah[mt][0] = *(const uint32_t*)ar;
                ah[mt][1] = *(const uint32_t*)(ar + 8 * GP);
                ah[mt][2] = *(const uint32_t*)(ar + 8);
                ah[mt][3] = *(const uint32_t*)(ar + 8 * GP + 8);
                const __nv_bfloat16* al_ = Al + (wm * 64 + mt * 16 + lq) * GP + ks * 16 + lk;
                al[mt][0] = *(const uint32_t*)al_;
                al[mt][1] = *(const uint32_t*)(al_ + 8 * GP);
                al[mt][2] = *(const uint32_t*)(al_ + 8);
                al[mt][3] = *(const uint32_t*)(al_ + 8 * GP + 8);
            }
#pragma unroll
            for (int nt = 0; nt < 4; nt++) {
                const __nv_bfloat16* bh = Wh + (wn * 32 + nt * 8 + lq) * GP + ks * 16 + lk;
                uint32_t bh0 = *(const uint32_t*)bh;
                uint32_t bh1 = *(const uint32_t*)(bh + 8);
                const __nv_bfloat16* bl = Wl + (wn * 32 + nt * 8 + lq) * GP + ks * 16 + lk;
                uint32_t bl0 = *(const uint32_t*)bl;
                uint32_t bl1 = *(const uint32_t*)(bl + 8);
#pragma unroll
                for (int mt = 0; mt < 4; mt++) {
                    mma16816(acc[mt][nt], ah[mt][0], ah[mt][1], ah[mt][2], ah[mt][3], bh0, bh1);
                    mma16816(acc[mt][nt], ah[mt][0], ah[mt][1], ah[mt][2], ah[mt][3], bl0, bl1);
                    mma16816(acc[mt][nt], al[mt][0], al[mt][1], al[mt][2], al[mt][3], bh0, bh1);
                }
            }
        }
        __syncthreads();
    }

#pragma unroll
    for (int mt = 0; mt < 4; mt++) {
#pragma unroll
        for (int nt = 0; nt < 4; nt++) {
            int row = m0 + wm * 64 + mt * 16 + lq;
            int col = n0 + wn * 32 + nt * 8 + lk;
            float b0 = bias[col], b1 = bias[col + 1];
#pragma unroll
            for (int half = 0; half < 2; half++) {
                int r = row + half * 8;
                float2 v;
                v.x = acc[mt][nt][half * 2 + 0] + b0;
                v.y = acc[mt][nt][half * 2 + 1] + b1;
                *(float2*)(C + (size_t)r * CE + col) = v;
            }
        }
    }
}

// ---------------- per-row norms ----------------
__global__ void __launch_bounds__(256) norm_q_kernel()
{
    int row  = blockIdx.x * 8 + (threadIdx.x >> 5);
    int lane = threadIdx.x & 31;
    const float* p = g_qh + row * 64;
    float a = p[lane], b = p[lane + 32];
    float s = a * a + b * b;
#pragma unroll
    for (int o = 16; o; o >>= 1) s += __shfl_down_sync(0xffffffffu, s, o);
    if (lane == 0) g_ll[row] = s;
}

__global__ void __launch_bounds__(256) norm_k_kernel()
{
    int row  = blockIdx.x * 8 + (threadIdx.x >> 5);
    int lane = threadIdx.x & 31;
    const float* p1 = g_k1h + row * 64;
    const float* p2 = g_k2h + row * 64;
    float x0 = p1[lane], x1 = p1[lane + 32];
    float y0 = p2[lane], y1 = p2[lane + 32];
    float svv = x0 * x0 + x1 * x1;
    float saa = y0 * y0 + y1 * y1;
    float sva = x0 * y0 + x1 * y1;
#pragma unroll
    for (int o = 16; o; o >>= 1) {
        svv += __shfl_down_sync(0xffffffffu, svv, o);
        saa += __shfl_down_sync(0xffffffffu, saa, o);
        sva += __shfl_down_sync(0xffffffffu, sva, o);
    }
    if (lane == 0) { g_vv[row] = svv; g_aa[row] = saa; g_va[row] = sva; }
}

// ---------------- V transpose -> bf16 hi/lo VT [bh][d][s] ----------------
__global__ void __launch_bounds__(256) prep_vt()
{
    __shared__ float tile[64 * 65];
    const int bh = blockIdx.y;
    const int s0 = blockIdx.x * 64;
    const int tid = threadIdx.x;
    const float* vp = g_vh + (size_t)(bh * 1024 + s0) * 64;
#pragma unroll
    for (int u = 0; u < 4; u++) {
        int id = tid + u * 256;
        int r = id >> 4, c4 = (id & 15) * 4;
        float4 x = *(const float4*)(vp + r * 64 + c4);
        tile[r * 65 + c4 + 0] = x.x;
        tile[r * 65 + c4 + 1] = x.y;
        tile[r * 65 + c4 + 2] = x.z;
        tile[r * 65 + c4 + 3] = x.w;
    }
    __syncthreads();
#pragma unroll
    for (int u = 0; u < 8; u++) {
        int id = tid + u * 256;
        int d = id >> 5, sp = id & 31;
        float x0 = tile[(2 * sp) * 65 + d];
        float x1 = tile[(2 * sp + 1) * 65 + d];
        size_t off = ((size_t)(bh * 64 + d) * 1024 + s0 + 2 * sp);
        *(uint32_t*)(g_vthb + off) = pk_hi(x0, x1);
        *(uint32_t*)(g_vtlb + off) = pk_lo(x0, x1);
    }
}

// =====================================================================
// flash_mma: cp.async double-buffered (epilogue -> bf16 hi/lo)
// =====================================================================
#define FK (64 * GP)
#define FL_SMEM_B (2 * 6 * FK * 2)

__global__ void __launch_bounds__(256) flash_mma()
{
    extern __shared__ __nv_bfloat16 fs[];
    const uint32_t sbs = smem_u32(fs);

    const int tid = threadIdx.x;
    const int wid = tid >> 5, lane = tid & 31;
    const int lq = lane >> 2;
    const int lk = (lane & 3) * 2;
    const int bh = blockIdx.y;
    const int l0 = blockIdx.x * 128;
    const int bhS = bh * 1024;

    uint32_t qh[4][4], ql[4][4];
    {
        const float* q0 = g_qh + (size_t)(bhS + l0 + wid * 16 + lq) * 64;
        const float* q8 = q0 + 8 * 64;
#pragma unroll
        for (int ks = 0; ks < 4; ks++) {
            float2 x00 = *(const float2*)(q0 + ks * 16 + lk);
            float2 x10 = *(const float2*)(q8 + ks * 16 + lk);
            float2 x01 = *(const float2*)(q0 + ks * 16 + lk + 8);
            float2 x11 = *(const float2*)(q8 + ks * 16 + lk + 8);
            qh[ks][0] = pk_hi(x00.x, x00.y); ql[ks][0] = pk_lo(x00.x, x00.y);
            qh[ks][1] = pk_hi(x10.x, x10.y); ql[ks][1] = pk_lo(x10.x, x10.y);
            qh[ks][2] = pk_hi(x01.x, x01.y); ql[ks][2] = pk_lo(x01.x, x01.y);
            qh[ks][3] = pk_hi(x11.x, x11.y); ql[ks][3] = pk_lo(x11.x, x11.y);
        }
    }
    const float ll0 = g_ll[bhS + l0 + wid * 16 + lq];
    const float ll1 = g_ll[bhS + l0 + wid * 16 + lq + 8];

    float m0 = -1e30f, m1 = -1e30f, ls0 = 0.f, ls1 = 0.f;
    float o[8][4];
#pragma unroll
    for (int dt = 0; dt < 8; dt++)
#pragma unroll
        for (int c = 0; c < 4; c++) o[dt][c] = 0.f;

    auto issue = [&](int buf, int s0) {
        const uint32_t dbase = sbs + (uint32_t)buf * (6 * FK * 2);
#pragma unroll
        for (int t = 0; t < 12; t++) {
            int cid = tid + t * 256;
            int tile = cid >> 9;
            int r = (cid >> 3) & 63;
            int c = cid & 7;
            const __nv_bfloat16* src;
            if (tile == 0)      src = g_k1hb + ((size_t)(bhS + s0 + r) * 64 + c * 8);
            else if (tile == 1) src = g_k1lb + ((size_t)(bhS + s0 + r) * 64 + c * 8);
            else if (tile == 2) src = g_k2hb + ((size_t)(bhS + s0 + r) * 64 + c * 8);
            else if (tile == 3) src = g_k2lb + ((size_t)(bhS + s0 + r) * 64 + c * 8);
            else if (tile == 4) src = g_vthb + ((size_t)(bh * 64 + r) * 1024 + s0 + c * 8);
            else                src = g_vtlb + ((size_t)(bh * 64 + r) * 1024 + s0 + c * 8);
            cpa16(dbase + (uint32_t)(tile * FK + r * GP + c * 8) * 2, src);
        }
        asm volatile("cp.async.commit_group;");
    };

    issue(0, 0);

    for (int it = 0; it < 16; it++) {
        const int buf = it & 1;
        const int s0 = it * 64;
        if (it < 15) issue(buf ^ 1, s0 + 64);
        if (it < 15) asm volatile("cp.async.wait_group 1;");
        else         asm volatile("cp.async.wait_group 0;");
        __syncthreads();

        const __nv_bfloat16* Kb  = fs + buf * (6 * FK);
        const __nv_bfloat16* K1h = Kb;
        const __nv_bfloat16* K1l = Kb + FK;
        const __nv_bfloat16* K2h = Kb + 2 * FK;
        const __nv_bfloat16* K2l = Kb + 3 * FK;
        const __nv_bfloat16* VTh = Kb + 4 * FK;
        const __nv_bfloat16* VTl = Kb + 5 * FK;

        float lv[8][4], la[8][4];
#pragma unroll
        for (int nt = 0; nt < 8; nt++)
#pragma unroll
            for (int c = 0; c < 4; c++) { lv[nt][c] = 0.f; la[nt][c] = 0.f; }
#pragma unroll
        for (int nt = 0; nt < 8; nt++) {
#pragma unroll
            for (int ks = 0; ks < 4; ks++) {
                const __nv_bfloat16* b1h = K1h + (nt * 8 + lq) * GP + ks * 16 + lk;
                uint32_t h0 = *(const uint32_t*)b1h;
                uint32_t h1 = *(const uint32_t*)(b1h + 8);
                const __nv_bfloat16* b1l = K1l + (nt * 8 + lq) * GP + ks * 16 + lk;
                uint32_t l0_ = *(const uint32_t*)b1l;
                uint32_t l1_ = *(const uint32_t*)(b1l + 8);
                mma16816(lv[nt], qh[ks][0], qh[ks][1], qh[ks][2], qh[ks][3], h0, h1);
                mma16816(lv[nt], qh[ks][0], qh[ks][1], qh[ks][2], qh[ks][3], l0_, l1_);
                mma16816(lv[nt], ql[ks][0], ql[ks][1], ql[ks][2], ql[ks][3], h0, h1);
                const __nv_bfloat16* b2h = K2h + (nt * 8 + lq) * GP + ks * 16 + lk;
                uint32_t g0 = *(const uint32_t*)b2h;
                uint32_t g1 = *(const uint32_t*)(b2h + 8);
                const __nv_bfloat16* b2l = K2l + (nt * 8 + lq) * GP + ks * 16 + lk;
                uint32_t e0 = *(const uint32_t*)b2l;
                uint32_t e1 = *(const uint32_t*)(b2l + 8);
                mma16816(la[nt], qh[ks][0], qh[ks][1], qh[ks][2], qh[ks][3], g0, g1);
                mma16816(la[nt], qh[ks][0], qh[ks][1], qh[ks][2], qh[ks][3], e0, e1);
                mma16816(la[nt], ql[ks][0], ql[ks][1], ql[ks][2], ql[ks][3], g0, g1);
            }
        }

        float mx0 = -1e30f, mx1 = -1e30f;
#pragma unroll
        for (int nt = 0; nt < 8; nt++) {
            float2 vv2 = *(const float2*)(g_vv + bhS + s0 + nt * 8 + lk);
            float2 aa2 = *(const float2*)(g_aa + bhS + s0 + nt * 8 + lk);
            float2 va2 = *(const float2*)(g_va + bhS + s0 + nt * 8 + lk);
            float g2x = vv2.x * aa2.x - va2.x * va2.x;
            float g2y = vv2.y * aa2.y - va2.y * va2.y;
            {
                float LV = lv[nt][0], LA = la[nt][0];
                float det = ll0 * g2x - LV * (LV * aa2.x - LA * va2.x) + LA * (LV * va2.x - LA * vv2.x);
                float sc = -fsqrt_pos(fmaxf(det, 1e-8f));
                lv[nt][0] = sc; mx0 = fmaxf(mx0, sc);
            }
            {
                float LV = lv[nt][1], LA = la[nt][1];
                float det = ll0 * g2y - LV * (LV * aa2.y - LA * va2.y) + LA * (LV * va2.y - LA * vv2.y);
                float sc = -fsqrt_pos(fmaxf(det, 1e-8f));
                lv[nt][1] = sc; mx0 = fmaxf(mx0, sc);
            }
            {
                float LV = lv[nt][2], LA = la[nt][2];
                float det = ll1 * g2x - LV * (LV * aa2.x - LA * va2.x) + LA * (LV * va2.x - LA * vv2.x);
                float sc = -fsqrt_pos(fmaxf(det, 1e-8f));
                lv[nt][2] = sc; mx1 = fmaxf(mx1, sc);
            }
            {
                float LV = lv[nt][3], LA = la[nt][3];
                float det = ll1 * g2y - LV * (LV * aa2.y - LA * va2.y) + LA * (LV * va2.y - LA * vv2.y);
                float sc = -fsqrt_pos(fmaxf(det, 1e-8f));
                lv[nt][3] = sc; mx1 = fmaxf(mx1, sc);
            }
        }
        mx0 = fmaxf(mx0, __shfl_xor_sync(0xffffffffu, mx0, 1));
        mx0 = fmaxf(mx0, __shfl_xor_sync(0xffffffffu, mx0, 2));
        mx1 = fmaxf(mx1, __shfl_xor_sync(0xffffffffu, mx1, 1));
        mx1 = fmaxf(mx1, __shfl_xor_sync(0xffffffffu, mx1, 2));

        float mn0 = fmaxf(m0, mx0), mn1 = fmaxf(m1, mx1);
        float alpha0 = fexp(m0 - mn0), alpha1 = fexp(m1 - mn1);
        m0 = mn0; m1 = mn1;

        float rs0 = 0.f, rs1 = 0.f;
#pragma unroll
        for (int nt = 0; nt < 8; nt++) {
            float p0 = fexp(lv[nt][0] - mn0);
            float p1 = fexp(lv[nt][1] - mn0);
            float p2 = fexp(lv[nt][2] - mn1);
            float p3 = fexp(lv[nt][3] - mn1);
            lv[nt][0] = p0; lv[nt][1] = p1; lv[nt][2] = p2; lv[nt][3] = p3;
            rs0 += p0 + p1; rs1 += p2 + p3;
        }
        rs0 += __shfl_xor_sync(0xffffffffu, rs0, 1);
        rs0 += __shfl_xor_sync(0xffffffffu, rs0, 2);
        rs1 += __shfl_xor_sync(0xffffffffu, rs1, 1);
        rs1 += __shfl_xor_sync(0xffffffffu, rs1, 2);
        ls0 = ls0 * alpha0 + rs0;
        ls1 = ls1 * alpha1 + rs1;

#pragma unroll
        for (int dt = 0; dt < 8; dt++) {
            o[dt][0] *= alpha0; o[dt][1] *= alpha0;
            o[dt][2] *= alpha1; o[dt][3] *= alpha1;
        }

        uint32_t ph[4][4], pl[4][4];
#pragma unroll
        for (int ks = 0; ks < 4; ks++) {
            ph[ks][0] = pk_hi(lv[2 * ks][0], lv[2 * ks][1]);
            pl[ks][0] = pk_lo(lv[2 * ks][0], lv[2 * ks][1]);
            ph[ks][1] = pk_hi(lv[2 * ks][2], lv[2 * ks][3]);
            pl[ks][1] = pk_lo(lv[2 * ks][2], lv[2 * ks][3]);
            ph[ks][2] = pk_hi(lv[2 * ks + 1][0], lv[2 * ks + 1][1]);
            pl[ks][2] = pk_lo(lv[2 * ks + 1][0], lv[2 * ks + 1][1]);
            ph[ks][3] = pk_hi(lv[2 * ks + 1][2], lv[2 * ks + 1][3]);
            pl[ks][3] = pk_lo(lv[2 * ks + 1][2], lv[2 * ks + 1][3]);
        }

#pragma unroll
        for (int dt = 0; dt < 8; dt++) {
#pragma unroll
            for (int ks = 0; ks < 4; ks++) {
                const __nv_bfloat16* vh = VTh + (dt * 8 + lq) * GP + ks * 16 + lk;
                uint32_t vh0 = *(const uint32_t*)vh;
                uint32_t vh1 = *(const uint32_t*)(vh + 8);
                const __nv_bfloat16* vl = VTl + (dt * 8 + lq) * GP + ks * 16 + lk;
                uint32_t vl0 = *(const uint32_t*)vl;
                uint32_t vl1 = *(const uint32_t*)(vl + 8);
                mma16816(o[dt], ph[ks][0], ph[ks][1], ph[ks][2], ph[ks][3], vh0, vh1);
                mma16816(o[dt], ph[ks][0], ph[ks][1], ph[ks][2], ph[ks][3], vl0, vl1);
                mma16816(o[dt], pl[ks][0], pl[ks][1], pl[ks][2], pl[ks][3], vh0, vh1);
            }
        }
        __syncthreads();
    }

    const float inv0 = frcp_pos(ls0);
    const float inv1 = frcp_pos(ls1);
    const int bi = bh >> 3, h = bh & 7;
    const int r0 = l0 + wid * 16 + lq;
#pragma unroll
    for (int dt = 0; dt < 8; dt++) {
        int d = dt * 8 + lk;
        float a0 = o[dt][0] * inv0, a1 = o[dt][1] * inv0;
        float b0 = o[dt][2] * inv1, b1 = o[dt][3] * inv1;
        size_t off0 = (size_t)(r0 * 8 + bi) * 512 + h * 64 + d;
        size_t off1 = (size_t)((r0 + 8) * 8 + bi) * 512 + h * 64 + d;
        *(uint32_t*)(g_aoh + off0) = pk_hi(a0, a1);
        *(uint32_t*)(g_aol + off0) = pk_lo(a0, a1);
        *(uint32_t*)(g_aoh + off1) = pk_hi(b0, b1);
        *(uint32_t*)(g_aol + off1) = pk_lo(b0, b1);
    }
}

// ---------------- launch ----------------
extern "C" void kernel_launch(void* const* d_in, const int* in_sizes, int n_in,
                              void* d_out, int out_size) {
    const float* query = (const float*)d_in[0];
    const float* mod1  = (const float*)d_in[1];
    const float* mod2  = (const float*)d_in[2];
    const float* Wq  = (const float*)d_in[3];  const float* bq  = (const float*)d_in[4];
    const float* Wk1 = (const float*)d_in[5];  const float* bk1 = (const float*)d_in[6];
    const float* Wk2 = (const float*)d_in[7];  const float* bk2 = (const float*)d_in[8];
    const float* Wv1 = (const float*)d_in[9];  const float* bv1 = (const float*)d_in[10];
    const float* Wv2 = (const float*)d_in[11]; const float* bv2 = (const float*)d_in[12];
    const float* Wg1 = (const float*)d_in[13]; const float* bg1 = (const float*)d_in[14];
    const float* Wg2 = (const float*)d_in[15]; const float* bg2 = (const float*)d_in[16];
    const float* Wo  = (const float*)d_in[17]; const float* bo  = (const float*)d_in[18];
    float* out = (float*)d_out;

    cudaFuncSetAttribute(proj3_cp,    cudaFuncAttributeMaxDynamicSharedMemorySize, PJ_SMEM_B);
    cudaFuncSetAttribute(proj_out_cp, cudaFuncAttributeMaxDynamicSharedMemorySize, PJ_SMEM_B);
    cudaFuncSetAttribute(projvg_cp,   cudaFuncAttributeMaxDynamicSharedMemorySize, VG_SMEM_B);
    cudaFuncSetAttribute(flash_mma,   cudaFuncAttributeMaxDynamicSharedMemorySize, FL_SMEM_B);

    dim3 pb(256);
    prep_act<<<dim3(4096, 1, 3), pb>>>(query, mod1, mod2);
    prep_w<<<dim3(256, 1, 8), pb>>>(Wq, Wk1, Wk2, Wv1, Wv2, Wg1, Wg2, Wo);
    proj3_cp<<<dim3(64, 4, 3), pb, PJ_SMEM_B>>>(bq, bk1, bk2);
    projvg_cp<<<dim3(64, 4), pb, VG_SMEM_B>>>(bv1, bg1, 0);
    projvg_cp<<<dim3(64, 4), pb, VG_SMEM_B>>>(bv2, bg2, 1);
    norm_q_kernel<<<8192, 256>>>();
    norm_k_kernel<<<8192, 256>>>();
    prep_vt<<<dim3(16, 64), 256>>>();
    flash_mma<<<dim3(8, 64), 256, FL_SMEM_B>>>();
    proj_out_cp<<<dim3(64, 4), pb, PJ_SMEM_B>>>(bo, out);
}